// round 3
// baseline (speedup 1.0000x reference)
#include <cuda_runtime.h>

#define NN   100000
#define EE   1000000
#define INC  128
#define HID  32
#define NH1  8
#define OUTC 40
#define NEGS 0.2f

// ---------------- device scratch ----------------
__device__ __align__(16) float g_h1[(size_t)NN * 256];
__device__ __align__(16) float g_x2[(size_t)NN * 256];
__device__ __align__(16) float g_as1[NN * NH1];
__device__ __align__(16) float g_ad1[NN * NH1];
__device__ __align__(16) float g_m1[NN * NH1];
__device__ __align__(16) float g_d1[NN * NH1];
__device__ __align__(16) float g_w1[(size_t)EE * NH1];   // per-edge per-head alpha -> weight
__device__ __align__(16) float g_h2[NN * HID];
__device__ __align__(16) float g_as2[NN];
__device__ __align__(16) float g_ad2[NN];
__device__ __align__(16) float g_m2[NN];
__device__ __align__(16) float g_d2[NN];
__device__ __align__(16) float g_w2[EE];
__device__ __align__(16) float g_o2[NN * HID];
__device__ int g_cnt[NN];
__device__ int g_rowptr[NN + 1];
__device__ int g_cursor[NN];
__device__ int g_col[EE];
__device__ int g_dstv[EE];

__device__ __forceinline__ float leaky(float x) { return x > 0.f ? x : NEGS * x; }

__device__ __forceinline__ void atomicMaxFloat(float* addr, float val) {
    if (val >= 0.f) atomicMax((int*)addr, __float_as_int(val));
    else            atomicMin((unsigned int*)addr, (unsigned int)__float_as_int(val));
}

// ---------------- CSR build ----------------
__global__ void k_zero() {
    int i = blockIdx.x * blockDim.x + threadIdx.x;
    if (i < NN) g_cnt[i] = 0;
}

__global__ void k_hist(const int* __restrict__ ei) {
    int e = blockIdx.x * blockDim.x + threadIdx.x;
    if (e < EE) atomicAdd(&g_cnt[ei[EE + e]], 1);
}

__global__ void k_scan() {
    __shared__ int ws[32];
    int tid = threadIdx.x;
    int lane = tid & 31, wid = tid >> 5;
    int carry = 0;
    for (int base = 0; base < NN; base += 1024) {
        int i = base + tid;
        int v = (i < NN) ? g_cnt[i] : 0;
        int x = v;
        #pragma unroll
        for (int o = 1; o < 32; o <<= 1) {
            int y = __shfl_up_sync(0xffffffffu, x, o);
            if (lane >= o) x += y;
        }
        if (lane == 31) ws[wid] = x;
        __syncthreads();
        if (wid == 0) {
            int s = ws[lane];
            #pragma unroll
            for (int o = 1; o < 32; o <<= 1) {
                int y = __shfl_up_sync(0xffffffffu, s, o);
                if (lane >= o) s += y;
            }
            ws[lane] = s;
        }
        __syncthreads();
        int incl = x + (wid ? ws[wid - 1] : 0) + carry;
        if (i < NN) {
            int ex = incl - v;
            g_rowptr[i] = ex;
            g_cursor[i] = ex;
            if (i == NN - 1) g_rowptr[NN] = incl;
        }
        carry += ws[31];
        __syncthreads();
    }
}

__global__ void k_scatter(const int* __restrict__ ei) {
    int e = blockIdx.x * blockDim.x + threadIdx.x;
    if (e < EE) {
        int s = ei[e];
        int d = ei[EE + e];
        int pos = atomicAdd(&g_cursor[d], 1);
        g_col[pos]  = s;
        g_dstv[pos] = d;
    }
}

// ---------------- GEMM1: h1 = x0 @ W1 ----------------
__global__ void __launch_bounds__(256) k_gemm1(const float* __restrict__ x0,
                                               const float* __restrict__ W1) {
    __shared__ __align__(16) float As[16][128];
    __shared__ __align__(16) float Bs[16][128];
    int tid = threadIdx.x;
    int rowBase = blockIdx.y * 128;
    int colBase = blockIdx.x * 128;
    int ty = tid >> 4, tx = tid & 15;

    float acc[8][8];
    #pragma unroll
    for (int i = 0; i < 8; i++)
        #pragma unroll
        for (int j = 0; j < 8; j++) acc[i][j] = 0.f;

    int lr = tid >> 1, seg = tid & 1;

    for (int kb = 0; kb < 128; kb += 16) {
        int row = rowBase + lr;
        float4 a0, a1;
        if (row < NN) {
            const float4* p = (const float4*)(x0 + (size_t)row * 128 + kb + seg * 8);
            a0 = p[0]; a1 = p[1];
        } else {
            a0 = make_float4(0, 0, 0, 0); a1 = a0;
        }
        As[seg * 8 + 0][lr] = a0.x; As[seg * 8 + 1][lr] = a0.y;
        As[seg * 8 + 2][lr] = a0.z; As[seg * 8 + 3][lr] = a0.w;
        As[seg * 8 + 4][lr] = a1.x; As[seg * 8 + 5][lr] = a1.y;
        As[seg * 8 + 6][lr] = a1.z; As[seg * 8 + 7][lr] = a1.w;
        #pragma unroll
        for (int i = 0; i < 2; i++) {
            int f = tid + i * 256;
            int kr = (f * 4) >> 7;
            int c  = (f * 4) & 127;
            float4 b = *(const float4*)(W1 + (size_t)(kb + kr) * 256 + colBase + c);
            *(float4*)&Bs[kr][c] = b;
        }
        __syncthreads();
        #pragma unroll
        for (int kk = 0; kk < 16; kk++) {
            float4 av0 = *(const float4*)&As[kk][ty * 8];
            float4 av1 = *(const float4*)&As[kk][ty * 8 + 4];
            float4 bv0 = *(const float4*)&Bs[kk][tx * 8];
            float4 bv1 = *(const float4*)&Bs[kk][tx * 8 + 4];
            float a[8] = {av0.x, av0.y, av0.z, av0.w, av1.x, av1.y, av1.z, av1.w};
            float b[8] = {bv0.x, bv0.y, bv0.z, bv0.w, bv1.x, bv1.y, bv1.z, bv1.w};
            #pragma unroll
            for (int i = 0; i < 8; i++)
                #pragma unroll
                for (int j = 0; j < 8; j++) acc[i][j] += a[i] * b[j];
        }
        __syncthreads();
    }
    #pragma unroll
    for (int i = 0; i < 8; i++) {
        int row = rowBase + ty * 8 + i;
        if (row < NN) {
            float4 v0 = make_float4(acc[i][0], acc[i][1], acc[i][2], acc[i][3]);
            float4 v1 = make_float4(acc[i][4], acc[i][5], acc[i][6], acc[i][7]);
            float* dst = g_h1 + (size_t)row * 256 + colBase + tx * 8;
            *(float4*)dst = v0;
            *(float4*)(dst + 4) = v1;
        }
    }
}

// ---------------- att dots layer1 + self-alpha init of m1 ----------------
__global__ void k_att1(const float* __restrict__ attS, const float* __restrict__ attD) {
    int warp = (blockIdx.x * blockDim.x + threadIdx.x) >> 5;
    int lane = threadIdx.x & 31;
    if (warp >= NN) return;
    const float* hrow = g_h1 + (size_t)warp * 256;
    #pragma unroll
    for (int h = 0; h < NH1; h++) {
        float v = hrow[h * 32 + lane];
        float ps = v * __ldg(&attS[h * 32 + lane]);
        float pd = v * __ldg(&attD[h * 32 + lane]);
        #pragma unroll
        for (int o = 16; o; o >>= 1) {
            ps += __shfl_xor_sync(0xffffffffu, ps, o);
            pd += __shfl_xor_sync(0xffffffffu, pd, o);
        }
        if (lane == 0) {
            g_as1[warp * 8 + h] = ps;
            g_ad1[warp * 8 + h] = pd;
            g_m1[warp * 8 + h]  = leaky(ps + pd);   // self-loop alpha seeds the max
        }
    }
}

// ---------------- layer1 pass A: alphas + segment max ----------------
__global__ void k_alpha1() {
    int p = blockIdx.x * blockDim.x + threadIdx.x;
    if (p >= EE) return;
    int s = g_col[p], d = g_dstv[p];
    float4 s0 = *(const float4*)&g_as1[s * 8];
    float4 s1 = *(const float4*)&g_as1[s * 8 + 4];
    float4 d0 = *(const float4*)&g_ad1[d * 8];
    float4 d1 = *(const float4*)&g_ad1[d * 8 + 4];
    float al[8];
    al[0] = leaky(s0.x + d0.x); al[1] = leaky(s0.y + d0.y);
    al[2] = leaky(s0.z + d0.z); al[3] = leaky(s0.w + d0.w);
    al[4] = leaky(s1.x + d1.x); al[5] = leaky(s1.y + d1.y);
    al[6] = leaky(s1.z + d1.z); al[7] = leaky(s1.w + d1.w);
    float* wp = &g_w1[(size_t)p * 8];
    *(float4*)wp       = make_float4(al[0], al[1], al[2], al[3]);
    *(float4*)(wp + 4) = make_float4(al[4], al[5], al[6], al[7]);
    #pragma unroll
    for (int h = 0; h < 8; h++) atomicMaxFloat(&g_m1[d * 8 + h], al[h]);
}

// den init with self-loop term (m1 is final here)
__global__ void k_dself1() {
    int i = blockIdx.x * blockDim.x + threadIdx.x;
    if (i < NN * 8) g_d1[i] = __expf(leaky(g_as1[i] + g_ad1[i]) - g_m1[i]);
}

// ---------------- layer1 pass B: exp + segment sum ----------------
__global__ void k_passb1() {
    int p = blockIdx.x * blockDim.x + threadIdx.x;
    if (p >= EE) return;
    int d = g_dstv[p];
    float* wp = &g_w1[(size_t)p * 8];
    float4 a0 = *(const float4*)wp;
    float4 a1 = *(const float4*)(wp + 4);
    float4 m0 = *(const float4*)&g_m1[d * 8];
    float4 m1v = *(const float4*)&g_m1[d * 8 + 4];
    float w[8];
    w[0] = __expf(a0.x - m0.x);  w[1] = __expf(a0.y - m0.y);
    w[2] = __expf(a0.z - m0.z);  w[3] = __expf(a0.w - m0.w);
    w[4] = __expf(a1.x - m1v.x); w[5] = __expf(a1.y - m1v.y);
    w[6] = __expf(a1.z - m1v.z); w[7] = __expf(a1.w - m1v.w);
    *(float4*)wp       = make_float4(w[0], w[1], w[2], w[3]);
    *(float4*)(wp + 4) = make_float4(w[4], w[5], w[6], w[7]);
    #pragma unroll
    for (int h = 0; h < 8; h++) atomicAdd(&g_d1[d * 8 + h], w[h]);
}

// ---------------- layer1 gather: block per node, warp per head ----------------
__global__ void __launch_bounds__(256) k_gather1(const float* __restrict__ b1) {
    int n = blockIdx.x;
    int h = threadIdx.x >> 5;
    int lane = threadIdx.x & 31;
    int e0 = g_rowptr[n], e1 = g_rowptr[n + 1];
    float acc = 0.f;
    #pragma unroll 4
    for (int p = e0; p < e1; p++) {
        int s = g_col[p];
        float wt = g_w1[(size_t)p * 8 + h];
        acc += wt * g_h1[(size_t)s * 256 + h * 32 + lane];
    }
    // self loop
    float sal = leaky(g_as1[n * 8 + h] + g_ad1[n * 8 + h]);
    float ws  = __expf(sal - g_m1[n * 8 + h]);
    acc += ws * g_h1[(size_t)n * 256 + h * 32 + lane];
    float den = fmaxf(g_d1[n * 8 + h], 1e-16f);
    float r = acc / den + __ldg(&b1[h * 32 + lane]);
    g_x2[(size_t)n * 256 + h * 32 + lane] = fmaxf(r, 0.f);
}

// ---------------- GEMM2 + att2 dots + m2 init ----------------
__global__ void __launch_bounds__(256) k_gemm2(const float* __restrict__ W2,
                                               const float* __restrict__ attS2,
                                               const float* __restrict__ attD2) {
    __shared__ float W2s[256 * 32];
    int tid = threadIdx.x;
    for (int i = tid; i < 256 * 32; i += 256) W2s[i] = W2[i];
    __syncthreads();
    int lane = tid & 31, wl = tid >> 5;
    int n = blockIdx.x * 8 + wl;
    const float* xr = g_x2 + (size_t)n * 256;
    float acc = 0.f;
    #pragma unroll
    for (int c = 0; c < 8; c++) {
        float xv = xr[c * 32 + lane];
        #pragma unroll
        for (int j = 0; j < 32; j++) {
            float xb = __shfl_sync(0xffffffffu, xv, j);
            acc += xb * W2s[(c * 32 + j) * 32 + lane];
        }
    }
    g_h2[n * 32 + lane] = acc;
    float ps = acc * __ldg(&attS2[lane]);
    float pd = acc * __ldg(&attD2[lane]);
    #pragma unroll
    for (int o = 16; o; o >>= 1) {
        ps += __shfl_xor_sync(0xffffffffu, ps, o);
        pd += __shfl_xor_sync(0xffffffffu, pd, o);
    }
    if (lane == 0) {
        g_as2[n] = ps;
        g_ad2[n] = pd;
        g_m2[n]  = leaky(ps + pd);
    }
}

// ---------------- layer2 passes ----------------
__global__ void k_alpha2() {
    int p = blockIdx.x * blockDim.x + threadIdx.x;
    if (p >= EE) return;
    int s = g_col[p], d = g_dstv[p];
    float al = leaky(g_as2[s] + g_ad2[d]);
    g_w2[p] = al;
    atomicMaxFloat(&g_m2[d], al);
}

__global__ void k_dself2() {
    int i = blockIdx.x * blockDim.x + threadIdx.x;
    if (i < NN) g_d2[i] = __expf(leaky(g_as2[i] + g_ad2[i]) - g_m2[i]);
}

__global__ void k_passb2() {
    int p = blockIdx.x * blockDim.x + threadIdx.x;
    if (p >= EE) return;
    int d = g_dstv[p];
    float w = __expf(g_w2[p] - g_m2[d]);
    g_w2[p] = w;
    atomicAdd(&g_d2[d], w);
}

// ---------------- layer2 gather: warp per node ----------------
__global__ void k_gather2(const float* __restrict__ b2) {
    int n = (blockIdx.x * blockDim.x + threadIdx.x) >> 5;
    int lane = threadIdx.x & 31;
    if (n >= NN) return;
    int e0 = g_rowptr[n], e1 = g_rowptr[n + 1];
    float acc = 0.f;
    #pragma unroll 4
    for (int p = e0; p < e1; p++) {
        int s = g_col[p];
        acc += g_w2[p] * g_h2[s * 32 + lane];
    }
    float sal = leaky(g_as2[n] + g_ad2[n]);
    float ws  = __expf(sal - g_m2[n]);
    acc += ws * g_h2[n * 32 + lane];
    float den = fmaxf(g_d2[n], 1e-16f);
    g_o2[n * 32 + lane] = acc / den + __ldg(&b2[lane]);
}

// ---------------- final linear ----------------
__global__ void __launch_bounds__(640) k_final(const float* __restrict__ linW,
                                               const float* __restrict__ linb,
                                               float* __restrict__ out) {
    __shared__ float lw[32 * 40];
    __shared__ float rows[16][32];
    int tid = threadIdx.x;
    for (int i = tid; i < 32 * 40; i += 640) lw[i] = linW[i];
    int nb = blockIdx.x * 16;
    for (int i = tid; i < 512; i += 640) {
        int r = i >> 5, c = i & 31;
        int n = nb + r;
        rows[r][c] = (n < NN) ? g_o2[n * 32 + c] : 0.f;
    }
    __syncthreads();
    int o = tid % 40, r = tid / 40;
    int n = nb + r;
    if (n < NN) {
        float acc = __ldg(&linb[o]);
        #pragma unroll
        for (int k = 0; k < 32; k++) acc += rows[r][k] * lw[k * 40 + o];
        out[(size_t)n * 40 + o] = acc;
    }
}

// ---------------- launch ----------------
extern "C" void kernel_launch(void* const* d_in, const int* in_sizes, int n_in,
                              void* d_out, int out_size) {
    const float* x0    = (const float*)d_in[0];
    const float* W1    = (const float*)d_in[1];
    const float* attS1 = (const float*)d_in[2];
    const float* attD1 = (const float*)d_in[3];
    const float* b1    = (const float*)d_in[4];
    const float* W2    = (const float*)d_in[5];
    const float* attS2 = (const float*)d_in[6];
    const float* attD2 = (const float*)d_in[7];
    const float* b2    = (const float*)d_in[8];
    const float* linW  = (const float*)d_in[9];
    const float* linb  = (const float*)d_in[10];
    const int*   ei    = (const int*)d_in[11];
    float* out = (float*)d_out;

    k_zero<<<(NN + 255) / 256, 256>>>();
    k_hist<<<(EE + 255) / 256, 256>>>(ei);
    k_scan<<<1, 1024>>>();
    k_scatter<<<(EE + 255) / 256, 256>>>(ei);
    k_gemm1<<<dim3(2, (NN + 127) / 128), 256>>>(x0, W1);
    k_att1<<<(NN + 7) / 8, 256>>>(attS1, attD1);
    k_alpha1<<<(EE + 255) / 256, 256>>>();
    k_dself1<<<(NN * 8 + 255) / 256, 256>>>();
    k_passb1<<<(EE + 255) / 256, 256>>>();
    k_gather1<<<NN, 256>>>(b1);
    k_gemm2<<<NN / 8, 256>>>(W2, attS2, attD2);
    k_alpha2<<<(EE + 255) / 256, 256>>>();
    k_dself2<<<(NN + 255) / 256, 256>>>();
    k_passb2<<<(EE + 255) / 256, 256>>>();
    k_gather2<<<(NN + 7) / 8, 256>>>(b2);
    k_final<<<(NN + 15) / 16, 640>>>(linW, linb, out);
}

// round 5
// speedup vs baseline: 1.1393x; 1.1393x over previous
#include <cuda_runtime.h>

#define NN   100000
#define EE   1000000
#define HID  32
#define NH1  8
#define OUTC 40
#define NEGS 0.2f

// ================= device scratch =================
__device__ __align__(16) float g_h1[(size_t)NN * 256];
__device__ __align__(16) float g_x2[(size_t)NN * 256];
__device__ __align__(16) float g_as1[NN * NH1];
__device__ __align__(16) float g_ad1[NN * NH1];
__device__ __align__(16) float g_d1[NN * NH1];
__device__ __align__(16) float g_w1[(size_t)EE * NH1];
__device__ __align__(16) float g_h2[NN * HID];
__device__ __align__(16) float g_as2[NN];
__device__ __align__(16) float g_ad2[NN];
__device__ __align__(16) float g_d2[NN];
__device__ __align__(16) float g_w2[EE];
__device__ __align__(16) float g_o2[NN * HID];
__device__ int g_cnt[NN];
__device__ int g_rowptr[NN + 1];
__device__ int g_cursor[NN];
__device__ int g_col[EE];
__device__ int g_dstv[EE];
__device__ int g_bsum[128];
__device__ int g_boff[128];

__device__ __forceinline__ float leaky(float x) { return x > 0.f ? x : NEGS * x; }

// ================= CSR build =================
__global__ void k_zero() {
    int i = blockIdx.x * blockDim.x + threadIdx.x;
    if (i < NN) g_cnt[i] = 0;
}
__global__ void k_hist(const int* __restrict__ ei) {
    int e = blockIdx.x * blockDim.x + threadIdx.x;
    if (e < EE) atomicAdd(&g_cnt[ei[EE + e]], 1);
}
__global__ void __launch_bounds__(1024) k_scan1() {
    __shared__ int ws[32];
    int tid = threadIdx.x, lane = tid & 31, wid = tid >> 5;
    int i = blockIdx.x * 1024 + tid;
    int v = (i < NN) ? g_cnt[i] : 0;
    int x = v;
    #pragma unroll
    for (int o = 1; o < 32; o <<= 1) {
        int y = __shfl_up_sync(0xffffffffu, x, o);
        if (lane >= o) x += y;
    }
    if (lane == 31) ws[wid] = x;
    __syncthreads();
    if (wid == 0) {
        int s = ws[lane];
        #pragma unroll
        for (int o = 1; o < 32; o <<= 1) {
            int y = __shfl_up_sync(0xffffffffu, s, o);
            if (lane >= o) s += y;
        }
        ws[lane] = s;
    }
    __syncthreads();
    int incl = x + (wid ? ws[wid - 1] : 0);
    if (i < NN) g_rowptr[i] = incl - v;
    if (tid == 1023) g_bsum[blockIdx.x] = incl;
}
__global__ void k_scan2(int nblk) {
    __shared__ int ws[4];
    int tid = threadIdx.x, lane = tid & 31, wid = tid >> 5;
    int v = (tid < nblk) ? g_bsum[tid] : 0;
    int x = v;
    #pragma unroll
    for (int o = 1; o < 32; o <<= 1) {
        int y = __shfl_up_sync(0xffffffffu, x, o);
        if (lane >= o) x += y;
    }
    if (lane == 31) ws[wid] = x;
    __syncthreads();
    int pre = 0;
    for (int w = 0; w < wid; w++) pre += ws[w];
    int incl = x + pre;
    if (tid < nblk) g_boff[tid] = incl - v;
    if (tid == nblk - 1) g_rowptr[NN] = incl;
}
__global__ void __launch_bounds__(1024) k_scan3() {
    int i = blockIdx.x * 1024 + threadIdx.x;
    if (i < NN) {
        int r = g_rowptr[i] + g_boff[blockIdx.x];
        g_rowptr[i] = r;
        g_cursor[i] = r;
    }
}
__global__ void k_scatter(const int* __restrict__ ei) {
    int e = blockIdx.x * blockDim.x + threadIdx.x;
    if (e < EE) {
        int s = ei[e];
        int d = ei[EE + e];
        int pos = atomicAdd(&g_cursor[d], 1);
        g_col[pos]  = s;
        g_dstv[pos] = d;
    }
}

// ================= GEMM1: h1 = x0 @ W1 (fp32 SIMT, known-good) =================
__global__ void __launch_bounds__(256) k_gemm1(const float* __restrict__ x0,
                                               const float* __restrict__ W1) {
    __shared__ __align__(16) float As[16][128];
    __shared__ __align__(16) float Bs[16][128];
    int tid = threadIdx.x;
    int rowBase = blockIdx.y * 128;
    int colBase = blockIdx.x * 128;
    int ty = tid >> 4, tx = tid & 15;

    float acc[8][8];
    #pragma unroll
    for (int i = 0; i < 8; i++)
        #pragma unroll
        for (int j = 0; j < 8; j++) acc[i][j] = 0.f;

    int lr = tid >> 1, seg = tid & 1;

    for (int kb = 0; kb < 128; kb += 16) {
        int row = rowBase + lr;
        float4 a0, a1;
        if (row < NN) {
            const float4* p = (const float4*)(x0 + (size_t)row * 128 + kb + seg * 8);
            a0 = p[0]; a1 = p[1];
        } else {
            a0 = make_float4(0, 0, 0, 0); a1 = a0;
        }
        As[seg * 8 + 0][lr] = a0.x; As[seg * 8 + 1][lr] = a0.y;
        As[seg * 8 + 2][lr] = a0.z; As[seg * 8 + 3][lr] = a0.w;
        As[seg * 8 + 4][lr] = a1.x; As[seg * 8 + 5][lr] = a1.y;
        As[seg * 8 + 6][lr] = a1.z; As[seg * 8 + 7][lr] = a1.w;
        #pragma unroll
        for (int i = 0; i < 2; i++) {
            int f = tid + i * 256;
            int kr = (f * 4) >> 7;
            int c  = (f * 4) & 127;
            float4 b = *(const float4*)(W1 + (size_t)(kb + kr) * 256 + colBase + c);
            *(float4*)&Bs[kr][c] = b;
        }
        __syncthreads();
        #pragma unroll
        for (int kk = 0; kk < 16; kk++) {
            float4 av0 = *(const float4*)&As[kk][ty * 8];
            float4 av1 = *(const float4*)&As[kk][ty * 8 + 4];
            float4 bv0 = *(const float4*)&Bs[kk][tx * 8];
            float4 bv1 = *(const float4*)&Bs[kk][tx * 8 + 4];
            float a[8] = {av0.x, av0.y, av0.z, av0.w, av1.x, av1.y, av1.z, av1.w};
            float b[8] = {bv0.x, bv0.y, bv0.z, bv0.w, bv1.x, bv1.y, bv1.z, bv1.w};
            #pragma unroll
            for (int i = 0; i < 8; i++)
                #pragma unroll
                for (int j = 0; j < 8; j++) acc[i][j] += a[i] * b[j];
        }
        __syncthreads();
    }
    #pragma unroll
    for (int i = 0; i < 8; i++) {
        int row = rowBase + ty * 8 + i;
        if (row < NN) {
            float4 v0 = make_float4(acc[i][0], acc[i][1], acc[i][2], acc[i][3]);
            float4 v1 = make_float4(acc[i][4], acc[i][5], acc[i][6], acc[i][7]);
            float* dst = g_h1 + (size_t)row * 256 + colBase + tx * 8;
            *(float4*)dst = v0;
            *(float4*)(dst + 4) = v1;
        }
    }
}

// ============ att dots layer1 + self-loop denom init ============
__global__ void k_att1(const float* __restrict__ attS, const float* __restrict__ attD) {
    int warp = (blockIdx.x * blockDim.x + threadIdx.x) >> 5;
    int lane = threadIdx.x & 31;
    if (warp >= NN) return;
    const float* hrow = g_h1 + (size_t)warp * 256;
    #pragma unroll
    for (int h = 0; h < NH1; h++) {
        float v = hrow[h * 32 + lane];
        float ps = v * __ldg(&attS[h * 32 + lane]);
        float pd = v * __ldg(&attD[h * 32 + lane]);
        #pragma unroll
        for (int o = 16; o; o >>= 1) {
            ps += __shfl_xor_sync(0xffffffffu, ps, o);
            pd += __shfl_xor_sync(0xffffffffu, pd, o);
        }
        if (lane == 0) {
            g_as1[warp * 8 + h] = ps;
            g_ad1[warp * 8 + h] = pd;
            g_d1[warp * 8 + h]  = __expf(leaky(ps + pd));   // self-loop seeds denom
        }
    }
}

// ============ layer1 softmax pass (no max; alphas are O(1)) ============
__global__ void k_den1() {
    int p = blockIdx.x * blockDim.x + threadIdx.x;
    if (p >= EE) return;
    int s = g_col[p], d = g_dstv[p];
    float4 s0 = *(const float4*)&g_as1[s * 8];
    float4 s1 = *(const float4*)&g_as1[s * 8 + 4];
    float4 d0 = *(const float4*)&g_ad1[d * 8];
    float4 d1v = *(const float4*)&g_ad1[d * 8 + 4];
    float w[8];
    w[0] = __expf(leaky(s0.x + d0.x));  w[1] = __expf(leaky(s0.y + d0.y));
    w[2] = __expf(leaky(s0.z + d0.z));  w[3] = __expf(leaky(s0.w + d0.w));
    w[4] = __expf(leaky(s1.x + d1v.x)); w[5] = __expf(leaky(s1.y + d1v.y));
    w[6] = __expf(leaky(s1.z + d1v.z)); w[7] = __expf(leaky(s1.w + d1v.w));
    float* wp = &g_w1[(size_t)p * 8];
    *(float4*)wp       = make_float4(w[0], w[1], w[2], w[3]);
    *(float4*)(wp + 4) = make_float4(w[4], w[5], w[6], w[7]);
    #pragma unroll
    for (int h = 0; h < 8; h++) atomicAdd(&g_d1[d * 8 + h], w[h]);
}

// ============ layer1 gather: block per node, warp per head ============
__global__ void __launch_bounds__(256) k_gather1(const float* __restrict__ b1) {
    int n = blockIdx.x;
    int h = threadIdx.x >> 5;
    int lane = threadIdx.x & 31;
    int e0 = g_rowptr[n], e1 = g_rowptr[n + 1];
    float acc = 0.f;
    #pragma unroll 4
    for (int p = e0; p < e1; p++) {
        int s = g_col[p];
        float wt = g_w1[(size_t)p * 8 + h];
        acc += wt * __ldg(&g_h1[(size_t)s * 256 + h * 32 + lane]);
    }
    float ws = __expf(leaky(g_as1[n * 8 + h] + g_ad1[n * 8 + h]));   // self loop
    acc += ws * g_h1[(size_t)n * 256 + h * 32 + lane];
    float den = fmaxf(g_d1[n * 8 + h], 1e-16f);
    float r = acc / den + __ldg(&b1[h * 32 + lane]);
    g_x2[(size_t)n * 256 + h * 32 + lane] = fmaxf(r, 0.f);
}

// ============ GEMM2 + att2 dots + d2 self-init ============
__global__ void __launch_bounds__(256) k_gemm2(const float* __restrict__ W2,
                                               const float* __restrict__ attS2,
                                               const float* __restrict__ attD2) {
    __shared__ float W2s[256 * 32];
    int tid = threadIdx.x;
    for (int i = tid; i < 256 * 32; i += 256) W2s[i] = W2[i];
    __syncthreads();
    int lane = tid & 31, wl = tid >> 5;
    int n = blockIdx.x * 8 + wl;                 // 12500*8 == 100000 exactly
    const float* xr = g_x2 + (size_t)n * 256;
    float acc = 0.f;
    #pragma unroll
    for (int c = 0; c < 8; c++) {
        float xv = xr[c * 32 + lane];
        #pragma unroll
        for (int j = 0; j < 32; j++) {
            float xb = __shfl_sync(0xffffffffu, xv, j);
            acc += xb * W2s[(c * 32 + j) * 32 + lane];
        }
    }
    g_h2[n * 32 + lane] = acc;
    float ps = acc * __ldg(&attS2[lane]);
    float pd = acc * __ldg(&attD2[lane]);
    #pragma unroll
    for (int o = 16; o; o >>= 1) {
        ps += __shfl_xor_sync(0xffffffffu, ps, o);
        pd += __shfl_xor_sync(0xffffffffu, pd, o);
    }
    if (lane == 0) {
        g_as2[n] = ps;
        g_ad2[n] = pd;
        g_d2[n]  = __expf(leaky(ps + pd));
    }
}

// ============ layer2 softmax pass ============
__global__ void k_den2() {
    int p = blockIdx.x * blockDim.x + threadIdx.x;
    if (p >= EE) return;
    int s = g_col[p], d = g_dstv[p];
    float w = __expf(leaky(g_as2[s] + g_ad2[d]));
    g_w2[p] = w;
    atomicAdd(&g_d2[d], w);
}

// ============ layer2 gather: warp per node ============
__global__ void k_gather2(const float* __restrict__ b2) {
    int n = (blockIdx.x * blockDim.x + threadIdx.x) >> 5;
    int lane = threadIdx.x & 31;
    if (n >= NN) return;
    int e0 = g_rowptr[n], e1 = g_rowptr[n + 1];
    float acc = 0.f;
    #pragma unroll 4
    for (int p = e0; p < e1; p++) {
        int s = g_col[p];
        acc += g_w2[p] * __ldg(&g_h2[s * 32 + lane]);
    }
    float ws = __expf(leaky(g_as2[n] + g_ad2[n]));
    acc += ws * g_h2[n * 32 + lane];
    float den = fmaxf(g_d2[n], 1e-16f);
    g_o2[n * 32 + lane] = acc / den + __ldg(&b2[lane]);
}

// ============ final linear ============
__global__ void __launch_bounds__(640) k_final(const float* __restrict__ linW,
                                               const float* __restrict__ linb,
                                               float* __restrict__ out) {
    __shared__ float lw[32 * 40];
    __shared__ float rows[16][32];
    int tid = threadIdx.x;
    for (int i = tid; i < 32 * 40; i += 640) lw[i] = linW[i];
    int nb = blockIdx.x * 16;
    for (int i = tid; i < 512; i += 640) {
        int r = i >> 5, c = i & 31;
        int n = nb + r;
        rows[r][c] = (n < NN) ? g_o2[n * 32 + c] : 0.f;
    }
    __syncthreads();
    int o = tid % 40, r = tid / 40;
    int n = nb + r;
    if (n < NN) {
        float acc = __ldg(&linb[o]);
        #pragma unroll
        for (int k = 0; k < 32; k++) acc += rows[r][k] * lw[k * 40 + o];
        out[(size_t)n * 40 + o] = acc;
    }
}

// ================= launch =================
extern "C" void kernel_launch(void* const* d_in, const int* in_sizes, int n_in,
                              void* d_out, int out_size) {
    const float* x0    = (const float*)d_in[0];
    const float* W1    = (const float*)d_in[1];
    const float* attS1 = (const float*)d_in[2];
    const float* attD1 = (const float*)d_in[3];
    const float* b1    = (const float*)d_in[4];
    const float* W2    = (const float*)d_in[5];
    const float* attS2 = (const float*)d_in[6];
    const float* attD2 = (const float*)d_in[7];
    const float* b2    = (const float*)d_in[8];
    const float* linW  = (const float*)d_in[9];
    const float* linb  = (const float*)d_in[10];
    const int*   ei    = (const int*)d_in[11];
    float* out = (float*)d_out;

    const int NBLK = (NN + 1023) / 1024;   // 98
    k_zero<<<(NN + 255) / 256, 256>>>();
    k_hist<<<(EE + 255) / 256, 256>>>(ei);
    k_scan1<<<NBLK, 1024>>>();
    k_scan2<<<1, 128>>>(NBLK);
    k_scan3<<<NBLK, 1024>>>();
    k_scatter<<<(EE + 255) / 256, 256>>>(ei);
    k_gemm1<<<dim3(2, (NN + 127) / 128), 256>>>(x0, W1);
    k_att1<<<(NN + 7) / 8, 256>>>(attS1, attD1);
    k_den1<<<(EE + 255) / 256, 256>>>();
    k_gather1<<<NN, 256>>>(b1);
    k_gemm2<<<NN / 8, 256>>>(W2, attS2, attD2);
    k_den2<<<(EE + 255) / 256, 256>>>();
    k_gather2<<<(NN + 7) / 8, 256>>>(b2);
    k_final<<<(NN + 15) / 16, 640>>>(linW, linb, out);
}

// round 7
// speedup vs baseline: 1.5202x; 1.3343x over previous
#include <cuda_runtime.h>
#include <cuda_bf16.h>
#include <cstdint>

#define NN   100000
#define EE   1000000
#define HID  32
#define NH1  8
#define OUTC 40
#define NEGS 0.2f

// ================= device scratch =================
__device__ __align__(16) float g_h1[(size_t)NN * 256];
__device__ __align__(16) float g_x2[(size_t)NN * 256];
__device__ __align__(16) float g_as1[NN * NH1];
__device__ __align__(16) float g_ad1[NN * NH1];
__device__ __align__(16) float g_h2[NN * HID];
__device__ __align__(16) float g_as2[NN];
__device__ __align__(16) float g_ad2[NN];
__device__ __align__(16) float g_o2[NN * HID];
__device__ int g_cnt[NN];
__device__ int g_rowptr[NN + 1];
__device__ int g_cursor[NN];
__device__ int g_col[EE];
__device__ int g_bsum[128];
__device__ int g_boff[128];

__device__ __forceinline__ float leaky(float x) { return x > 0.f ? x : NEGS * x; }

__device__ __forceinline__ uint32_t smem_u32(const void* p) {
    uint32_t a;
    asm("{ .reg .u64 t; cvta.to.shared.u64 t, %1; cvt.u32.u64 %0, t; }" : "=r"(a) : "l"(p));
    return a;
}

#define LDSM4(r0, r1, r2, r3, a) \
    asm volatile("ldmatrix.sync.aligned.m8n8.x4.shared.b16 {%0,%1,%2,%3}, [%4];" \
                 : "=r"(r0), "=r"(r1), "=r"(r2), "=r"(r3) : "r"(a))
#define LDSM2(r0, r1, a) \
    asm volatile("ldmatrix.sync.aligned.m8n8.x2.shared.b16 {%0,%1}, [%2];" \
                 : "=r"(r0), "=r"(r1) : "r"(a))
#define MMA16816(c, a0, a1, a2, a3, b0, b1) \
    asm volatile("mma.sync.aligned.m16n8k16.row.col.f32.bf16.bf16.f32 " \
                 "{%0,%1,%2,%3},{%4,%5,%6,%7},{%8,%9},{%0,%1,%2,%3};" \
                 : "+f"((c)[0]), "+f"((c)[1]), "+f"((c)[2]), "+f"((c)[3]) \
                 : "r"(a0), "r"(a1), "r"(a2), "r"(a3), "r"(b0), "r"(b1))

// ================= CSR build =================
__global__ void k_zero() {
    int i = blockIdx.x * blockDim.x + threadIdx.x;
    if (i < NN) g_cnt[i] = 0;
}
__global__ void k_hist(const int* __restrict__ ei) {
    int e = blockIdx.x * blockDim.x + threadIdx.x;
    if (e < EE) atomicAdd(&g_cnt[ei[EE + e]], 1);
}
__global__ void __launch_bounds__(1024) k_scan1() {
    __shared__ int ws[32];
    int tid = threadIdx.x, lane = tid & 31, wid = tid >> 5;
    int i = blockIdx.x * 1024 + tid;
    int v = (i < NN) ? g_cnt[i] : 0;
    int x = v;
    #pragma unroll
    for (int o = 1; o < 32; o <<= 1) {
        int y = __shfl_up_sync(0xffffffffu, x, o);
        if (lane >= o) x += y;
    }
    if (lane == 31) ws[wid] = x;
    __syncthreads();
    if (wid == 0) {
        int s = ws[lane];
        #pragma unroll
        for (int o = 1; o < 32; o <<= 1) {
            int y = __shfl_up_sync(0xffffffffu, s, o);
            if (lane >= o) s += y;
        }
        ws[lane] = s;
    }
    __syncthreads();
    int incl = x + (wid ? ws[wid - 1] : 0);
    if (i < NN) g_rowptr[i] = incl - v;
    if (tid == 1023) g_bsum[blockIdx.x] = incl;
}
__global__ void k_scan2(int nblk) {
    __shared__ int ws[4];
    int tid = threadIdx.x, lane = tid & 31, wid = tid >> 5;
    int v = (tid < nblk) ? g_bsum[tid] : 0;
    int x = v;
    #pragma unroll
    for (int o = 1; o < 32; o <<= 1) {
        int y = __shfl_up_sync(0xffffffffu, x, o);
        if (lane >= o) x += y;
    }
    if (lane == 31) ws[wid] = x;
    __syncthreads();
    int pre = 0;
    for (int w = 0; w < wid; w++) pre += ws[w];
    int incl = x + pre;
    if (tid < nblk) g_boff[tid] = incl - v;
    if (tid == nblk - 1) g_rowptr[NN] = incl;
}
__global__ void __launch_bounds__(1024) k_scan3() {
    int i = blockIdx.x * 1024 + threadIdx.x;
    if (i < NN) {
        int r = g_rowptr[i] + g_boff[blockIdx.x];
        g_rowptr[i] = r;
        g_cursor[i] = r;
    }
}
__global__ void k_scatter(const int* __restrict__ ei) {
    int e = blockIdx.x * blockDim.x + threadIdx.x;
    if (e < EE) {
        int s = ei[e];
        int d = ei[EE + e];
        int pos = atomicAdd(&g_cursor[d], 1);
        g_col[pos] = s;
    }
}

// ======== GEMM1 via mma.sync bf16 split: h1 = x0 @ W1  (128x128 tile, K=128) ========
#define SKEW 136                    // bf16 elems per smem row (128 + 8 pad)
#define SA_HI 0
#define SA_LO 34816
#define SB_HI 69632
#define SB_LO 104448
#define SM_G1 139264

__global__ void __launch_bounds__(256) k_gemm1_mma(const float* __restrict__ x0,
                                                   const float* __restrict__ W1) {
    extern __shared__ __align__(128) char smem[];
    __nv_bfloat16* sAhi = (__nv_bfloat16*)(smem + SA_HI);
    __nv_bfloat16* sAlo = (__nv_bfloat16*)(smem + SA_LO);
    __nv_bfloat16* sBhi = (__nv_bfloat16*)(smem + SB_HI);
    __nv_bfloat16* sBlo = (__nv_bfloat16*)(smem + SB_LO);
    uint32_t sb = smem_u32(smem);

    int tid = threadIdx.x;
    int rowBase = blockIdx.y * 128;
    int colBase = blockIdx.x * 128;

    // stage A: x0[rowBase..+128][0..128] -> bf16 hi/lo
    #pragma unroll 8
    for (int i = 0; i < 64; i++) {
        int idx = i * 256 + tid;
        int r = idx >> 7, c = idx & 127;
        int grow = rowBase + r;
        float v = (grow < NN) ? __ldg(&x0[(size_t)grow * 128 + c]) : 0.f;
        __nv_bfloat16 hi = __float2bfloat16(v);
        __nv_bfloat16 lo = __float2bfloat16(v - __bfloat162float(hi));
        sAhi[r * SKEW + c] = hi;
        sAlo[r * SKEW + c] = lo;
    }
    // stage B transposed: sB[n][k] = W1[k][colBase+n]
    #pragma unroll 8
    for (int i = 0; i < 64; i++) {
        int idx = i * 256 + tid;
        int k = idx >> 7, nl = idx & 127;
        float v = __ldg(&W1[(size_t)k * 256 + colBase + nl]);
        __nv_bfloat16 hi = __float2bfloat16(v);
        __nv_bfloat16 lo = __float2bfloat16(v - __bfloat162float(hi));
        sBhi[nl * SKEW + k] = hi;
        sBlo[nl * SKEW + k] = lo;
    }
    __syncthreads();

    int wid = tid >> 5, lane = tid & 31;
    int warpM = wid >> 2, warpN = wid & 3;        // 2 x 4 warp grid, warp tile 64x32

    float acc[4][4][4];
    #pragma unroll
    for (int mt = 0; mt < 4; mt++)
        #pragma unroll
        for (int nt = 0; nt < 4; nt++)
            #pragma unroll
            for (int q = 0; q < 4; q++) acc[mt][nt][q] = 0.f;

    // lane-dependent ldmatrix address components
    int aRow = warpM * 64 + (lane & 15);          // + mt*16
    int aColHalf = (lane >> 4) * 8;               // 0 or 8 within k16
    int bRow = warpN * 32 + (lane & 7);           // + nt*8
    int bColHalf = ((lane >> 3) & 1) * 8;

    uint32_t aBasePass[3] = {sb + SA_HI, sb + SA_HI, sb + SA_LO};
    uint32_t bBasePass[3] = {sb + SB_HI, sb + SB_LO, sb + SB_HI};

    #pragma unroll 1
    for (int pass = 0; pass < 3; pass++) {
        uint32_t aB = aBasePass[pass];
        uint32_t bB = bBasePass[pass];
        #pragma unroll
        for (int ks = 0; ks < 8; ks++) {
            uint32_t a[4][4], b[4][2];
            #pragma unroll
            for (int mt = 0; mt < 4; mt++) {
                uint32_t addr = aB + (uint32_t)(((aRow + mt * 16) * SKEW) + ks * 16 + aColHalf) * 2;
                LDSM4(a[mt][0], a[mt][1], a[mt][2], a[mt][3], addr);
            }
            #pragma unroll
            for (int nt = 0; nt < 4; nt++) {
                uint32_t addr = bB + (uint32_t)(((bRow + nt * 8) * SKEW) + ks * 16 + bColHalf) * 2;
                LDSM2(b[nt][0], b[nt][1], addr);
            }
            #pragma unroll
            for (int mt = 0; mt < 4; mt++)
                #pragma unroll
                for (int nt = 0; nt < 4; nt++)
                    MMA16816(acc[mt][nt], a[mt][0], a[mt][1], a[mt][2], a[mt][3],
                             b[nt][0], b[nt][1]);
        }
    }

    // epilogue
    int rq = lane >> 2, cq = (lane & 3) * 2;
    #pragma unroll
    for (int mt = 0; mt < 4; mt++) {
        #pragma unroll
        for (int nt = 0; nt < 4; nt++) {
            int r0 = rowBase + warpM * 64 + mt * 16 + rq;
            int cc = colBase + warpN * 32 + nt * 8 + cq;
            if (r0 < NN)
                *(float2*)&g_h1[(size_t)r0 * 256 + cc] =
                    make_float2(acc[mt][nt][0], acc[mt][nt][1]);
            int r1 = r0 + 8;
            if (r1 < NN)
                *(float2*)&g_h1[(size_t)r1 * 256 + cc] =
                    make_float2(acc[mt][nt][2], acc[mt][nt][3]);
        }
    }
}

// ============ att dots layer1 ============
__global__ void k_att1(const float* __restrict__ attS, const float* __restrict__ attD) {
    int warp = (blockIdx.x * blockDim.x + threadIdx.x) >> 5;
    int lane = threadIdx.x & 31;
    if (warp >= NN) return;
    const float* hrow = g_h1 + (size_t)warp * 256;
    #pragma unroll
    for (int h = 0; h < NH1; h++) {
        float v = hrow[h * 32 + lane];
        float ps = v * __ldg(&attS[h * 32 + lane]);
        float pd = v * __ldg(&attD[h * 32 + lane]);
        #pragma unroll
        for (int o = 16; o; o >>= 1) {
            ps += __shfl_xor_sync(0xffffffffu, ps, o);
            pd += __shfl_xor_sync(0xffffffffu, pd, o);
        }
        if (lane == 0) {
            g_as1[warp * 8 + h] = ps;
            g_ad1[warp * 8 + h] = pd;
        }
    }
}

// ============ GAT1 fused, no-max, independent edge iterations ============
__global__ void __launch_bounds__(256) k_gat1(const float* __restrict__ b1) {
    int n = (blockIdx.x * blockDim.x + threadIdx.x) >> 5;
    int lane = threadIdx.x & 31;
    if (n >= NN) return;

    float adst = (lane < 8) ? g_ad1[n * 8 + lane] : 0.f;
    float den = 0.f;
    float acc[8];
    #pragma unroll
    for (int h = 0; h < 8; h++) acc[h] = 0.f;

    int e0 = g_rowptr[n], e1 = g_rowptr[n + 1];
    #pragma unroll 2
    for (int p = e0 - 1; p < e1; p++) {          // p = e0-1 is the self loop
        int s = (p < e0) ? n : g_col[p];
        float a = (lane < 8) ? __ldg(&g_as1[s * 8 + lane]) : 0.f;
        float w = __expf(leaky(a + adst));       // lanes>=8 compute garbage, never read
        den += w;
        const float* hs = g_h1 + (size_t)s * 256;
        #pragma unroll
        for (int h = 0; h < 8; h++) {
            float wh = __shfl_sync(0xffffffffu, w, h);
            acc[h] += wh * __ldg(&hs[h * 32 + lane]);
        }
    }
    float* orow = g_x2 + (size_t)n * 256;
    #pragma unroll
    for (int h = 0; h < 8; h++) {
        float dh = __shfl_sync(0xffffffffu, den, h);
        float r = acc[h] / fmaxf(dh, 1e-16f) + __ldg(&b1[h * 32 + lane]);
        orow[h * 32 + lane] = fmaxf(r, 0.f);
    }
}

// ============ GEMM2 + att2 dots ============
__global__ void __launch_bounds__(256) k_gemm2(const float* __restrict__ W2,
                                               const float* __restrict__ attS2,
                                               const float* __restrict__ attD2) {
    __shared__ float W2s[256 * 32];
    int tid = threadIdx.x;
    for (int i = tid; i < 256 * 32; i += 256) W2s[i] = W2[i];
    __syncthreads();
    int lane = tid & 31, wl = tid >> 5;
    int n = blockIdx.x * 8 + wl;
    const float* xr = g_x2 + (size_t)n * 256;
    float acc = 0.f;
    #pragma unroll
    for (int c = 0; c < 8; c++) {
        float xv = xr[c * 32 + lane];
        #pragma unroll
        for (int j = 0; j < 32; j++) {
            float xb = __shfl_sync(0xffffffffu, xv, j);
            acc += xb * W2s[(c * 32 + j) * 32 + lane];
        }
    }
    g_h2[n * 32 + lane] = acc;
    float ps = acc * __ldg(&attS2[lane]);
    float pd = acc * __ldg(&attD2[lane]);
    #pragma unroll
    for (int o = 16; o; o >>= 1) {
        ps += __shfl_xor_sync(0xffffffffu, ps, o);
        pd += __shfl_xor_sync(0xffffffffu, pd, o);
    }
    if (lane == 0) {
        g_as2[n] = ps;
        g_ad2[n] = pd;
    }
}

// ============ GAT2 fused, no-max (w uniform across warp, zero shuffles) ============
__global__ void __launch_bounds__(256) k_gat2(const float* __restrict__ b2) {
    int n = (blockIdx.x * blockDim.x + threadIdx.x) >> 5;
    int lane = threadIdx.x & 31;
    if (n >= NN) return;
    float adst = g_ad2[n];
    float den = 0.f, acc = 0.f;
    int e0 = g_rowptr[n], e1 = g_rowptr[n + 1];
    #pragma unroll 4
    for (int p = e0 - 1; p < e1; p++) {
        int s = (p < e0) ? n : g_col[p];
        float w = __expf(leaky(__ldg(&g_as2[s]) + adst));
        den += w;
        acc += w * __ldg(&g_h2[s * 32 + lane]);
    }
    g_o2[n * 32 + lane] = acc / fmaxf(den, 1e-16f) + __ldg(&b2[lane]);
}

// ============ final linear ============
__global__ void __launch_bounds__(640) k_final(const float* __restrict__ linW,
                                               const float* __restrict__ linb,
                                               float* __restrict__ out) {
    __shared__ float lw[32 * 40];
    __shared__ float rows[16][32];
    int tid = threadIdx.x;
    for (int i = tid; i < 32 * 40; i += 640) lw[i] = linW[i];
    int nb = blockIdx.x * 16;
    for (int i = tid; i < 512; i += 640) {
        int r = i >> 5, c = i & 31;
        int n = nb + r;
        rows[r][c] = (n < NN) ? g_o2[n * 32 + c] : 0.f;
    }
    __syncthreads();
    int o = tid % 40, r = tid / 40;
    int n = nb + r;
    if (n < NN) {
        float acc = __ldg(&linb[o]);
        #pragma unroll
        for (int k = 0; k < 32; k++) acc += rows[r][k] * lw[k * 40 + o];
        out[(size_t)n * 40 + o] = acc;
    }
}

// ================= launch =================
extern "C" void kernel_launch(void* const* d_in, const int* in_sizes, int n_in,
                              void* d_out, int out_size) {
    const float* x0    = (const float*)d_in[0];
    const float* W1    = (const float*)d_in[1];
    const float* attS1 = (const float*)d_in[2];
    const float* attD1 = (const float*)d_in[3];
    const float* b1    = (const float*)d_in[4];
    const float* W2    = (const float*)d_in[5];
    const float* attS2 = (const float*)d_in[6];
    const float* attD2 = (const float*)d_in[7];
    const float* b2    = (const float*)d_in[8];
    const float* linW  = (const float*)d_in[9];
    const float* linb  = (const float*)d_in[10];
    const int*   ei    = (const int*)d_in[11];
    float* out = (float*)d_out;

    static int smemSet = 0;
    if (!smemSet) {
        cudaFuncSetAttribute(k_gemm1_mma, cudaFuncAttributeMaxDynamicSharedMemorySize, SM_G1);
        smemSet = 1;
    }

    const int NBLK = (NN + 1023) / 1024;   // 98
    k_zero<<<(NN + 255) / 256, 256>>>();
    k_hist<<<(EE + 255) / 256, 256>>>(ei);
    k_scan1<<<NBLK, 1024>>>();
    k_scan2<<<1, 128>>>(NBLK);
    k_scan3<<<NBLK, 1024>>>();
    k_scatter<<<(EE + 255) / 256, 256>>>(ei);
    k_gemm1_mma<<<dim3(2, (NN + 127) / 128), 256, SM_G1>>>(x0, W1);
    k_att1<<<(NN + 7) / 8, 256>>>(attS1, attD1);
    k_gat1<<<(NN + 7) / 8, 256>>>(b1);
    k_gemm2<<<NN / 8, 256>>>(W2, attS2, attD2);
    k_gat2<<<(NN + 7) / 8, 256>>>(b2);
    k_final<<<(NN + 15) / 16, 640>>>(linW, linb, out);
}

// round 8
// speedup vs baseline: 1.8876x; 1.2417x over previous
#include <cuda_runtime.h>
#include <cuda_bf16.h>
#include <cstdint>

#define NN   100000
#define EE   1000000
#define HID  32
#define NH1  8
#define OUTC 40
#define NEGS 0.2f

// ================= device scratch =================
__device__ __align__(16) float g_h1[(size_t)NN * 256];
__device__ __align__(16) float g_x2[(size_t)NN * 256];
__device__ __align__(16) float g_as1[NN * NH1];
__device__ __align__(16) float g_ad1[NN * NH1];
__device__ __align__(16) float g_h2[NN * HID];
__device__ __align__(16) float g_as2[NN];
__device__ __align__(16) float g_ad2[NN];
__device__ int g_cnt[NN];
__device__ int g_rowptr[NN + 1];
__device__ int g_cursor[NN];
__device__ int g_col[EE];
__device__ int g_bsum[128];
__device__ int g_boff[128];

__device__ __forceinline__ float leaky(float x) { return x > 0.f ? x : NEGS * x; }

__device__ __forceinline__ uint32_t smem_u32(const void* p) {
    uint32_t a;
    asm("{ .reg .u64 t; cvta.to.shared.u64 t, %1; cvt.u32.u64 %0, t; }" : "=r"(a) : "l"(p));
    return a;
}

#define LDSM4(r0, r1, r2, r3, a) \
    asm volatile("ldmatrix.sync.aligned.m8n8.x4.shared.b16 {%0,%1,%2,%3}, [%4];" \
                 : "=r"(r0), "=r"(r1), "=r"(r2), "=r"(r3) : "r"(a))
#define LDSM2(r0, r1, a) \
    asm volatile("ldmatrix.sync.aligned.m8n8.x2.shared.b16 {%0,%1}, [%2];" \
                 : "=r"(r0), "=r"(r1) : "r"(a))
#define MMA16816(c, a0, a1, a2, a3, b0, b1) \
    asm volatile("mma.sync.aligned.m16n8k16.row.col.f32.bf16.bf16.f32 " \
                 "{%0,%1,%2,%3},{%4,%5,%6,%7},{%8,%9},{%0,%1,%2,%3};" \
                 : "+f"((c)[0]), "+f"((c)[1]), "+f"((c)[2]), "+f"((c)[3]) \
                 : "r"(a0), "r"(a1), "r"(a2), "r"(a3), "r"(b0), "r"(b1))

// ================= CSR build =================
__global__ void k_zero() {
    int i = blockIdx.x * blockDim.x + threadIdx.x;
    if (i < NN) g_cnt[i] = 0;
}
__global__ void k_hist(const int* __restrict__ ei) {
    int e = blockIdx.x * blockDim.x + threadIdx.x;
    if (e < EE) atomicAdd(&g_cnt[ei[EE + e]], 1);
}
__global__ void __launch_bounds__(1024) k_scan1() {
    __shared__ int ws[32];
    int tid = threadIdx.x, lane = tid & 31, wid = tid >> 5;
    int i = blockIdx.x * 1024 + tid;
    int v = (i < NN) ? g_cnt[i] : 0;
    int x = v;
    #pragma unroll
    for (int o = 1; o < 32; o <<= 1) {
        int y = __shfl_up_sync(0xffffffffu, x, o);
        if (lane >= o) x += y;
    }
    if (lane == 31) ws[wid] = x;
    __syncthreads();
    if (wid == 0) {
        int s = ws[lane];
        #pragma unroll
        for (int o = 1; o < 32; o <<= 1) {
            int y = __shfl_up_sync(0xffffffffu, s, o);
            if (lane >= o) s += y;
        }
        ws[lane] = s;
    }
    __syncthreads();
    int incl = x + (wid ? ws[wid - 1] : 0);
    if (i < NN) g_rowptr[i] = incl - v;
    if (tid == 1023) g_bsum[blockIdx.x] = incl;
}
__global__ void k_scan2(int nblk) {
    __shared__ int ws[4];
    int tid = threadIdx.x, lane = tid & 31, wid = tid >> 5;
    int v = (tid < nblk) ? g_bsum[tid] : 0;
    int x = v;
    #pragma unroll
    for (int o = 1; o < 32; o <<= 1) {
        int y = __shfl_up_sync(0xffffffffu, x, o);
        if (lane >= o) x += y;
    }
    if (lane == 31) ws[wid] = x;
    __syncthreads();
    int pre = 0;
    for (int w = 0; w < wid; w++) pre += ws[w];
    int incl = x + pre;
    if (tid < nblk) g_boff[tid] = incl - v;
    if (tid == nblk - 1) g_rowptr[NN] = incl;
}
__global__ void __launch_bounds__(1024) k_scan3() {
    int i = blockIdx.x * 1024 + threadIdx.x;
    if (i < NN) {
        int r = g_rowptr[i] + g_boff[blockIdx.x];
        g_rowptr[i] = r;
        g_cursor[i] = r;
    }
}
__global__ void k_scatter(const int* __restrict__ ei) {
    int e = blockIdx.x * blockDim.x + threadIdx.x;
    if (e < EE) {
        int s = ei[e];
        int d = ei[EE + e];
        int pos = atomicAdd(&g_cursor[d], 1);
        g_col[pos] = s;
    }
}

// ======== GEMM1 (bf16-split mma) + fused att1 dots.  One CTA: 128 rows, both col tiles ====
#define SKEW 136
#define SA_HI 0
#define SA_LO 34816
#define SB_HI 69632
#define SB_LO 104448
#define SM_G1 139264

__global__ void __launch_bounds__(256) k_gemm1_mma(const float* __restrict__ x0,
                                                   const float* __restrict__ W1,
                                                   const float* __restrict__ attS,
                                                   const float* __restrict__ attD) {
    extern __shared__ __align__(128) char smem[];
    __nv_bfloat16* sAhi = (__nv_bfloat16*)(smem + SA_HI);
    __nv_bfloat16* sAlo = (__nv_bfloat16*)(smem + SA_LO);
    __nv_bfloat16* sBhi = (__nv_bfloat16*)(smem + SB_HI);
    __nv_bfloat16* sBlo = (__nv_bfloat16*)(smem + SB_LO);
    uint32_t sb = smem_u32(smem);

    int tid = threadIdx.x;
    int rowBase = blockIdx.x * 128;

    // stage A once: x0[rowBase..+128][0..128] -> bf16 hi/lo
    #pragma unroll 8
    for (int i = 0; i < 64; i++) {
        int idx = i * 256 + tid;
        int r = idx >> 7, c = idx & 127;
        int grow = rowBase + r;
        float v = (grow < NN) ? __ldg(&x0[(size_t)grow * 128 + c]) : 0.f;
        __nv_bfloat16 hi = __float2bfloat16(v);
        __nv_bfloat16 lo = __float2bfloat16(v - __bfloat162float(hi));
        sAhi[r * SKEW + c] = hi;
        sAlo[r * SKEW + c] = lo;
    }

    int wid = tid >> 5, lane = tid & 31;
    int warpM = wid >> 2, warpN = wid & 3;
    int aRow = warpM * 64 + (lane & 15);
    int aColHalf = (lane >> 4) * 8;
    int bRow = warpN * 32 + (lane & 7);
    int bColHalf = ((lane >> 3) & 1) * 8;
    int rq = lane >> 2, cq = (lane & 3) * 2;

    #pragma unroll 1
    for (int ct = 0; ct < 2; ct++) {
        int colBase = ct * 128;
        __syncthreads();           // A staged (ct=0) / previous compute done (ct=1)
        // stage B: sB[n][k] = W1[k][colBase+n]
        #pragma unroll 8
        for (int i = 0; i < 64; i++) {
            int idx = i * 256 + tid;
            int k = idx >> 7, nl = idx & 127;
            float v = __ldg(&W1[(size_t)k * 256 + colBase + nl]);
            __nv_bfloat16 hi = __float2bfloat16(v);
            __nv_bfloat16 lo = __float2bfloat16(v - __bfloat162float(hi));
            sBhi[nl * SKEW + k] = hi;
            sBlo[nl * SKEW + k] = lo;
        }
        __syncthreads();

        float acc[4][4][4];
        #pragma unroll
        for (int mt = 0; mt < 4; mt++)
            #pragma unroll
            for (int nt = 0; nt < 4; nt++)
                #pragma unroll
                for (int q = 0; q < 4; q++) acc[mt][nt][q] = 0.f;

        uint32_t aBasePass[3] = {sb + SA_HI, sb + SA_HI, sb + SA_LO};
        uint32_t bBasePass[3] = {sb + SB_HI, sb + SB_LO, sb + SB_HI};

        #pragma unroll 1
        for (int pass = 0; pass < 3; pass++) {
            uint32_t aB = aBasePass[pass];
            uint32_t bB = bBasePass[pass];
            #pragma unroll
            for (int ks = 0; ks < 8; ks++) {
                uint32_t a[4][4], b[4][2];
                #pragma unroll
                for (int mt = 0; mt < 4; mt++) {
                    uint32_t addr = aB + (uint32_t)(((aRow + mt * 16) * SKEW) + ks * 16 + aColHalf) * 2;
                    LDSM4(a[mt][0], a[mt][1], a[mt][2], a[mt][3], addr);
                }
                #pragma unroll
                for (int nt = 0; nt < 4; nt++) {
                    uint32_t addr = bB + (uint32_t)(((bRow + nt * 8) * SKEW) + ks * 16 + bColHalf) * 2;
                    LDSM2(b[nt][0], b[nt][1], addr);
                }
                #pragma unroll
                for (int mt = 0; mt < 4; mt++)
                    #pragma unroll
                    for (int nt = 0; nt < 4; nt++)
                        MMA16816(acc[mt][nt], a[mt][0], a[mt][1], a[mt][2], a[mt][3],
                                 b[nt][0], b[nt][1]);
            }
        }

        // epilogue: h1 store + fused att dots (warp's 32 cols == one head)
        int h = ct * 4 + warpN;
        float aS[8], aD[8];
        #pragma unroll
        for (int nt = 0; nt < 4; nt++) {
            aS[nt * 2 + 0] = __ldg(&attS[h * 32 + nt * 8 + cq]);
            aS[nt * 2 + 1] = __ldg(&attS[h * 32 + nt * 8 + cq + 1]);
            aD[nt * 2 + 0] = __ldg(&attD[h * 32 + nt * 8 + cq]);
            aD[nt * 2 + 1] = __ldg(&attD[h * 32 + nt * 8 + cq + 1]);
        }
        #pragma unroll
        for (int mt = 0; mt < 4; mt++) {
            int r0 = rowBase + warpM * 64 + mt * 16 + rq;
            int r1 = r0 + 8;
            float ps0 = 0.f, pd0 = 0.f, ps1 = 0.f, pd1 = 0.f;
            #pragma unroll
            for (int nt = 0; nt < 4; nt++) {
                ps0 += acc[mt][nt][0] * aS[nt * 2] + acc[mt][nt][1] * aS[nt * 2 + 1];
                pd0 += acc[mt][nt][0] * aD[nt * 2] + acc[mt][nt][1] * aD[nt * 2 + 1];
                ps1 += acc[mt][nt][2] * aS[nt * 2] + acc[mt][nt][3] * aS[nt * 2 + 1];
                pd1 += acc[mt][nt][2] * aD[nt * 2] + acc[mt][nt][3] * aD[nt * 2 + 1];
                int cc = colBase + warpN * 32 + nt * 8 + cq;
                if (r0 < NN)
                    *(float2*)&g_h1[(size_t)r0 * 256 + cc] =
                        make_float2(acc[mt][nt][0], acc[mt][nt][1]);
                if (r1 < NN)
                    *(float2*)&g_h1[(size_t)r1 * 256 + cc] =
                        make_float2(acc[mt][nt][2], acc[mt][nt][3]);
            }
            #pragma unroll
            for (int o = 1; o <= 2; o <<= 1) {
                ps0 += __shfl_xor_sync(0xffffffffu, ps0, o);
                pd0 += __shfl_xor_sync(0xffffffffu, pd0, o);
                ps1 += __shfl_xor_sync(0xffffffffu, ps1, o);
                pd1 += __shfl_xor_sync(0xffffffffu, pd1, o);
            }
            if ((lane & 3) == 0) {
                if (r0 < NN) { g_as1[r0 * 8 + h] = ps0; g_ad1[r0 * 8 + h] = pd0; }
                if (r1 < NN) { g_as1[r1 * 8 + h] = ps1; g_ad1[r1 * 8 + h] = pd1; }
            }
        }
    }
}

// ============ GAT1: per-lane head ownership, float4 gathers, zero shuffles ============
__global__ void __launch_bounds__(256) k_gat1(const float* __restrict__ b1) {
    int n = (blockIdx.x * blockDim.x + threadIdx.x) >> 5;
    int lane = threadIdx.x & 31;
    if (n >= NN) return;
    int ha = lane >> 3, hb = ha + 4;
    int c4 = (lane & 7) * 4;

    float adA = __ldg(&g_ad1[n * 8 + ha]);
    float adB = __ldg(&g_ad1[n * 8 + hb]);
    float denA = 0.f, denB = 0.f;
    float4 accA = make_float4(0.f, 0.f, 0.f, 0.f);
    float4 accB = make_float4(0.f, 0.f, 0.f, 0.f);

    int e0 = g_rowptr[n], e1 = g_rowptr[n + 1];
    #pragma unroll 4
    for (int p = e0 - 1; p < e1; p++) {          // p = e0-1 is the self loop
        int s = (p < e0) ? n : __ldg(&g_col[p]);
        float wa = __expf(leaky(__ldg(&g_as1[s * 8 + ha]) + adA));
        float wb = __expf(leaky(__ldg(&g_as1[s * 8 + hb]) + adB));
        denA += wa; denB += wb;
        float4 va = __ldg((const float4*)&g_h1[(size_t)s * 256 + ha * 32 + c4]);
        float4 vb = __ldg((const float4*)&g_h1[(size_t)s * 256 + hb * 32 + c4]);
        accA.x += wa * va.x; accA.y += wa * va.y; accA.z += wa * va.z; accA.w += wa * va.w;
        accB.x += wb * vb.x; accB.y += wb * vb.y; accB.z += wb * vb.z; accB.w += wb * vb.w;
    }
    float iA = 1.f / fmaxf(denA, 1e-16f);
    float iB = 1.f / fmaxf(denB, 1e-16f);
    float4 bA = __ldg((const float4*)&b1[ha * 32 + c4]);
    float4 bB = __ldg((const float4*)&b1[hb * 32 + c4]);
    float4 rA = make_float4(fmaxf(accA.x * iA + bA.x, 0.f), fmaxf(accA.y * iA + bA.y, 0.f),
                            fmaxf(accA.z * iA + bA.z, 0.f), fmaxf(accA.w * iA + bA.w, 0.f));
    float4 rB = make_float4(fmaxf(accB.x * iB + bB.x, 0.f), fmaxf(accB.y * iB + bB.y, 0.f),
                            fmaxf(accB.z * iB + bB.z, 0.f), fmaxf(accB.w * iB + bB.w, 0.f));
    __stcs((float4*)&g_x2[(size_t)n * 256 + ha * 32 + c4], rA);   // evict-first: keep h1 in L2
    __stcs((float4*)&g_x2[(size_t)n * 256 + hb * 32 + c4], rB);
}

// ============ GEMM2 + att2 dots ============
__global__ void __launch_bounds__(256) k_gemm2(const float* __restrict__ W2,
                                               const float* __restrict__ attS2,
                                               const float* __restrict__ attD2) {
    __shared__ float W2s[256 * 32];
    int tid = threadIdx.x;
    for (int i = tid; i < 256 * 32; i += 256) W2s[i] = W2[i];
    __syncthreads();
    int lane = tid & 31, wl = tid >> 5;
    int n = blockIdx.x * 8 + wl;
    const float* xr = g_x2 + (size_t)n * 256;
    float acc = 0.f;
    #pragma unroll
    for (int c = 0; c < 8; c++) {
        float xv = __ldcs(&xr[c * 32 + lane]);
        #pragma unroll
        for (int j = 0; j < 32; j++) {
            float xb = __shfl_sync(0xffffffffu, xv, j);
            acc += xb * W2s[(c * 32 + j) * 32 + lane];
        }
    }
    g_h2[n * 32 + lane] = acc;
    float ps = acc * __ldg(&attS2[lane]);
    float pd = acc * __ldg(&attD2[lane]);
    #pragma unroll
    for (int o = 16; o; o >>= 1) {
        ps += __shfl_xor_sync(0xffffffffu, ps, o);
        pd += __shfl_xor_sync(0xffffffffu, pd, o);
    }
    if (lane == 0) {
        g_as2[n] = ps;
        g_ad2[n] = pd;
    }
}

// ============ GAT2 (4-edge groups, float4) + fused final linear ============
__global__ void __launch_bounds__(256) k_gat2(const float* __restrict__ b2,
                                              const float* __restrict__ linW,
                                              const float* __restrict__ linb,
                                              float* __restrict__ out) {
    __shared__ float lw[32 * 40];
    __shared__ float rows[8][32];
    int tid = threadIdx.x;
    for (int i = tid; i < 32 * 40; i += 256) lw[i] = linW[i];

    int wl = tid >> 5, lane = tid & 31;
    int n = blockIdx.x * 8 + wl;                 // grid 12500 -> exact
    int grp = lane >> 3, c4 = (lane & 7) * 4;

    float adst = g_ad2[n];
    float asn  = g_as2[n];
    float den; float4 acc;
    {
        float ws = __expf(leaky(asn + adst));    // self loop, counted once (group 0)
        if (grp == 0) {
            float4 h = __ldg((const float4*)&g_h2[n * 32 + c4]);
            den = ws;
            acc = make_float4(ws * h.x, ws * h.y, ws * h.z, ws * h.w);
        } else {
            den = 0.f;
            acc = make_float4(0.f, 0.f, 0.f, 0.f);
        }
    }
    int e0 = g_rowptr[n], e1 = g_rowptr[n + 1];
    #pragma unroll 2
    for (int p0 = e0; p0 < e1; p0 += 4) {
        int p = p0 + grp;
        bool v = p < e1;
        int s = v ? __ldg(&g_col[p]) : n;
        float w = v ? __expf(leaky(__ldg(&g_as2[s]) + adst)) : 0.f;
        den += w;
        float4 h = __ldg((const float4*)&g_h2[s * 32 + c4]);
        acc.x += w * h.x; acc.y += w * h.y; acc.z += w * h.z; acc.w += w * h.w;
    }
    // reduce across 4 groups
    #pragma unroll
    for (int o = 8; o <= 16; o <<= 1) {
        acc.x += __shfl_xor_sync(0xffffffffu, acc.x, o);
        acc.y += __shfl_xor_sync(0xffffffffu, acc.y, o);
        acc.z += __shfl_xor_sync(0xffffffffu, acc.z, o);
        acc.w += __shfl_xor_sync(0xffffffffu, acc.w, o);
        den   += __shfl_xor_sync(0xffffffffu, den, o);
    }
    if (grp == 0) {
        float inv = 1.f / fmaxf(den, 1e-16f);
        float4 bb = __ldg((const float4*)&b2[c4]);
        rows[wl][c4 + 0] = acc.x * inv + bb.x;
        rows[wl][c4 + 1] = acc.y * inv + bb.y;
        rows[wl][c4 + 2] = acc.z * inv + bb.z;
        rows[wl][c4 + 3] = acc.w * inv + bb.w;
    }
    __syncthreads();
    // final linear: 8 nodes x 40 outputs = 320 results
    int nb = blockIdx.x * 8;
    for (int t = tid; t < 320; t += 256) {
        int r = t / 40, o = t % 40;
        float s = __ldg(&linb[o]);
        #pragma unroll
        for (int k = 0; k < 32; k++) s += rows[r][k] * lw[k * 40 + o];
        out[(size_t)(nb + r) * 40 + o] = s;
    }
}

// ================= launch =================
extern "C" void kernel_launch(void* const* d_in, const int* in_sizes, int n_in,
                              void* d_out, int out_size) {
    const float* x0    = (const float*)d_in[0];
    const float* W1    = (const float*)d_in[1];
    const float* attS1 = (const float*)d_in[2];
    const float* attD1 = (const float*)d_in[3];
    const float* b1    = (const float*)d_in[4];
    const float* W2    = (const float*)d_in[5];
    const float* attS2 = (const float*)d_in[6];
    const float* attD2 = (const float*)d_in[7];
    const float* b2    = (const float*)d_in[8];
    const float* linW  = (const float*)d_in[9];
    const float* linb  = (const float*)d_in[10];
    const int*   ei    = (const int*)d_in[11];
    float* out = (float*)d_out;

    static int smemSet = 0;
    if (!smemSet) {
        cudaFuncSetAttribute(k_gemm1_mma, cudaFuncAttributeMaxDynamicSharedMemorySize, SM_G1);
        smemSet = 1;
    }

    const int NBLK = (NN + 1023) / 1024;   // 98
    k_zero<<<(NN + 255) / 256, 256>>>();
    k_hist<<<(EE + 255) / 256, 256>>>(ei);
    k_scan1<<<NBLK, 1024>>>();
    k_scan2<<<1, 128>>>(NBLK);
    k_scan3<<<NBLK, 1024>>>();
    k_scatter<<<(EE + 255) / 256, 256>>>(ei);
    k_gemm1_mma<<<(NN + 127) / 128, 256, SM_G1>>>(x0, W1, attS1, attD1);
    k_gat1<<<(NN + 7) / 8, 256>>>(b1);
    k_gemm2<<<NN / 8, 256>>>(W2, attS2, attD2);
    k_gat2<<<NN / 8, 256>>>(b2, linW, linb, out);
}

// round 9
// speedup vs baseline: 2.0029x; 1.0611x over previous
#include <cuda_runtime.h>
#include <cuda_bf16.h>
#include <cuda_fp16.h>
#include <cstdint>

#define NN   100000
#define EE   1000000
#define HID  32
#define NH1  8
#define OUTC 40
#define NEGS 0.2f

// ================= device scratch =================
__device__ __align__(16) __half g_h1h[(size_t)NN * 256];   // layer1 messages, fp16
__device__ __align__(16) float g_x2[(size_t)NN * 256];
__device__ __align__(16) float g_as1[NN * NH1];
__device__ __align__(16) float g_ad1[NN * NH1];
__device__ __align__(16) __half g_h2h[NN * HID];           // layer2 messages, fp16
__device__ __align__(16) float g_as2[NN];
__device__ __align__(16) float g_ad2[NN];
__device__ int g_cnt[NN];
__device__ int g_rowptr[NN + 1];
__device__ int g_cursor[NN];
__device__ int g_col[EE];
__device__ int g_bsum[128];
__device__ int g_boff[128];

__device__ __forceinline__ float leaky(float x) { return x > 0.f ? x : NEGS * x; }

__device__ __forceinline__ uint32_t smem_u32(const void* p) {
    uint32_t a;
    asm("{ .reg .u64 t; cvta.to.shared.u64 t, %1; cvt.u32.u64 %0, t; }" : "=r"(a) : "l"(p));
    return a;
}

#define LDSM4(r0, r1, r2, r3, a) \
    asm volatile("ldmatrix.sync.aligned.m8n8.x4.shared.b16 {%0,%1,%2,%3}, [%4];" \
                 : "=r"(r0), "=r"(r1), "=r"(r2), "=r"(r3) : "r"(a))
#define LDSM2(r0, r1, a) \
    asm volatile("ldmatrix.sync.aligned.m8n8.x2.shared.b16 {%0,%1}, [%2];" \
                 : "=r"(r0), "=r"(r1) : "r"(a))
#define MMA16816(c, a0, a1, a2, a3, b0, b1) \
    asm volatile("mma.sync.aligned.m16n8k16.row.col.f32.bf16.bf16.f32 " \
                 "{%0,%1,%2,%3},{%4,%5,%6,%7},{%8,%9},{%0,%1,%2,%3};" \
                 : "+f"((c)[0]), "+f"((c)[1]), "+f"((c)[2]), "+f"((c)[3]) \
                 : "r"(a0), "r"(a1), "r"(a2), "r"(a3), "r"(b0), "r"(b1))

// ================= CSR build =================
__global__ void k_zero() {
    int i = blockIdx.x * blockDim.x + threadIdx.x;
    if (i < NN) g_cnt[i] = 0;
}
__global__ void k_hist(const int* __restrict__ ei) {
    int e = blockIdx.x * blockDim.x + threadIdx.x;
    if (e < EE) atomicAdd(&g_cnt[ei[EE + e]], 1);
}
__global__ void __launch_bounds__(1024) k_scan1() {
    __shared__ int ws[32];
    int tid = threadIdx.x, lane = tid & 31, wid = tid >> 5;
    int i = blockIdx.x * 1024 + tid;
    int v = (i < NN) ? g_cnt[i] : 0;
    int x = v;
    #pragma unroll
    for (int o = 1; o < 32; o <<= 1) {
        int y = __shfl_up_sync(0xffffffffu, x, o);
        if (lane >= o) x += y;
    }
    if (lane == 31) ws[wid] = x;
    __syncthreads();
    if (wid == 0) {
        int s = ws[lane];
        #pragma unroll
        for (int o = 1; o < 32; o <<= 1) {
            int y = __shfl_up_sync(0xffffffffu, s, o);
            if (lane >= o) s += y;
        }
        ws[lane] = s;
    }
    __syncthreads();
    int incl = x + (wid ? ws[wid - 1] : 0);
    if (i < NN) g_rowptr[i] = incl - v;
    if (tid == 1023) g_bsum[blockIdx.x] = incl;
}
__global__ void k_scan2(int nblk) {
    __shared__ int ws[4];
    int tid = threadIdx.x, lane = tid & 31, wid = tid >> 5;
    int v = (tid < nblk) ? g_bsum[tid] : 0;
    int x = v;
    #pragma unroll
    for (int o = 1; o < 32; o <<= 1) {
        int y = __shfl_up_sync(0xffffffffu, x, o);
        if (lane >= o) x += y;
    }
    if (lane == 31) ws[wid] = x;
    __syncthreads();
    int pre = 0;
    for (int w = 0; w < wid; w++) pre += ws[w];
    int incl = x + pre;
    if (tid < nblk) g_boff[tid] = incl - v;
    if (tid == nblk - 1) g_rowptr[NN] = incl;
}
__global__ void __launch_bounds__(1024) k_scan3() {
    int i = blockIdx.x * 1024 + threadIdx.x;
    if (i < NN) {
        int r = g_rowptr[i] + g_boff[blockIdx.x];
        g_rowptr[i] = r;
        g_cursor[i] = r;
    }
}
__global__ void k_scatter(const int* __restrict__ ei) {
    int e = blockIdx.x * blockDim.x + threadIdx.x;
    if (e < EE) {
        int s = ei[e];
        int d = ei[EE + e];
        int pos = atomicAdd(&g_cursor[d], 1);
        g_col[pos] = s;
    }
}

// ======== GEMM1 (bf16-split mma) + fused att1 dots; h1 stored fp16 ========
#define SKEW 136
#define SA_HI 0
#define SA_LO 34816
#define SB_HI 69632
#define SB_LO 104448
#define SM_G1 139264

__global__ void __launch_bounds__(256) k_gemm1_mma(const float* __restrict__ x0,
                                                   const float* __restrict__ W1,
                                                   const float* __restrict__ attS,
                                                   const float* __restrict__ attD) {
    extern __shared__ __align__(128) char smem[];
    __nv_bfloat16* sAhi = (__nv_bfloat16*)(smem + SA_HI);
    __nv_bfloat16* sAlo = (__nv_bfloat16*)(smem + SA_LO);
    __nv_bfloat16* sBhi = (__nv_bfloat16*)(smem + SB_HI);
    __nv_bfloat16* sBlo = (__nv_bfloat16*)(smem + SB_LO);
    uint32_t sb = smem_u32(smem);

    int tid = threadIdx.x;
    int rowBase = blockIdx.x * 128;

    #pragma unroll 8
    for (int i = 0; i < 64; i++) {
        int idx = i * 256 + tid;
        int r = idx >> 7, c = idx & 127;
        int grow = rowBase + r;
        float v = (grow < NN) ? __ldg(&x0[(size_t)grow * 128 + c]) : 0.f;
        __nv_bfloat16 hi = __float2bfloat16(v);
        __nv_bfloat16 lo = __float2bfloat16(v - __bfloat162float(hi));
        sAhi[r * SKEW + c] = hi;
        sAlo[r * SKEW + c] = lo;
    }

    int wid = tid >> 5, lane = tid & 31;
    int warpM = wid >> 2, warpN = wid & 3;
    int aRow = warpM * 64 + (lane & 15);
    int aColHalf = (lane >> 4) * 8;
    int bRow = warpN * 32 + (lane & 7);
    int bColHalf = ((lane >> 3) & 1) * 8;
    int rq = lane >> 2, cq = (lane & 3) * 2;

    #pragma unroll 1
    for (int ct = 0; ct < 2; ct++) {
        int colBase = ct * 128;
        __syncthreads();
        #pragma unroll 8
        for (int i = 0; i < 64; i++) {
            int idx = i * 256 + tid;
            int k = idx >> 7, nl = idx & 127;
            float v = __ldg(&W1[(size_t)k * 256 + colBase + nl]);
            __nv_bfloat16 hi = __float2bfloat16(v);
            __nv_bfloat16 lo = __float2bfloat16(v - __bfloat162float(hi));
            sBhi[nl * SKEW + k] = hi;
            sBlo[nl * SKEW + k] = lo;
        }
        __syncthreads();

        float acc[4][4][4];
        #pragma unroll
        for (int mt = 0; mt < 4; mt++)
            #pragma unroll
            for (int nt = 0; nt < 4; nt++)
                #pragma unroll
                for (int q = 0; q < 4; q++) acc[mt][nt][q] = 0.f;

        uint32_t aBasePass[3] = {sb + SA_HI, sb + SA_HI, sb + SA_LO};
        uint32_t bBasePass[3] = {sb + SB_HI, sb + SB_LO, sb + SB_HI};

        #pragma unroll 1
        for (int pass = 0; pass < 3; pass++) {
            uint32_t aB = aBasePass[pass];
            uint32_t bB = bBasePass[pass];
            #pragma unroll
            for (int ks = 0; ks < 8; ks++) {
                uint32_t a[4][4], b[4][2];
                #pragma unroll
                for (int mt = 0; mt < 4; mt++) {
                    uint32_t addr = aB + (uint32_t)(((aRow + mt * 16) * SKEW) + ks * 16 + aColHalf) * 2;
                    LDSM4(a[mt][0], a[mt][1], a[mt][2], a[mt][3], addr);
                }
                #pragma unroll
                for (int nt = 0; nt < 4; nt++) {
                    uint32_t addr = bB + (uint32_t)(((bRow + nt * 8) * SKEW) + ks * 16 + bColHalf) * 2;
                    LDSM2(b[nt][0], b[nt][1], addr);
                }
                #pragma unroll
                for (int mt = 0; mt < 4; mt++)
                    #pragma unroll
                    for (int nt = 0; nt < 4; nt++)
                        MMA16816(acc[mt][nt], a[mt][0], a[mt][1], a[mt][2], a[mt][3],
                                 b[nt][0], b[nt][1]);
            }
        }

        int h = ct * 4 + warpN;
        float aS[8], aD[8];
        #pragma unroll
        for (int nt = 0; nt < 4; nt++) {
            aS[nt * 2 + 0] = __ldg(&attS[h * 32 + nt * 8 + cq]);
            aS[nt * 2 + 1] = __ldg(&attS[h * 32 + nt * 8 + cq + 1]);
            aD[nt * 2 + 0] = __ldg(&attD[h * 32 + nt * 8 + cq]);
            aD[nt * 2 + 1] = __ldg(&attD[h * 32 + nt * 8 + cq + 1]);
        }
        #pragma unroll
        for (int mt = 0; mt < 4; mt++) {
            int r0 = rowBase + warpM * 64 + mt * 16 + rq;
            int r1 = r0 + 8;
            float ps0 = 0.f, pd0 = 0.f, ps1 = 0.f, pd1 = 0.f;
            #pragma unroll
            for (int nt = 0; nt < 4; nt++) {
                ps0 += acc[mt][nt][0] * aS[nt * 2] + acc[mt][nt][1] * aS[nt * 2 + 1];
                pd0 += acc[mt][nt][0] * aD[nt * 2] + acc[mt][nt][1] * aD[nt * 2 + 1];
                ps1 += acc[mt][nt][2] * aS[nt * 2] + acc[mt][nt][3] * aS[nt * 2 + 1];
                pd1 += acc[mt][nt][2] * aD[nt * 2] + acc[mt][nt][3] * aD[nt * 2 + 1];
                int cc = colBase + warpN * 32 + nt * 8 + cq;
                if (r0 < NN)
                    *(__half2*)&g_h1h[(size_t)r0 * 256 + cc] =
                        __floats2half2_rn(acc[mt][nt][0], acc[mt][nt][1]);
                if (r1 < NN)
                    *(__half2*)&g_h1h[(size_t)r1 * 256 + cc] =
                        __floats2half2_rn(acc[mt][nt][2], acc[mt][nt][3]);
            }
            #pragma unroll
            for (int o = 1; o <= 2; o <<= 1) {
                ps0 += __shfl_xor_sync(0xffffffffu, ps0, o);
                pd0 += __shfl_xor_sync(0xffffffffu, pd0, o);
                ps1 += __shfl_xor_sync(0xffffffffu, ps1, o);
                pd1 += __shfl_xor_sync(0xffffffffu, pd1, o);
            }
            if ((lane & 3) == 0) {
                if (r0 < NN) { g_as1[r0 * 8 + h] = ps0; g_ad1[r0 * 8 + h] = pd0; }
                if (r1 < NN) { g_as1[r1 * 8 + h] = ps1; g_ad1[r1 * 8 + h] = pd1; }
            }
        }
    }
}

// ============ GAT1: per-lane head ownership, fp16 8B gathers, zero shuffles ============
__global__ void __launch_bounds__(256) k_gat1(const float* __restrict__ b1) {
    int n = (blockIdx.x * blockDim.x + threadIdx.x) >> 5;
    int lane = threadIdx.x & 31;
    if (n >= NN) return;
    int ha = lane >> 3, hb = ha + 4;
    int c4 = (lane & 7) * 4;

    float adA = __ldg(&g_ad1[n * 8 + ha]);
    float adB = __ldg(&g_ad1[n * 8 + hb]);
    float denA = 0.f, denB = 0.f;
    float4 accA = make_float4(0.f, 0.f, 0.f, 0.f);
    float4 accB = make_float4(0.f, 0.f, 0.f, 0.f);

    int e0 = g_rowptr[n], e1 = g_rowptr[n + 1];
    #pragma unroll 4
    for (int p = e0 - 1; p < e1; p++) {          // p = e0-1 is the self loop
        int s = (p < e0) ? n : __ldg(&g_col[p]);
        float wa = __expf(leaky(__ldg(&g_as1[s * 8 + ha]) + adA));
        float wb = __expf(leaky(__ldg(&g_as1[s * 8 + hb]) + adB));
        denA += wa; denB += wb;
        uint2 ra = *(const uint2*)&g_h1h[(size_t)s * 256 + ha * 32 + c4];
        uint2 rb = *(const uint2*)&g_h1h[(size_t)s * 256 + hb * 32 + c4];
        float2 a01 = __half22float2(*(__half2*)&ra.x);
        float2 a23 = __half22float2(*(__half2*)&ra.y);
        float2 b01 = __half22float2(*(__half2*)&rb.x);
        float2 b23 = __half22float2(*(__half2*)&rb.y);
        accA.x += wa * a01.x; accA.y += wa * a01.y; accA.z += wa * a23.x; accA.w += wa * a23.y;
        accB.x += wb * b01.x; accB.y += wb * b01.y; accB.z += wb * b23.x; accB.w += wb * b23.y;
    }
    float iA = 1.f / fmaxf(denA, 1e-16f);
    float iB = 1.f / fmaxf(denB, 1e-16f);
    float4 bA = __ldg((const float4*)&b1[ha * 32 + c4]);
    float4 bB = __ldg((const float4*)&b1[hb * 32 + c4]);
    float4 rA = make_float4(fmaxf(accA.x * iA + bA.x, 0.f), fmaxf(accA.y * iA + bA.y, 0.f),
                            fmaxf(accA.z * iA + bA.z, 0.f), fmaxf(accA.w * iA + bA.w, 0.f));
    float4 rB = make_float4(fmaxf(accB.x * iB + bB.x, 0.f), fmaxf(accB.y * iB + bB.y, 0.f),
                            fmaxf(accB.z * iB + bB.z, 0.f), fmaxf(accB.w * iB + bB.w, 0.f));
    __stcs((float4*)&g_x2[(size_t)n * 256 + ha * 32 + c4], rA);
    __stcs((float4*)&g_x2[(size_t)n * 256 + hb * 32 + c4], rB);
}

// ============ GEMM2 + att2 dots; h2 stored fp16 ============
__global__ void __launch_bounds__(256) k_gemm2(const float* __restrict__ W2,
                                               const float* __restrict__ attS2,
                                               const float* __restrict__ attD2) {
    __shared__ float W2s[256 * 32];
    int tid = threadIdx.x;
    for (int i = tid; i < 256 * 32; i += 256) W2s[i] = W2[i];
    __syncthreads();
    int lane = tid & 31, wl = tid >> 5;
    int n = blockIdx.x * 8 + wl;
    const float* xr = g_x2 + (size_t)n * 256;
    float acc = 0.f;
    #pragma unroll
    for (int c = 0; c < 8; c++) {
        float xv = __ldcs(&xr[c * 32 + lane]);
        #pragma unroll
        for (int j = 0; j < 32; j++) {
            float xb = __shfl_sync(0xffffffffu, xv, j);
            acc += xb * W2s[(c * 32 + j) * 32 + lane];
        }
    }
    g_h2h[n * 32 + lane] = __float2half_rn(acc);
    float ps = acc * __ldg(&attS2[lane]);
    float pd = acc * __ldg(&attD2[lane]);
    #pragma unroll
    for (int o = 16; o; o >>= 1) {
        ps += __shfl_xor_sync(0xffffffffu, ps, o);
        pd += __shfl_xor_sync(0xffffffffu, pd, o);
    }
    if (lane == 0) {
        g_as2[n] = ps;
        g_ad2[n] = pd;
    }
}

// ============ GAT2 (4-edge groups, fp16 8B loads) + fused final linear ============
__global__ void __launch_bounds__(256) k_gat2(const float* __restrict__ b2,
                                              const float* __restrict__ linW,
                                              const float* __restrict__ linb,
                                              float* __restrict__ out) {
    __shared__ float lw[32 * 40];
    __shared__ float rows[8][32];
    int tid = threadIdx.x;
    for (int i = tid; i < 32 * 40; i += 256) lw[i] = linW[i];

    int wl = tid >> 5, lane = tid & 31;
    int n = blockIdx.x * 8 + wl;
    int grp = lane >> 3, c4 = (lane & 7) * 4;

    float adst = g_ad2[n];
    float asn  = g_as2[n];
    float den; float4 acc;
    {
        float ws = __expf(leaky(asn + adst));
        if (grp == 0) {
            uint2 rh = *(const uint2*)&g_h2h[n * 32 + c4];
            float2 h01 = __half22float2(*(__half2*)&rh.x);
            float2 h23 = __half22float2(*(__half2*)&rh.y);
            den = ws;
            acc = make_float4(ws * h01.x, ws * h01.y, ws * h23.x, ws * h23.y);
        } else {
            den = 0.f;
            acc = make_float4(0.f, 0.f, 0.f, 0.f);
        }
    }
    int e0 = g_rowptr[n], e1 = g_rowptr[n + 1];
    #pragma unroll 2
    for (int p0 = e0; p0 < e1; p0 += 4) {
        int p = p0 + grp;
        bool v = p < e1;
        int s = v ? __ldg(&g_col[p]) : n;
        float w = v ? __expf(leaky(__ldg(&g_as2[s]) + adst)) : 0.f;
        den += w;
        uint2 rh = *(const uint2*)&g_h2h[s * 32 + c4];
        float2 h01 = __half22float2(*(__half2*)&rh.x);
        float2 h23 = __half22float2(*(__half2*)&rh.y);
        acc.x += w * h01.x; acc.y += w * h01.y; acc.z += w * h23.x; acc.w += w * h23.y;
    }
    #pragma unroll
    for (int o = 8; o <= 16; o <<= 1) {
        acc.x += __shfl_xor_sync(0xffffffffu, acc.x, o);
        acc.y += __shfl_xor_sync(0xffffffffu, acc.y, o);
        acc.z += __shfl_xor_sync(0xffffffffu, acc.z, o);
        acc.w += __shfl_xor_sync(0xffffffffu, acc.w, o);
        den   += __shfl_xor_sync(0xffffffffu, den, o);
    }
    if (grp == 0) {
        float inv = 1.f / fmaxf(den, 1e-16f);
        float4 bb = __ldg((const float4*)&b2[c4]);
        rows[wl][c4 + 0] = acc.x * inv + bb.x;
        rows[wl][c4 + 1] = acc.y * inv + bb.y;
        rows[wl][c4 + 2] = acc.z * inv + bb.z;
        rows[wl][c4 + 3] = acc.w * inv + bb.w;
    }
    __syncthreads();
    int nb = blockIdx.x * 8;
    for (int t = tid; t < 320; t += 256) {
        int r = t / 40, o = t % 40;
        float s = __ldg(&linb[o]);
        #pragma unroll
        for (int k = 0; k < 32; k++) s += rows[r][k] * lw[k * 40 + o];
        out[(size_t)(nb + r) * 40 + o] = s;
    }
}

// ================= launch =================
extern "C" void kernel_launch(void* const* d_in, const int* in_sizes, int n_in,
                              void* d_out, int out_size) {
    const float* x0    = (const float*)d_in[0];
    const float* W1    = (const float*)d_in[1];
    const float* attS1 = (const float*)d_in[2];
    const float* attD1 = (const float*)d_in[3];
    const float* b1    = (const float*)d_in[4];
    const float* W2    = (const float*)d_in[5];
    const float* attS2 = (const float*)d_in[6];
    const float* attD2 = (const float*)d_in[7];
    const float* b2    = (const float*)d_in[8];
    const float* linW  = (const float*)d_in[9];
    const float* linb  = (const float*)d_in[10];
    const int*   ei    = (const int*)d_in[11];
    float* out = (float*)d_out;

    static int smemSet = 0;
    if (!smemSet) {
        cudaFuncSetAttribute(k_gemm1_mma, cudaFuncAttributeMaxDynamicSharedMemorySize, SM_G1);
        smemSet = 1;
    }

    const int NBLK = (NN + 1023) / 1024;   // 98
    k_zero<<<(NN + 255) / 256, 256>>>();
    k_hist<<<(EE + 255) / 256, 256>>>(ei);
    k_scan1<<<NBLK, 1024>>>();
    // gemm1 is independent of the CSR chain; placed here so ncu's fixed
    // capture index (launch #3) profiles the GEMM instead of a tiny scan.
    k_gemm1_mma<<<(NN + 127) / 128, 256, SM_G1>>>(x0, W1, attS1, attD1);
    k_scan2<<<1, 128>>>(NBLK);
    k_scan3<<<NBLK, 1024>>>();
    k_scatter<<<(EE + 255) / 256, 256>>>(ei);
    k_gat1<<<(NN + 7) / 8, 256>>>(b1);
    k_gemm2<<<NN / 8, 256>>>(W2, attS2, attD2);
    k_gat2<<<NN / 8, 256>>>(b2, linW, linb, out);
}

// round 10
// speedup vs baseline: 2.0801x; 1.0385x over previous
#include <cuda_runtime.h>
#include <cuda_bf16.h>
#include <cuda_fp16.h>
#include <cstdint>

#define NN   100000
#define EE   1000000
#define HID  32
#define NH1  8
#define OUTC 40
#define NEGS 0.2f

// ================= device scratch =================
__device__ __align__(16) __half g_h1h[(size_t)NN * 256];   // layer1 messages, fp16
__device__ __align__(16) __half g_x2h[(size_t)NN * 256];   // relu(layer1 out), fp16
__device__ __align__(16) float g_as1[NN * NH1];
__device__ __align__(16) float g_ad1[NN * NH1];
__device__ __align__(16) __half g_h2h[NN * HID];           // layer2 messages, fp16
__device__ __align__(16) float g_as2[NN];
__device__ __align__(16) float g_ad2[NN];
__device__ int g_cnt[NN];
__device__ int g_rowptr[NN + 1];
__device__ int g_cursor[NN];
__device__ int g_col[EE];
__device__ int g_bsum[128];
__device__ int g_boff[128];

__device__ __forceinline__ float leaky(float x) { return x > 0.f ? x : NEGS * x; }

__device__ __forceinline__ uint32_t smem_u32(const void* p) {
    uint32_t a;
    asm("{ .reg .u64 t; cvta.to.shared.u64 t, %1; cvt.u32.u64 %0, t; }" : "=r"(a) : "l"(p));
    return a;
}

#define LDSM4(r0, r1, r2, r3, a) \
    asm volatile("ldmatrix.sync.aligned.m8n8.x4.shared.b16 {%0,%1,%2,%3}, [%4];" \
                 : "=r"(r0), "=r"(r1), "=r"(r2), "=r"(r3) : "r"(a))
#define LDSM2(r0, r1, a) \
    asm volatile("ldmatrix.sync.aligned.m8n8.x2.shared.b16 {%0,%1}, [%2];" \
                 : "=r"(r0), "=r"(r1) : "r"(a))
#define MMA16816(c, a0, a1, a2, a3, b0, b1) \
    asm volatile("mma.sync.aligned.m16n8k16.row.col.f32.bf16.bf16.f32 " \
                 "{%0,%1,%2,%3},{%4,%5,%6,%7},{%8,%9},{%0,%1,%2,%3};" \
                 : "+f"((c)[0]), "+f"((c)[1]), "+f"((c)[2]), "+f"((c)[3]) \
                 : "r"(a0), "r"(a1), "r"(a2), "r"(a3), "r"(b0), "r"(b1))

// ================= CSR build =================
__global__ void k_zero() {
    int i = blockIdx.x * blockDim.x + threadIdx.x;
    if (i < NN) g_cnt[i] = 0;
}
__global__ void k_hist(const int* __restrict__ ei) {
    int e = blockIdx.x * blockDim.x + threadIdx.x;
    if (e < EE) atomicAdd(&g_cnt[ei[EE + e]], 1);
}
__global__ void __launch_bounds__(1024) k_scan1() {
    __shared__ int ws[32];
    int tid = threadIdx.x, lane = tid & 31, wid = tid >> 5;
    int i = blockIdx.x * 1024 + tid;
    int v = (i < NN) ? g_cnt[i] : 0;
    int x = v;
    #pragma unroll
    for (int o = 1; o < 32; o <<= 1) {
        int y = __shfl_up_sync(0xffffffffu, x, o);
        if (lane >= o) x += y;
    }
    if (lane == 31) ws[wid] = x;
    __syncthreads();
    if (wid == 0) {
        int s = ws[lane];
        #pragma unroll
        for (int o = 1; o < 32; o <<= 1) {
            int y = __shfl_up_sync(0xffffffffu, s, o);
            if (lane >= o) s += y;
        }
        ws[lane] = s;
    }
    __syncthreads();
    int incl = x + (wid ? ws[wid - 1] : 0);
    if (i < NN) g_rowptr[i] = incl - v;
    if (tid == 1023) g_bsum[blockIdx.x] = incl;
}
__global__ void k_scan2(int nblk) {
    __shared__ int ws[4];
    int tid = threadIdx.x, lane = tid & 31, wid = tid >> 5;
    int v = (tid < nblk) ? g_bsum[tid] : 0;
    int x = v;
    #pragma unroll
    for (int o = 1; o < 32; o <<= 1) {
        int y = __shfl_up_sync(0xffffffffu, x, o);
        if (lane >= o) x += y;
    }
    if (lane == 31) ws[wid] = x;
    __syncthreads();
    int pre = 0;
    for (int w = 0; w < wid; w++) pre += ws[w];
    int incl = x + pre;
    if (tid < nblk) g_boff[tid] = incl - v;
    if (tid == nblk - 1) g_rowptr[NN] = incl;
}
__global__ void __launch_bounds__(1024) k_scan3() {
    int i = blockIdx.x * 1024 + threadIdx.x;
    if (i < NN) {
        int r = g_rowptr[i] + g_boff[blockIdx.x];
        g_rowptr[i] = r;
        g_cursor[i] = r;
    }
}
__global__ void k_scatter(const int* __restrict__ ei) {
    int e = blockIdx.x * blockDim.x + threadIdx.x;
    if (e < EE) {
        int s = ei[e];
        int d = ei[EE + e];
        int pos = atomicAdd(&g_cursor[d], 1);
        g_col[pos] = s;
    }
}

// ======== GEMM1 (bf16-split mma, fused 3-term k-loop) + fused att1 dots ========
#define SKEW 136
#define SA_HI 0
#define SA_LO 34816
#define SB_HI 69632
#define SB_LO 104448
#define SM_G1 139264

__global__ void __launch_bounds__(256) k_gemm1_mma(const float* __restrict__ x0,
                                                   const float* __restrict__ W1,
                                                   const float* __restrict__ attS,
                                                   const float* __restrict__ attD) {
    extern __shared__ __align__(128) char smem[];
    __nv_bfloat16* sAhi = (__nv_bfloat16*)(smem + SA_HI);
    __nv_bfloat16* sAlo = (__nv_bfloat16*)(smem + SA_LO);
    __nv_bfloat16* sBhi = (__nv_bfloat16*)(smem + SB_HI);
    __nv_bfloat16* sBlo = (__nv_bfloat16*)(smem + SB_LO);
    uint32_t sb = smem_u32(smem);

    int tid = threadIdx.x;
    int rowBase = blockIdx.x * 128;

    #pragma unroll 8
    for (int i = 0; i < 64; i++) {
        int idx = i * 256 + tid;
        int r = idx >> 7, c = idx & 127;
        int grow = rowBase + r;
        float v = (grow < NN) ? __ldg(&x0[(size_t)grow * 128 + c]) : 0.f;
        __nv_bfloat16 hi = __float2bfloat16(v);
        __nv_bfloat16 lo = __float2bfloat16(v - __bfloat162float(hi));
        sAhi[r * SKEW + c] = hi;
        sAlo[r * SKEW + c] = lo;
    }

    int wid = tid >> 5, lane = tid & 31;
    int warpM = wid >> 2, warpN = wid & 3;
    int aRow = warpM * 64 + (lane & 15);
    int aColHalf = (lane >> 4) * 8;
    int bRow = warpN * 32 + (lane & 7);
    int bColHalf = ((lane >> 3) & 1) * 8;
    int rq = lane >> 2, cq = (lane & 3) * 2;

    #pragma unroll 1
    for (int ct = 0; ct < 2; ct++) {
        int colBase = ct * 128;
        __syncthreads();
        #pragma unroll 8
        for (int i = 0; i < 64; i++) {
            int idx = i * 256 + tid;
            int k = idx >> 7, nl = idx & 127;
            float v = __ldg(&W1[(size_t)k * 256 + colBase + nl]);
            __nv_bfloat16 hi = __float2bfloat16(v);
            __nv_bfloat16 lo = __float2bfloat16(v - __bfloat162float(hi));
            sBhi[nl * SKEW + k] = hi;
            sBlo[nl * SKEW + k] = lo;
        }
        __syncthreads();

        float acc[4][4][4];
        #pragma unroll
        for (int mt = 0; mt < 4; mt++)
            #pragma unroll
            for (int nt = 0; nt < 4; nt++)
                #pragma unroll
                for (int q = 0; q < 4; q++) acc[mt][nt][q] = 0.f;

        // fused hi*hi + hi*lo + lo*hi in one k-loop: 16 ldmatrix + 48 MMA per ks
        #pragma unroll 1
        for (int ks = 0; ks < 8; ks++) {
            uint32_t ah[4][4], al[4][4], bh[4][2], bl[4][2];
            #pragma unroll
            for (int mt = 0; mt < 4; mt++) {
                uint32_t off = (uint32_t)(((aRow + mt * 16) * SKEW) + ks * 16 + aColHalf) * 2;
                LDSM4(ah[mt][0], ah[mt][1], ah[mt][2], ah[mt][3], sb + SA_HI + off);
                LDSM4(al[mt][0], al[mt][1], al[mt][2], al[mt][3], sb + SA_LO + off);
            }
            #pragma unroll
            for (int nt = 0; nt < 4; nt++) {
                uint32_t off = (uint32_t)(((bRow + nt * 8) * SKEW) + ks * 16 + bColHalf) * 2;
                LDSM2(bh[nt][0], bh[nt][1], sb + SB_HI + off);
                LDSM2(bl[nt][0], bl[nt][1], sb + SB_LO + off);
            }
            #pragma unroll
            for (int mt = 0; mt < 4; mt++)
                #pragma unroll
                for (int nt = 0; nt < 4; nt++) {
                    MMA16816(acc[mt][nt], ah[mt][0], ah[mt][1], ah[mt][2], ah[mt][3],
                             bh[nt][0], bh[nt][1]);
                    MMA16816(acc[mt][nt], ah[mt][0], ah[mt][1], ah[mt][2], ah[mt][3],
                             bl[nt][0], bl[nt][1]);
                    MMA16816(acc[mt][nt], al[mt][0], al[mt][1], al[mt][2], al[mt][3],
                             bh[nt][0], bh[nt][1]);
                }
        }

        int h = ct * 4 + warpN;
        float aS[8], aD[8];
        #pragma unroll
        for (int nt = 0; nt < 4; nt++) {
            aS[nt * 2 + 0] = __ldg(&attS[h * 32 + nt * 8 + cq]);
            aS[nt * 2 + 1] = __ldg(&attS[h * 32 + nt * 8 + cq + 1]);
            aD[nt * 2 + 0] = __ldg(&attD[h * 32 + nt * 8 + cq]);
            aD[nt * 2 + 1] = __ldg(&attD[h * 32 + nt * 8 + cq + 1]);
        }
        #pragma unroll
        for (int mt = 0; mt < 4; mt++) {
            int r0 = rowBase + warpM * 64 + mt * 16 + rq;
            int r1 = r0 + 8;
            float ps0 = 0.f, pd0 = 0.f, ps1 = 0.f, pd1 = 0.f;
            #pragma unroll
            for (int nt = 0; nt < 4; nt++) {
                ps0 += acc[mt][nt][0] * aS[nt * 2] + acc[mt][nt][1] * aS[nt * 2 + 1];
                pd0 += acc[mt][nt][0] * aD[nt * 2] + acc[mt][nt][1] * aD[nt * 2 + 1];
                ps1 += acc[mt][nt][2] * aS[nt * 2] + acc[mt][nt][3] * aS[nt * 2 + 1];
                pd1 += acc[mt][nt][2] * aD[nt * 2] + acc[mt][nt][3] * aD[nt * 2 + 1];
                int cc = colBase + warpN * 32 + nt * 8 + cq;
                if (r0 < NN)
                    *(__half2*)&g_h1h[(size_t)r0 * 256 + cc] =
                        __floats2half2_rn(acc[mt][nt][0], acc[mt][nt][1]);
                if (r1 < NN)
                    *(__half2*)&g_h1h[(size_t)r1 * 256 + cc] =
                        __floats2half2_rn(acc[mt][nt][2], acc[mt][nt][3]);
            }
            #pragma unroll
            for (int o = 1; o <= 2; o <<= 1) {
                ps0 += __shfl_xor_sync(0xffffffffu, ps0, o);
                pd0 += __shfl_xor_sync(0xffffffffu, pd0, o);
                ps1 += __shfl_xor_sync(0xffffffffu, ps1, o);
                pd1 += __shfl_xor_sync(0xffffffffu, pd1, o);
            }
            if ((lane & 3) == 0) {
                if (r0 < NN) { g_as1[r0 * 8 + h] = ps0; g_ad1[r0 * 8 + h] = pd0; }
                if (r1 < NN) { g_as1[r1 * 8 + h] = ps1; g_ad1[r1 * 8 + h] = pd1; }
            }
        }
    }
}

// ============ GAT1: per-lane head ownership, fp16 8B gathers, zero shuffles ============
__global__ void __launch_bounds__(256) k_gat1(const float* __restrict__ b1) {
    int n = (blockIdx.x * blockDim.x + threadIdx.x) >> 5;
    int lane = threadIdx.x & 31;
    if (n >= NN) return;
    int ha = lane >> 3, hb = ha + 4;
    int c4 = (lane & 7) * 4;

    float adA = __ldg(&g_ad1[n * 8 + ha]);
    float adB = __ldg(&g_ad1[n * 8 + hb]);
    float denA = 0.f, denB = 0.f;
    float4 accA = make_float4(0.f, 0.f, 0.f, 0.f);
    float4 accB = make_float4(0.f, 0.f, 0.f, 0.f);

    int e0 = g_rowptr[n], e1 = g_rowptr[n + 1];
    #pragma unroll 4
    for (int p = e0 - 1; p < e1; p++) {          // p = e0-1 is the self loop
        int s = (p < e0) ? n : __ldg(&g_col[p]);
        float wa = __expf(leaky(__ldg(&g_as1[s * 8 + ha]) + adA));
        float wb = __expf(leaky(__ldg(&g_as1[s * 8 + hb]) + adB));
        denA += wa; denB += wb;
        uint2 ra = *(const uint2*)&g_h1h[(size_t)s * 256 + ha * 32 + c4];
        uint2 rb = *(const uint2*)&g_h1h[(size_t)s * 256 + hb * 32 + c4];
        float2 a01 = __half22float2(*(__half2*)&ra.x);
        float2 a23 = __half22float2(*(__half2*)&ra.y);
        float2 b01 = __half22float2(*(__half2*)&rb.x);
        float2 b23 = __half22float2(*(__half2*)&rb.y);
        accA.x += wa * a01.x; accA.y += wa * a01.y; accA.z += wa * a23.x; accA.w += wa * a23.y;
        accB.x += wb * b01.x; accB.y += wb * b01.y; accB.z += wb * b23.x; accB.w += wb * b23.y;
    }
    float iA = 1.f / fmaxf(denA, 1e-16f);
    float iB = 1.f / fmaxf(denB, 1e-16f);
    float4 bA = __ldg((const float4*)&b1[ha * 32 + c4]);
    float4 bB = __ldg((const float4*)&b1[hb * 32 + c4]);
    __half2 rA0 = __floats2half2_rn(fmaxf(accA.x * iA + bA.x, 0.f), fmaxf(accA.y * iA + bA.y, 0.f));
    __half2 rA1 = __floats2half2_rn(fmaxf(accA.z * iA + bA.z, 0.f), fmaxf(accA.w * iA + bA.w, 0.f));
    __half2 rB0 = __floats2half2_rn(fmaxf(accB.x * iB + bB.x, 0.f), fmaxf(accB.y * iB + bB.y, 0.f));
    __half2 rB1 = __floats2half2_rn(fmaxf(accB.z * iB + bB.z, 0.f), fmaxf(accB.w * iB + bB.w, 0.f));
    uint2 pa, pb;
    pa.x = *(uint32_t*)&rA0; pa.y = *(uint32_t*)&rA1;
    pb.x = *(uint32_t*)&rB0; pb.y = *(uint32_t*)&rB1;
    __stcs((uint2*)&g_x2h[(size_t)n * 256 + ha * 32 + c4], pa);
    __stcs((uint2*)&g_x2h[(size_t)n * 256 + hb * 32 + c4], pb);
}

// ============ GEMM2 (fp16 x2 input) + att2 dots; h2 stored fp16 ============
__global__ void __launch_bounds__(256) k_gemm2(const float* __restrict__ W2,
                                               const float* __restrict__ attS2,
                                               const float* __restrict__ attD2) {
    __shared__ float W2s[256 * 32];
    int tid = threadIdx.x;
    for (int i = tid; i < 256 * 32; i += 256) W2s[i] = W2[i];
    __syncthreads();
    int lane = tid & 31, wl = tid >> 5;
    int n = blockIdx.x * 8 + wl;
    // lane L holds channels [8L, 8L+8) of the row (one uint4 = 8 halves)
    uint4 raw = __ldcs((const uint4*)&g_x2h[(size_t)n * 256 + lane * 8]);
    float xv[8];
    {
        float2 t0 = __half22float2(*(__half2*)&raw.x);
        float2 t1 = __half22float2(*(__half2*)&raw.y);
        float2 t2 = __half22float2(*(__half2*)&raw.z);
        float2 t3 = __half22float2(*(__half2*)&raw.w);
        xv[0] = t0.x; xv[1] = t0.y; xv[2] = t1.x; xv[3] = t1.y;
        xv[4] = t2.x; xv[5] = t2.y; xv[6] = t3.x; xv[7] = t3.y;
    }
    float acc = 0.f;
    #pragma unroll
    for (int c = 0; c < 32; c++) {
        #pragma unroll
        for (int e = 0; e < 8; e++) {
            float xb = __shfl_sync(0xffffffffu, xv[e], c);
            acc += xb * W2s[(c * 8 + e) * 32 + lane];
        }
    }
    g_h2h[n * 32 + lane] = __float2half_rn(acc);
    float ps = acc * __ldg(&attS2[lane]);
    float pd = acc * __ldg(&attD2[lane]);
    #pragma unroll
    for (int o = 16; o; o >>= 1) {
        ps += __shfl_xor_sync(0xffffffffu, ps, o);
        pd += __shfl_xor_sync(0xffffffffu, pd, o);
    }
    if (lane == 0) {
        g_as2[n] = ps;
        g_ad2[n] = pd;
    }
}

// ============ GAT2 (4-edge groups, fp16 8B loads) + fused final linear ============
__global__ void __launch_bounds__(256) k_gat2(const float* __restrict__ b2,
                                              const float* __restrict__ linW,
                                              const float* __restrict__ linb,
                                              float* __restrict__ out) {
    __shared__ float lw[32 * 40];
    __shared__ float rows[8][32];
    int tid = threadIdx.x;
    for (int i = tid; i < 32 * 40; i += 256) lw[i] = linW[i];

    int wl = tid >> 5, lane = tid & 31;
    int n = blockIdx.x * 8 + wl;
    int grp = lane >> 3, c4 = (lane & 7) * 4;

    float adst = g_ad2[n];
    float asn  = g_as2[n];
    float den; float4 acc;
    {
        float ws = __expf(leaky(asn + adst));
        if (grp == 0) {
            uint2 rh = *(const uint2*)&g_h2h[n * 32 + c4];
            float2 h01 = __half22float2(*(__half2*)&rh.x);
            float2 h23 = __half22float2(*(__half2*)&rh.y);
            den = ws;
            acc = make_float4(ws * h01.x, ws * h01.y, ws * h23.x, ws * h23.y);
        } else {
            den = 0.f;
            acc = make_float4(0.f, 0.f, 0.f, 0.f);
        }
    }
    int e0 = g_rowptr[n], e1 = g_rowptr[n + 1];
    #pragma unroll 2
    for (int p0 = e0; p0 < e1; p0 += 4) {
        int p = p0 + grp;
        bool v = p < e1;
        int s = v ? __ldg(&g_col[p]) : n;
        float w = v ? __expf(leaky(__ldg(&g_as2[s]) + adst)) : 0.f;
        den += w;
        uint2 rh = *(const uint2*)&g_h2h[s * 32 + c4];
        float2 h01 = __half22float2(*(__half2*)&rh.x);
        float2 h23 = __half22float2(*(__half2*)&rh.y);
        acc.x += w * h01.x; acc.y += w * h01.y; acc.z += w * h23.x; acc.w += w * h23.y;
    }
    #pragma unroll
    for (int o = 8; o <= 16; o <<= 1) {
        acc.x += __shfl_xor_sync(0xffffffffu, acc.x, o);
        acc.y += __shfl_xor_sync(0xffffffffu, acc.y, o);
        acc.z += __shfl_xor_sync(0xffffffffu, acc.z, o);
        acc.w += __shfl_xor_sync(0xffffffffu, acc.w, o);
        den   += __shfl_xor_sync(0xffffffffu, den, o);
    }
    if (grp == 0) {
        float inv = 1.f / fmaxf(den, 1e-16f);
        float4 bb = __ldg((const float4*)&b2[c4]);
        rows[wl][c4 + 0] = acc.x * inv + bb.x;
        rows[wl][c4 + 1] = acc.y * inv + bb.y;
        rows[wl][c4 + 2] = acc.z * inv + bb.z;
        rows[wl][c4 + 3] = acc.w * inv + bb.w;
    }
    __syncthreads();
    int nb = blockIdx.x * 8;
    for (int t = tid; t < 320; t += 256) {
        int r = t / 40, o = t % 40;
        float s = __ldg(&linb[o]);
        #pragma unroll
        for (int k = 0; k < 32; k++) s += rows[r][k] * lw[k * 40 + o];
        out[(size_t)(nb + r) * 40 + o] = s;
    }
}

// ================= launch =================
extern "C" void kernel_launch(void* const* d_in, const int* in_sizes, int n_in,
                              void* d_out, int out_size) {
    const float* x0    = (const float*)d_in[0];
    const float* W1    = (const float*)d_in[1];
    const float* attS1 = (const float*)d_in[2];
    const float* attD1 = (const float*)d_in[3];
    const float* b1    = (const float*)d_in[4];
    const float* W2    = (const float*)d_in[5];
    const float* attS2 = (const float*)d_in[6];
    const float* attD2 = (const float*)d_in[7];
    const float* b2    = (const float*)d_in[8];
    const float* linW  = (const float*)d_in[9];
    const float* linb  = (const float*)d_in[10];
    const int*   ei    = (const int*)d_in[11];
    float* out = (float*)d_out;

    static cudaStream_t s_side = nullptr;
    static cudaEvent_t ev_fork = nullptr, ev_join = nullptr;
    if (!s_side) {
        cudaFuncSetAttribute(k_gemm1_mma, cudaFuncAttributeMaxDynamicSharedMemorySize, SM_G1);
        cudaStreamCreateWithFlags(&s_side, cudaStreamNonBlocking);
        cudaEventCreateWithFlags(&ev_fork, cudaEventDisableTiming);
        cudaEventCreateWithFlags(&ev_join, cudaEventDisableTiming);
    }

    const int NBLK = (NN + 1023) / 1024;   // 98

    // fork: CSR chain on side stream, GEMM1 on main stream (independent work)
    cudaEventRecord(ev_fork, 0);
    cudaStreamWaitEvent(s_side, ev_fork, 0);
    k_zero<<<(NN + 255) / 256, 256, 0, s_side>>>();
    k_hist<<<(EE + 255) / 256, 256, 0, s_side>>>(ei);
    k_scan1<<<NBLK, 1024, 0, s_side>>>();
    k_scan2<<<1, 128, 0, s_side>>>(NBLK);
    k_scan3<<<NBLK, 1024, 0, s_side>>>();
    k_scatter<<<(EE + 255) / 256, 256, 0, s_side>>>(ei);
    cudaEventRecord(ev_join, s_side);

    k_gemm1_mma<<<(NN + 127) / 128, 256, SM_G1>>>(x0, W1, attS1, attD1);

    // join: gat1 needs both gemm1 (main) and CSR (side)
    cudaStreamWaitEvent(0, ev_join, 0);
    k_gat1<<<(NN + 7) / 8, 256>>>(b1);
    k_gemm2<<<NN / 8, 256>>>(W2, attS2, attD2);
    k_gat2<<<NN / 8, 256>>>(b2, linW, linb, out);
}

// round 11
// speedup vs baseline: 2.2815x; 1.0968x over previous
#include <cuda_runtime.h>
#include <cuda_bf16.h>
#include <cuda_fp16.h>
#include <cstdint>

#define NN   100000
#define EE   1000000
#define HID  32
#define NH1  8
#define OUTC 40
#define NEGS 0.2f

// ================= device scratch =================
__device__ __align__(16) __half g_h1h[(size_t)NN * 256];   // layer1 messages, fp16
__device__ __align__(16) __half g_x2h[(size_t)NN * 256];   // relu(layer1 out), fp16
__device__ __align__(16) float g_as1[NN * NH1];
__device__ __align__(16) float g_ad1[NN * NH1];
__device__ __align__(16) __half g_h2h[NN * HID];           // layer2 messages, fp16
__device__ __align__(16) float g_as2[NN];
__device__ __align__(16) float g_ad2[NN];
__device__ __align__(16) __nv_bfloat16 g_w1hi[32768];      // W1 split, tile layout [ct][n][k]
__device__ __align__(16) __nv_bfloat16 g_w1lo[32768];
__device__ int g_cnt[NN];
__device__ int g_rowptr[NN + 1];
__device__ int g_cursor[NN];
__device__ int g_col[EE];
__device__ int g_bsum[128];
__device__ int g_boff[128];

__device__ __forceinline__ float leaky(float x) { return x > 0.f ? x : NEGS * x; }

__device__ __forceinline__ uint32_t smem_u32(const void* p) {
    uint32_t a;
    asm("{ .reg .u64 t; cvta.to.shared.u64 t, %1; cvt.u32.u64 %0, t; }" : "=r"(a) : "l"(p));
    return a;
}

#define LDSM4(r0, r1, r2, r3, a) \
    asm volatile("ldmatrix.sync.aligned.m8n8.x4.shared.b16 {%0,%1,%2,%3}, [%4];" \
                 : "=r"(r0), "=r"(r1), "=r"(r2), "=r"(r3) : "r"(a))
#define LDSM2(r0, r1, a) \
    asm volatile("ldmatrix.sync.aligned.m8n8.x2.shared.b16 {%0,%1}, [%2];" \
                 : "=r"(r0), "=r"(r1) : "r"(a))
#define MMA16816(c, a0, a1, a2, a3, b0, b1) \
    asm volatile("mma.sync.aligned.m16n8k16.row.col.f32.bf16.bf16.f32 " \
                 "{%0,%1,%2,%3},{%4,%5,%6,%7},{%8,%9},{%0,%1,%2,%3};" \
                 : "+f"((c)[0]), "+f"((c)[1]), "+f"((c)[2]), "+f"((c)[3]) \
                 : "r"(a0), "r"(a1), "r"(a2), "r"(a3), "r"(b0), "r"(b1))

// ================= W1 prep: fp32 -> bf16 hi/lo in tile layout =================
__global__ void k_prepw1(const float* __restrict__ W1) {
    int idx = blockIdx.x * blockDim.x + threadIdx.x;
    if (idx >= 32768) return;
    int k = idx >> 8, n = idx & 255;
    float v = __ldg(&W1[idx]);
    __nv_bfloat16 hi = __float2bfloat16(v);
    __nv_bfloat16 lo = __float2bfloat16(v - __bfloat162float(hi));
    int ct = n >> 7, nl = n & 127;
    int off = ct * 16384 + nl * 128 + k;
    g_w1hi[off] = hi;
    g_w1lo[off] = lo;
}

// ================= CSR build =================
__global__ void k_zero() {
    int i = blockIdx.x * blockDim.x + threadIdx.x;
    if (i < NN) g_cnt[i] = 0;
}
__global__ void k_hist(const int* __restrict__ ei) {
    int e = blockIdx.x * blockDim.x + threadIdx.x;
    if (e < EE) atomicAdd(&g_cnt[ei[EE + e]], 1);
}
__global__ void __launch_bounds__(1024) k_scan1() {
    __shared__ int ws[32];
    int tid = threadIdx.x, lane = tid & 31, wid = tid >> 5;
    int i = blockIdx.x * 1024 + tid;
    int v = (i < NN) ? g_cnt[i] : 0;
    int x = v;
    #pragma unroll
    for (int o = 1; o < 32; o <<= 1) {
        int y = __shfl_up_sync(0xffffffffu, x, o);
        if (lane >= o) x += y;
    }
    if (lane == 31) ws[wid] = x;
    __syncthreads();
    if (wid == 0) {
        int s = ws[lane];
        #pragma unroll
        for (int o = 1; o < 32; o <<= 1) {
            int y = __shfl_up_sync(0xffffffffu, s, o);
            if (lane >= o) s += y;
        }
        ws[lane] = s;
    }
    __syncthreads();
    int incl = x + (wid ? ws[wid - 1] : 0);
    if (i < NN) g_rowptr[i] = incl - v;
    if (tid == 1023) g_bsum[blockIdx.x] = incl;
}
__global__ void k_scan2(int nblk) {
    __shared__ int ws[4];
    int tid = threadIdx.x, lane = tid & 31, wid = tid >> 5;
    int v = (tid < nblk) ? g_bsum[tid] : 0;
    int x = v;
    #pragma unroll
    for (int o = 1; o < 32; o <<= 1) {
        int y = __shfl_up_sync(0xffffffffu, x, o);
        if (lane >= o) x += y;
    }
    if (lane == 31) ws[wid] = x;
    __syncthreads();
    int pre = 0;
    for (int w = 0; w < wid; w++) pre += ws[w];
    int incl = x + pre;
    if (tid < nblk) g_boff[tid] = incl - v;
    if (tid == nblk - 1) g_rowptr[NN] = incl;
}
__global__ void __launch_bounds__(1024) k_scan3() {
    int i = blockIdx.x * 1024 + threadIdx.x;
    if (i < NN) {
        int r = g_rowptr[i] + g_boff[blockIdx.x];
        g_rowptr[i] = r;
        g_cursor[i] = r;
    }
}
__global__ void k_scatter(const int* __restrict__ ei) {
    int e = blockIdx.x * blockDim.x + threadIdx.x;
    if (e < EE) {
        int s = ei[e];
        int d = ei[EE + e];
        int pos = atomicAdd(&g_cursor[d], 1);
        g_col[pos] = s;
    }
}

// ======== GEMM1: 64-row tiles, 2 CTAs/SM, bf16-split mma + fused att1 dots ========
#define SKEW 136
#define SA_HI 0
#define SA_LO 17408
#define SB_HI 34816
#define SB_LO 69632
#define SM_G1 104448

__global__ void __launch_bounds__(256, 2) k_gemm1_mma(const float* __restrict__ x0,
                                                      const float* __restrict__ attS,
                                                      const float* __restrict__ attD) {
    extern __shared__ __align__(128) char smem[];
    __nv_bfloat16* sAhi = (__nv_bfloat16*)(smem + SA_HI);
    __nv_bfloat16* sAlo = (__nv_bfloat16*)(smem + SA_LO);
    __nv_bfloat16* sBhi = (__nv_bfloat16*)(smem + SB_HI);
    __nv_bfloat16* sBlo = (__nv_bfloat16*)(smem + SB_LO);
    uint32_t sb = smem_u32(smem);

    int tid = threadIdx.x;
    int rowBase = blockIdx.x * 64;

    // stage A: 64 rows x 128 cols fp32 -> bf16 hi/lo
    #pragma unroll 4
    for (int i = 0; i < 32; i++) {
        int idx = i * 256 + tid;
        int r = idx >> 7, c = idx & 127;
        int grow = rowBase + r;
        float v = (grow < NN) ? __ldg(&x0[(size_t)grow * 128 + c]) : 0.f;
        __nv_bfloat16 hi = __float2bfloat16(v);
        __nv_bfloat16 lo = __float2bfloat16(v - __bfloat162float(hi));
        sAhi[r * SKEW + c] = hi;
        sAlo[r * SKEW + c] = lo;
    }

    int wid = tid >> 5, lane = tid & 31;
    int warpM = wid >> 2, warpN = wid & 3;        // 2 x 4 warps, warp tile 32x32
    int aRow = warpM * 32 + (lane & 15);
    int aColHalf = (lane >> 4) * 8;
    int bRow = warpN * 32 + (lane & 7);
    int bColHalf = ((lane >> 3) & 1) * 8;
    int rq = lane >> 2, cq = (lane & 3) * 2;

    #pragma unroll 1
    for (int ct = 0; ct < 2; ct++) {
        __syncthreads();
        // stage B: pure uint4 copy from pre-split images (tile layout [n][k])
        {
            const uint4* srcH = (const uint4*)(g_w1hi + ct * 16384);
            const uint4* srcL = (const uint4*)(g_w1lo + ct * 16384);
            #pragma unroll
            for (int i = 0; i < 8; i++) {
                int q = i * 256 + tid;            // uint4 index, 2048 total
                int nl = q >> 4, k8 = (q & 15) * 8;
                *(uint4*)&sBhi[nl * SKEW + k8] = srcH[q];
                *(uint4*)&sBlo[nl * SKEW + k8] = srcL[q];
            }
        }
        __syncthreads();

        float acc[2][4][4];
        #pragma unroll
        for (int mt = 0; mt < 2; mt++)
            #pragma unroll
            for (int nt = 0; nt < 4; nt++)
                #pragma unroll
                for (int q = 0; q < 4; q++) acc[mt][nt][q] = 0.f;

        #pragma unroll 1
        for (int ks = 0; ks < 8; ks++) {
            uint32_t ah[2][4], al[2][4], bh[4][2], bl[4][2];
            #pragma unroll
            for (int mt = 0; mt < 2; mt++) {
                uint32_t off = (uint32_t)(((aRow + mt * 16) * SKEW) + ks * 16 + aColHalf) * 2;
                LDSM4(ah[mt][0], ah[mt][1], ah[mt][2], ah[mt][3], sb + SA_HI + off);
                LDSM4(al[mt][0], al[mt][1], al[mt][2], al[mt][3], sb + SA_LO + off);
            }
            #pragma unroll
            for (int nt = 0; nt < 4; nt++) {
                uint32_t off = (uint32_t)(((bRow + nt * 8) * SKEW) + ks * 16 + bColHalf) * 2;
                LDSM2(bh[nt][0], bh[nt][1], sb + SB_HI + off);
                LDSM2(bl[nt][0], bl[nt][1], sb + SB_LO + off);
            }
            #pragma unroll
            for (int mt = 0; mt < 2; mt++)
                #pragma unroll
                for (int nt = 0; nt < 4; nt++) {
                    MMA16816(acc[mt][nt], ah[mt][0], ah[mt][1], ah[mt][2], ah[mt][3],
                             bh[nt][0], bh[nt][1]);
                    MMA16816(acc[mt][nt], ah[mt][0], ah[mt][1], ah[mt][2], ah[mt][3],
                             bl[nt][0], bl[nt][1]);
                    MMA16816(acc[mt][nt], al[mt][0], al[mt][1], al[mt][2], al[mt][3],
                             bh[nt][0], bh[nt][1]);
                }
        }

        int h = ct * 4 + warpN;
        float aS[8], aD[8];
        #pragma unroll
        for (int nt = 0; nt < 4; nt++) {
            aS[nt * 2 + 0] = __ldg(&attS[h * 32 + nt * 8 + cq]);
            aS[nt * 2 + 1] = __ldg(&attS[h * 32 + nt * 8 + cq + 1]);
            aD[nt * 2 + 0] = __ldg(&attD[h * 32 + nt * 8 + cq]);
            aD[nt * 2 + 1] = __ldg(&attD[h * 32 + nt * 8 + cq + 1]);
        }
        #pragma unroll
        for (int mt = 0; mt < 2; mt++) {
            int r0 = rowBase + warpM * 32 + mt * 16 + rq;
            int r1 = r0 + 8;
            float ps0 = 0.f, pd0 = 0.f, ps1 = 0.f, pd1 = 0.f;
            #pragma unroll
            for (int nt = 0; nt < 4; nt++) {
                ps0 += acc[mt][nt][0] * aS[nt * 2] + acc[mt][nt][1] * aS[nt * 2 + 1];
                pd0 += acc[mt][nt][0] * aD[nt * 2] + acc[mt][nt][1] * aD[nt * 2 + 1];
                ps1 += acc[mt][nt][2] * aS[nt * 2] + acc[mt][nt][3] * aS[nt * 2 + 1];
                pd1 += acc[mt][nt][2] * aD[nt * 2] + acc[mt][nt][3] * aD[nt * 2 + 1];
                int cc = ct * 128 + warpN * 32 + nt * 8 + cq;
                if (r0 < NN)
                    *(__half2*)&g_h1h[(size_t)r0 * 256 + cc] =
                        __floats2half2_rn(acc[mt][nt][0], acc[mt][nt][1]);
                if (r1 < NN)
                    *(__half2*)&g_h1h[(size_t)r1 * 256 + cc] =
                        __floats2half2_rn(acc[mt][nt][2], acc[mt][nt][3]);
            }
            #pragma unroll
            for (int o = 1; o <= 2; o <<= 1) {
                ps0 += __shfl_xor_sync(0xffffffffu, ps0, o);
                pd0 += __shfl_xor_sync(0xffffffffu, pd0, o);
                ps1 += __shfl_xor_sync(0xffffffffu, ps1, o);
                pd1 += __shfl_xor_sync(0xffffffffu, pd1, o);
            }
            if ((lane & 3) == 0) {
                if (r0 < NN) { g_as1[r0 * 8 + h] = ps0; g_ad1[r0 * 8 + h] = pd0; }
                if (r1 < NN) { g_as1[r1 * 8 + h] = ps1; g_ad1[r1 * 8 + h] = pd1; }
            }
        }
    }
}

// ============ GAT1: per-lane head ownership, fp16 8B gathers, zero shuffles ============
__global__ void __launch_bounds__(256) k_gat1(const float* __restrict__ b1) {
    int n = (blockIdx.x * blockDim.x + threadIdx.x) >> 5;
    int lane = threadIdx.x & 31;
    if (n >= NN) return;
    int ha = lane >> 3, hb = ha + 4;
    int c4 = (lane & 7) * 4;

    float adA = __ldg(&g_ad1[n * 8 + ha]);
    float adB = __ldg(&g_ad1[n * 8 + hb]);
    float denA = 0.f, denB = 0.f;
    float4 accA = make_float4(0.f, 0.f, 0.f, 0.f);
    float4 accB = make_float4(0.f, 0.f, 0.f, 0.f);

    int e0 = g_rowptr[n], e1 = g_rowptr[n + 1];
    #pragma unroll 4
    for (int p = e0 - 1; p < e1; p++) {          // p = e0-1 is the self loop
        int s = (p < e0) ? n : __ldg(&g_col[p]);
        float wa = __expf(leaky(__ldg(&g_as1[s * 8 + ha]) + adA));
        float wb = __expf(leaky(__ldg(&g_as1[s * 8 + hb]) + adB));
        denA += wa; denB += wb;
        uint2 ra = *(const uint2*)&g_h1h[(size_t)s * 256 + ha * 32 + c4];
        uint2 rb = *(const uint2*)&g_h1h[(size_t)s * 256 + hb * 32 + c4];
        float2 a01 = __half22float2(*(__half2*)&ra.x);
        float2 a23 = __half22float2(*(__half2*)&ra.y);
        float2 b01 = __half22float2(*(__half2*)&rb.x);
        float2 b23 = __half22float2(*(__half2*)&rb.y);
        accA.x += wa * a01.x; accA.y += wa * a01.y; accA.z += wa * a23.x; accA.w += wa * a23.y;
        accB.x += wb * b01.x; accB.y += wb * b01.y; accB.z += wb * b23.x; accB.w += wb * b23.y;
    }
    float iA = 1.f / fmaxf(denA, 1e-16f);
    float iB = 1.f / fmaxf(denB, 1e-16f);
    float4 bA = __ldg((const float4*)&b1[ha * 32 + c4]);
    float4 bB = __ldg((const float4*)&b1[hb * 32 + c4]);
    __half2 rA0 = __floats2half2_rn(fmaxf(accA.x * iA + bA.x, 0.f), fmaxf(accA.y * iA + bA.y, 0.f));
    __half2 rA1 = __floats2half2_rn(fmaxf(accA.z * iA + bA.z, 0.f), fmaxf(accA.w * iA + bA.w, 0.f));
    __half2 rB0 = __floats2half2_rn(fmaxf(accB.x * iB + bB.x, 0.f), fmaxf(accB.y * iB + bB.y, 0.f));
    __half2 rB1 = __floats2half2_rn(fmaxf(accB.z * iB + bB.z, 0.f), fmaxf(accB.w * iB + bB.w, 0.f));
    uint2 pa, pb;
    pa.x = *(uint32_t*)&rA0; pa.y = *(uint32_t*)&rA1;
    pb.x = *(uint32_t*)&rB0; pb.y = *(uint32_t*)&rB1;
    __stcs((uint2*)&g_x2h[(size_t)n * 256 + ha * 32 + c4], pa);
    __stcs((uint2*)&g_x2h[(size_t)n * 256 + hb * 32 + c4], pb);
}

// ============ GEMM2 (fp16 x2 input) + att2 dots; h2 stored fp16 ============
__global__ void __launch_bounds__(256) k_gemm2(const float* __restrict__ W2,
                                               const float* __restrict__ attS2,
                                               const float* __restrict__ attD2) {
    __shared__ float W2s[256 * 32];
    int tid = threadIdx.x;
    for (int i = tid; i < 256 * 32; i += 256) W2s[i] = W2[i];
    __syncthreads();
    int lane = tid & 31, wl = tid >> 5;
    int n = blockIdx.x * 8 + wl;
    uint4 raw = __ldcs((const uint4*)&g_x2h[(size_t)n * 256 + lane * 8]);
    float xv[8];
    {
        float2 t0 = __half22float2(*(__half2*)&raw.x);
        float2 t1 = __half22float2(*(__half2*)&raw.y);
        float2 t2 = __half22float2(*(__half2*)&raw.z);
        float2 t3 = __half22float2(*(__half2*)&raw.w);
        xv[0] = t0.x; xv[1] = t0.y; xv[2] = t1.x; xv[3] = t1.y;
        xv[4] = t2.x; xv[5] = t2.y; xv[6] = t3.x; xv[7] = t3.y;
    }
    float acc = 0.f;
    #pragma unroll
    for (int c = 0; c < 32; c++) {
        #pragma unroll
        for (int e = 0; e < 8; e++) {
            float xb = __shfl_sync(0xffffffffu, xv[e], c);
            acc += xb * W2s[(c * 8 + e) * 32 + lane];
        }
    }
    g_h2h[n * 32 + lane] = __float2half_rn(acc);
    float ps = acc * __ldg(&attS2[lane]);
    float pd = acc * __ldg(&attD2[lane]);
    #pragma unroll
    for (int o = 16; o; o >>= 1) {
        ps += __shfl_xor_sync(0xffffffffu, ps, o);
        pd += __shfl_xor_sync(0xffffffffu, pd, o);
    }
    if (lane == 0) {
        g_as2[n] = ps;
        g_ad2[n] = pd;
    }
}

// ============ GAT2 (4-edge groups, fp16 8B loads) + fused final linear ============
__global__ void __launch_bounds__(256) k_gat2(const float* __restrict__ b2,
                                              const float* __restrict__ linW,
                                              const float* __restrict__ linb,
                                              float* __restrict__ out) {
    __shared__ float lw[32 * 40];
    __shared__ float rows[8][32];
    int tid = threadIdx.x;
    for (int i = tid; i < 32 * 40; i += 256) lw[i] = linW[i];

    int wl = tid >> 5, lane = tid & 31;
    int n = blockIdx.x * 8 + wl;
    int grp = lane >> 3, c4 = (lane & 7) * 4;

    float adst = g_ad2[n];
    float asn  = g_as2[n];
    float den; float4 acc;
    {
        float ws = __expf(leaky(asn + adst));
        if (grp == 0) {
            uint2 rh = *(const uint2*)&g_h2h[n * 32 + c4];
            float2 h01 = __half22float2(*(__half2*)&rh.x);
            float2 h23 = __half22float2(*(__half2*)&rh.y);
            den = ws;
            acc = make_float4(ws * h01.x, ws * h01.y, ws * h23.x, ws * h23.y);
        } else {
            den = 0.f;
            acc = make_float4(0.f, 0.f, 0.f, 0.f);
        }
    }
    int e0 = g_rowptr[n], e1 = g_rowptr[n + 1];
    #pragma unroll 2
    for (int p0 = e0; p0 < e1; p0 += 4) {
        int p = p0 + grp;
        bool v = p < e1;
        int s = v ? __ldg(&g_col[p]) : n;
        float w = v ? __expf(leaky(__ldg(&g_as2[s]) + adst)) : 0.f;
        den += w;
        uint2 rh = *(const uint2*)&g_h2h[s * 32 + c4];
        float2 h01 = __half22float2(*(__half2*)&rh.x);
        float2 h23 = __half22float2(*(__half2*)&rh.y);
        acc.x += w * h01.x; acc.y += w * h01.y; acc.z += w * h23.x; acc.w += w * h23.y;
    }
    #pragma unroll
    for (int o = 8; o <= 16; o <<= 1) {
        acc.x += __shfl_xor_sync(0xffffffffu, acc.x, o);
        acc.y += __shfl_xor_sync(0xffffffffu, acc.y, o);
        acc.z += __shfl_xor_sync(0xffffffffu, acc.z, o);
        acc.w += __shfl_xor_sync(0xffffffffu, acc.w, o);
        den   += __shfl_xor_sync(0xffffffffu, den, o);
    }
    if (grp == 0) {
        float inv = 1.f / fmaxf(den, 1e-16f);
        float4 bb = __ldg((const float4*)&b2[c4]);
        rows[wl][c4 + 0] = acc.x * inv + bb.x;
        rows[wl][c4 + 1] = acc.y * inv + bb.y;
        rows[wl][c4 + 2] = acc.z * inv + bb.z;
        rows[wl][c4 + 3] = acc.w * inv + bb.w;
    }
    __syncthreads();
    int nb = blockIdx.x * 8;
    for (int t = tid; t < 320; t += 256) {
        int r = t / 40, o = t % 40;
        float s = __ldg(&linb[o]);
        #pragma unroll
        for (int k = 0; k < 32; k++) s += rows[r][k] * lw[k * 40 + o];
        out[(size_t)(nb + r) * 40 + o] = s;
    }
}

// ================= launch =================
extern "C" void kernel_launch(void* const* d_in, const int* in_sizes, int n_in,
                              void* d_out, int out_size) {
    const float* x0    = (const float*)d_in[0];
    const float* W1    = (const float*)d_in[1];
    const float* attS1 = (const float*)d_in[2];
    const float* attD1 = (const float*)d_in[3];
    const float* b1    = (const float*)d_in[4];
    const float* W2    = (const float*)d_in[5];
    const float* attS2 = (const float*)d_in[6];
    const float* attD2 = (const float*)d_in[7];
    const float* b2    = (const float*)d_in[8];
    const float* linW  = (const float*)d_in[9];
    const float* linb  = (const float*)d_in[10];
    const int*   ei    = (const int*)d_in[11];
    float* out = (float*)d_out;

    static cudaStream_t s_side = nullptr;
    static cudaEvent_t ev_fork = nullptr, ev_join = nullptr;
    if (!s_side) {
        cudaFuncSetAttribute(k_gemm1_mma, cudaFuncAttributeMaxDynamicSharedMemorySize, SM_G1);
        cudaStreamCreateWithFlags(&s_side, cudaStreamNonBlocking);
        cudaEventCreateWithFlags(&ev_fork, cudaEventDisableTiming);
        cudaEventCreateWithFlags(&ev_join, cudaEventDisableTiming);
    }

    const int NBLK = (NN + 1023) / 1024;   // 98

    // fork: CSR chain on side stream; prep+gemm1 on main.
    // submission order makes gemm1 global launch #4 (ncu profiles the 4th launch).
    cudaEventRecord(ev_fork, 0);
    cudaStreamWaitEvent(s_side, ev_fork, 0);
    k_prepw1<<<128, 256>>>(W1);                                  // 1 (main)
    k_zero<<<(NN + 255) / 256, 256, 0, s_side>>>();              // 2 (side)
    k_hist<<<(EE + 255) / 256, 256, 0, s_side>>>(ei);            // 3 (side)
    k_gemm1_mma<<<(NN + 63) / 64, 256, SM_G1>>>(x0, attS1, attD1); // 4 (main)
    k_scan1<<<NBLK, 1024, 0, s_side>>>();                        // 5
    k_scan2<<<1, 128, 0, s_side>>>(NBLK);                        // 6
    k_scan3<<<NBLK, 1024, 0, s_side>>>();                        // 7
    k_scatter<<<(EE + 255) / 256, 256, 0, s_side>>>(ei);         // 8
    cudaEventRecord(ev_join, s_side);

    // join: gat1 needs both gemm1 (main) and CSR (side)
    cudaStreamWaitEvent(0, ev_join, 0);
    k_gat1<<<(NN + 7) / 8, 256>>>(b1);
    k_gemm2<<<NN / 8, 256>>>(W2, attS2, attD2);
    k_gat2<<<NN / 8, 256>>>(b2, linW, linb, out);
}

// round 12
// speedup vs baseline: 3.7336x; 1.6365x over previous
#include <cuda_runtime.h>
#include <cuda_bf16.h>
#include <cuda_fp16.h>
#include <cstdint>

#define NN   100000
#define EE   1000000
#define HID  32
#define NH1  8
#define OUTC 40
#define NEGS 0.2f

// ================= device scratch =================
__device__ __align__(16) __half g_h1h[(size_t)NN * 256];   // layer1 messages, fp16
__device__ __align__(16) __half g_x2h[(size_t)NN * 256];   // relu(layer1 out), fp16
__device__ __align__(16) float g_as1[NN * NH1];
__device__ __align__(16) float g_ad1[NN * NH1];
__device__ __align__(16) __half g_h2h[NN * HID];           // layer2 messages, fp16
__device__ __align__(16) float g_as2[NN];
__device__ __align__(16) float g_ad2[NN];
__device__ __align__(16) __nv_bfloat16 g_w1hi[32768];      // W1 split, tile layout [ct][n][k]
__device__ __align__(16) __nv_bfloat16 g_w1lo[32768];
__device__ __align__(16) __half g_w2hi[8192];              // W2 split fp16, [n][k] layout
__device__ __align__(16) __half g_w2lo[8192];
__device__ int g_cnt[NN];
__device__ int g_rowptr[NN + 1];
__device__ int g_cursor[NN];
__device__ int g_col[EE];
__device__ int g_bsum[128];
__device__ int g_boff[128];

__device__ __forceinline__ float leaky(float x) { return x > 0.f ? x : NEGS * x; }

__device__ __forceinline__ uint32_t smem_u32(const void* p) {
    uint32_t a;
    asm("{ .reg .u64 t; cvta.to.shared.u64 t, %1; cvt.u32.u64 %0, t; }" : "=r"(a) : "l"(p));
    return a;
}

#define LDSM4(r0, r1, r2, r3, a) \
    asm volatile("ldmatrix.sync.aligned.m8n8.x4.shared.b16 {%0,%1,%2,%3}, [%4];" \
                 : "=r"(r0), "=r"(r1), "=r"(r2), "=r"(r3) : "r"(a))
#define MMA16816(c, a0, a1, a2, a3, b0, b1) \
    asm volatile("mma.sync.aligned.m16n8k16.row.col.f32.bf16.bf16.f32 " \
                 "{%0,%1,%2,%3},{%4,%5,%6,%7},{%8,%9},{%0,%1,%2,%3};" \
                 : "+f"((c)[0]), "+f"((c)[1]), "+f"((c)[2]), "+f"((c)[3]) \
                 : "r"(a0), "r"(a1), "r"(a2), "r"(a3), "r"(b0), "r"(b1))
#define MMA16816H(c, a0, a1, a2, a3, b0, b1) \
    asm volatile("mma.sync.aligned.m16n8k16.row.col.f32.f16.f16.f32 " \
                 "{%0,%1,%2,%3},{%4,%5,%6,%7},{%8,%9},{%0,%1,%2,%3};" \
                 : "+f"((c)[0]), "+f"((c)[1]), "+f"((c)[2]), "+f"((c)[3]) \
                 : "r"(a0), "r"(a1), "r"(a2), "r"(a3), "r"(b0), "r"(b1))

// ================= weight prep =================
__global__ void k_prepw1(const float* __restrict__ W1) {
    int idx = blockIdx.x * blockDim.x + threadIdx.x;
    if (idx >= 32768) return;
    int k = idx >> 8, n = idx & 255;
    float v = __ldg(&W1[idx]);
    __nv_bfloat16 hi = __float2bfloat16(v);
    __nv_bfloat16 lo = __float2bfloat16(v - __bfloat162float(hi));
    int ct = n >> 7, nl = n & 127;
    int off = ct * 16384 + nl * 128 + k;
    g_w1hi[off] = hi;
    g_w1lo[off] = lo;
}
__global__ void k_prepw2(const float* __restrict__ W2) {
    int idx = blockIdx.x * blockDim.x + threadIdx.x;
    if (idx >= 8192) return;
    int k = idx >> 5, n = idx & 31;
    float v = __ldg(&W2[idx]);
    __half hi = __float2half_rn(v);
    __half lo = __float2half_rn(v - __half2float(hi));
    g_w2hi[n * 256 + k] = hi;
    g_w2lo[n * 256 + k] = lo;
}

// ================= CSR build =================
__global__ void k_zero() {
    int i = blockIdx.x * blockDim.x + threadIdx.x;
    if (i < NN) g_cnt[i] = 0;
}
__global__ void k_hist(const int* __restrict__ ei) {
    int e = blockIdx.x * blockDim.x + threadIdx.x;
    if (e < EE) atomicAdd(&g_cnt[ei[EE + e]], 1);
}
__global__ void __launch_bounds__(1024) k_scan1() {
    __shared__ int ws[32];
    int tid = threadIdx.x, lane = tid & 31, wid = tid >> 5;
    int i = blockIdx.x * 1024 + tid;
    int v = (i < NN) ? g_cnt[i] : 0;
    int x = v;
    #pragma unroll
    for (int o = 1; o < 32; o <<= 1) {
        int y = __shfl_up_sync(0xffffffffu, x, o);
        if (lane >= o) x += y;
    }
    if (lane == 31) ws[wid] = x;
    __syncthreads();
    if (wid == 0) {
        int s = ws[lane];
        #pragma unroll
        for (int o = 1; o < 32; o <<= 1) {
            int y = __shfl_up_sync(0xffffffffu, s, o);
            if (lane >= o) s += y;
        }
        ws[lane] = s;
    }
    __syncthreads();
    int incl = x + (wid ? ws[wid - 1] : 0);
    if (i < NN) g_rowptr[i] = incl - v;
    if (tid == 1023) g_bsum[blockIdx.x] = incl;
}
__global__ void k_scan2(int nblk) {
    __shared__ int ws[4];
    int tid = threadIdx.x, lane = tid & 31, wid = tid >> 5;
    int v = (tid < nblk) ? g_bsum[tid] : 0;
    int x = v;
    #pragma unroll
    for (int o = 1; o < 32; o <<= 1) {
        int y = __shfl_up_sync(0xffffffffu, x, o);
        if (lane >= o) x += y;
    }
    if (lane == 31) ws[wid] = x;
    __syncthreads();
    int pre = 0;
    for (int w = 0; w < wid; w++) pre += ws[w];
    int incl = x + pre;
    if (tid < nblk) g_boff[tid] = incl - v;
    if (tid == nblk - 1) g_rowptr[NN] = incl;
}
__global__ void __launch_bounds__(1024) k_scan3() {
    int i = blockIdx.x * 1024 + threadIdx.x;
    if (i < NN) {
        int r = g_rowptr[i] + g_boff[blockIdx.x];
        g_rowptr[i] = r;
        g_cursor[i] = r;
    }
}
__global__ void k_scatter(const int* __restrict__ ei) {
    int e = blockIdx.x * blockDim.x + threadIdx.x;
    if (e < EE) {
        int s = ei[e];
        int d = ei[EE + e];
        int pos = atomicAdd(&g_cursor[d], 1);
        g_col[pos] = s;
    }
}

// ======== GEMM1: 64-row tiles, 2 CTAs/SM, bf16-split mma + fused att1 dots ========
#define SKEW 136
#define SA_HI 0
#define SA_LO 17408
#define SB_HI 34816
#define SB_LO 69632
#define SM_G1 104448

__global__ void __launch_bounds__(256, 2) k_gemm1_mma(const float* __restrict__ x0,
                                                      const float* __restrict__ attS,
                                                      const float* __restrict__ attD) {
    extern __shared__ __align__(128) char smem[];
    __nv_bfloat16* sAhi = (__nv_bfloat16*)(smem + SA_HI);
    __nv_bfloat16* sAlo = (__nv_bfloat16*)(smem + SA_LO);
    __nv_bfloat16* sBhi = (__nv_bfloat16*)(smem + SB_HI);
    __nv_bfloat16* sBlo = (__nv_bfloat16*)(smem + SB_LO);
    uint32_t sb = smem_u32(smem);

    int tid = threadIdx.x;
    int rowBase = blockIdx.x * 64;

    #pragma unroll 4
    for (int i = 0; i < 32; i++) {
        int idx = i * 256 + tid;
        int r = idx >> 7, c = idx & 127;
        int grow = rowBase + r;
        float v = (grow < NN) ? __ldg(&x0[(size_t)grow * 128 + c]) : 0.f;
        __nv_bfloat16 hi = __float2bfloat16(v);
        __nv_bfloat16 lo = __float2bfloat16(v - __bfloat162float(hi));
        sAhi[r * SKEW + c] = hi;
        sAlo[r * SKEW + c] = lo;
    }

    int wid = tid >> 5, lane = tid & 31;
    int warpM = wid >> 2, warpN = wid & 3;
    int aRow = warpM * 32 + (lane & 15);
    int aColHalf = (lane >> 4) * 8;
    int bRowX4 = ((lane >> 4) * 8) + (lane & 7);   // x4 pair row within 16-row block
    int bColHalf = ((lane >> 3) & 1) * 8;
    int rq = lane >> 2, cq = (lane & 3) * 2;

    #pragma unroll 1
    for (int ct = 0; ct < 2; ct++) {
        __syncthreads();
        {
            const uint4* srcH = (const uint4*)(g_w1hi + ct * 16384);
            const uint4* srcL = (const uint4*)(g_w1lo + ct * 16384);
            #pragma unroll
            for (int i = 0; i < 8; i++) {
                int q = i * 256 + tid;
                int nl = q >> 4, k8 = (q & 15) * 8;
                *(uint4*)&sBhi[nl * SKEW + k8] = srcH[q];
                *(uint4*)&sBlo[nl * SKEW + k8] = srcL[q];
            }
        }
        __syncthreads();

        float acc[2][4][4];
        #pragma unroll
        for (int mt = 0; mt < 2; mt++)
            #pragma unroll
            for (int nt = 0; nt < 4; nt++)
                #pragma unroll
                for (int q = 0; q < 4; q++) acc[mt][nt][q] = 0.f;

        #pragma unroll 1
        for (int ks = 0; ks < 8; ks++) {
            uint32_t ah[2][4], al[2][4], bh[4][2], bl[4][2];
            #pragma unroll
            for (int mt = 0; mt < 2; mt++) {
                uint32_t off = (uint32_t)(((aRow + mt * 16) * SKEW) + ks * 16 + aColHalf) * 2;
                LDSM4(ah[mt][0], ah[mt][1], ah[mt][2], ah[mt][3], sb + SA_HI + off);
                LDSM4(al[mt][0], al[mt][1], al[mt][2], al[mt][3], sb + SA_LO + off);
            }
            #pragma unroll
            for (int p = 0; p < 2; p++) {
                uint32_t off = (uint32_t)(((warpN * 32 + p * 16 + bRowX4) * SKEW) + ks * 16 + bColHalf) * 2;
                LDSM4(bh[2 * p][0], bh[2 * p][1], bh[2 * p + 1][0], bh[2 * p + 1][1], sb + SB_HI + off);
                LDSM4(bl[2 * p][0], bl[2 * p][1], bl[2 * p + 1][0], bl[2 * p + 1][1], sb + SB_LO + off);
            }
            #pragma unroll
            for (int mt = 0; mt < 2; mt++)
                #pragma unroll
                for (int nt = 0; nt < 4; nt++) {
                    MMA16816(acc[mt][nt], ah[mt][0], ah[mt][1], ah[mt][2], ah[mt][3],
                             bh[nt][0], bh[nt][1]);
                    MMA16816(acc[mt][nt], ah[mt][0], ah[mt][1], ah[mt][2], ah[mt][3],
                             bl[nt][0], bl[nt][1]);
                    MMA16816(acc[mt][nt], al[mt][0], al[mt][1], al[mt][2], al[mt][3],
                             bh[nt][0], bh[nt][1]);
                }
        }

        int h = ct * 4 + warpN;
        float aS[8], aD[8];
        #pragma unroll
        for (int nt = 0; nt < 4; nt++) {
            aS[nt * 2 + 0] = __ldg(&attS[h * 32 + nt * 8 + cq]);
            aS[nt * 2 + 1] = __ldg(&attS[h * 32 + nt * 8 + cq + 1]);
            aD[nt * 2 + 0] = __ldg(&attD[h * 32 + nt * 8 + cq]);
            aD[nt * 2 + 1] = __ldg(&attD[h * 32 + nt * 8 + cq + 1]);
        }
        #pragma unroll
        for (int mt = 0; mt < 2; mt++) {
            int r0 = rowBase + warpM * 32 + mt * 16 + rq;
            int r1 = r0 + 8;
            float ps0 = 0.f, pd0 = 0.f, ps1 = 0.f, pd1 = 0.f;
            #pragma unroll
            for (int nt = 0; nt < 4; nt++) {
                ps0 += acc[mt][nt][0] * aS[nt * 2] + acc[mt][nt][1] * aS[nt * 2 + 1];
                pd0 += acc[mt][nt][0] * aD[nt * 2] + acc[mt][nt][1] * aD[nt * 2 + 1];
                ps1 += acc[mt][nt][2] * aS[nt * 2] + acc[mt][nt][3] * aS[nt * 2 + 1];
                pd1 += acc[mt][nt][2] * aD[nt * 2] + acc[mt][nt][3] * aD[nt * 2 + 1];
                int cc = ct * 128 + warpN * 32 + nt * 8 + cq;
                if (r0 < NN)
                    *(__half2*)&g_h1h[(size_t)r0 * 256 + cc] =
                        __floats2half2_rn(acc[mt][nt][0], acc[mt][nt][1]);
                if (r1 < NN)
                    *(__half2*)&g_h1h[(size_t)r1 * 256 + cc] =
                        __floats2half2_rn(acc[mt][nt][2], acc[mt][nt][3]);
            }
            #pragma unroll
            for (int o = 1; o <= 2; o <<= 1) {
                ps0 += __shfl_xor_sync(0xffffffffu, ps0, o);
                pd0 += __shfl_xor_sync(0xffffffffu, pd0, o);
                ps1 += __shfl_xor_sync(0xffffffffu, ps1, o);
                pd1 += __shfl_xor_sync(0xffffffffu, pd1, o);
            }
            if ((lane & 3) == 0) {
                if (r0 < NN) { g_as1[r0 * 8 + h] = ps0; g_ad1[r0 * 8 + h] = pd0; }
                if (r1 < NN) { g_as1[r1 * 8 + h] = ps1; g_ad1[r1 * 8 + h] = pd1; }
            }
        }
    }
}

// ============ GAT1: per-lane head ownership, fp16 8B gathers, zero shuffles ============
__global__ void __launch_bounds__(256) k_gat1(const float* __restrict__ b1) {
    int n = (blockIdx.x * blockDim.x + threadIdx.x) >> 5;
    int lane = threadIdx.x & 31;
    if (n >= NN) return;
    int ha = lane >> 3, hb = ha + 4;
    int c4 = (lane & 7) * 4;

    float adA = __ldg(&g_ad1[n * 8 + ha]);
    float adB = __ldg(&g_ad1[n * 8 + hb]);
    float denA = 0.f, denB = 0.f;
    float4 accA = make_float4(0.f, 0.f, 0.f, 0.f);
    float4 accB = make_float4(0.f, 0.f, 0.f, 0.f);

    int e0 = g_rowptr[n], e1 = g_rowptr[n + 1];
    #pragma unroll 4
    for (int p = e0 - 1; p < e1; p++) {
        int s = (p < e0) ? n : __ldg(&g_col[p]);
        float wa = __expf(leaky(__ldg(&g_as1[s * 8 + ha]) + adA));
        float wb = __expf(leaky(__ldg(&g_as1[s * 8 + hb]) + adB));
        denA += wa; denB += wb;
        uint2 ra = *(const uint2*)&g_h1h[(size_t)s * 256 + ha * 32 + c4];
        uint2 rb = *(const uint2*)&g_h1h[(size_t)s * 256 + hb * 32 + c4];
        float2 a01 = __half22float2(*(__half2*)&ra.x);
        float2 a23 = __half22float2(*(__half2*)&ra.y);
        float2 b01 = __half22float2(*(__half2*)&rb.x);
        float2 b23 = __half22float2(*(__half2*)&rb.y);
        accA.x += wa * a01.x; accA.y += wa * a01.y; accA.z += wa * a23.x; accA.w += wa * a23.y;
        accB.x += wb * b01.x; accB.y += wb * b01.y; accB.z += wb * b23.x; accB.w += wb * b23.y;
    }
    float iA = 1.f / fmaxf(denA, 1e-16f);
    float iB = 1.f / fmaxf(denB, 1e-16f);
    float4 bA = __ldg((const float4*)&b1[ha * 32 + c4]);
    float4 bB = __ldg((const float4*)&b1[hb * 32 + c4]);
    __half2 rA0 = __floats2half2_rn(fmaxf(accA.x * iA + bA.x, 0.f), fmaxf(accA.y * iA + bA.y, 0.f));
    __half2 rA1 = __floats2half2_rn(fmaxf(accA.z * iA + bA.z, 0.f), fmaxf(accA.w * iA + bA.w, 0.f));
    __half2 rB0 = __floats2half2_rn(fmaxf(accB.x * iB + bB.x, 0.f), fmaxf(accB.y * iB + bB.y, 0.f));
    __half2 rB1 = __floats2half2_rn(fmaxf(accB.z * iB + bB.z, 0.f), fmaxf(accB.w * iB + bB.w, 0.f));
    uint2 pa, pb;
    pa.x = *(uint32_t*)&rA0; pa.y = *(uint32_t*)&rA1;
    pb.x = *(uint32_t*)&rB0; pb.y = *(uint32_t*)&rB1;
    __stcs((uint2*)&g_x2h[(size_t)n * 256 + ha * 32 + c4], pa);
    __stcs((uint2*)&g_x2h[(size_t)n * 256 + hb * 32 + c4], pb);
}

// ======== GEMM2 via fp16 mma: h2 = x2 @ W2 (K=256 -> 32) + fused att2 dots ========
// A (x2h) is exact fp16; W2 split hi+lo fp16 -> ~fp32 accuracy in 2 passes.
#define SKEW2 264
#define G2_SA  0
#define G2_SBH 67584
#define G2_SBL 84480
#define SM_G2  101376

__global__ void __launch_bounds__(256, 2) k_gemm2_mma(const float* __restrict__ attS2,
                                                      const float* __restrict__ attD2) {
    extern __shared__ __align__(128) char smem[];
    __half* sA  = (__half*)(smem + G2_SA);
    __half* sBh = (__half*)(smem + G2_SBH);
    __half* sBl = (__half*)(smem + G2_SBL);
    uint32_t sb = smem_u32(smem);

    int tid = threadIdx.x;
    int rowBase = blockIdx.x * 128;

    // stage A: 128 rows x 256 halves (pure copy, zeros for pad rows)
    #pragma unroll 4
    for (int i = 0; i < 16; i++) {
        int q = i * 256 + tid;              // uint4 index, 4096 total
        int r = q >> 5, c8 = (q & 31) * 8;
        int grow = rowBase + r;
        uint4 v = (grow < NN) ? *(const uint4*)&g_x2h[(size_t)grow * 256 + c8]
                              : make_uint4(0, 0, 0, 0);
        *(uint4*)&sA[r * SKEW2 + c8] = v;
    }
    // stage B: 32 rows x 256 halves x 2 images (pure copy)
    #pragma unroll
    for (int i = 0; i < 4; i++) {
        int q = i * 256 + tid;              // uint4 index, 1024 total
        int nl = q >> 5, k8 = (q & 31) * 8;
        *(uint4*)&sBh[nl * SKEW2 + k8] = *(const uint4*)&g_w2hi[nl * 256 + k8];
        *(uint4*)&sBl[nl * SKEW2 + k8] = *(const uint4*)&g_w2lo[nl * 256 + k8];
    }
    __syncthreads();

    int wid = tid >> 5, lane = tid & 31;    // warp = 16 rows x 32 cols
    int aRow = wid * 16 + (lane & 15);
    int aColHalf = (lane >> 4) * 8;
    int bRowX4 = ((lane >> 4) * 8) + (lane & 7);
    int bColHalf = ((lane >> 3) & 1) * 8;
    int rq = lane >> 2, cq = (lane & 3) * 2;

    float acc[4][4];
    #pragma unroll
    for (int nt = 0; nt < 4; nt++)
        #pragma unroll
        for (int q = 0; q < 4; q++) acc[nt][q] = 0.f;

    #pragma unroll 2
    for (int ks = 0; ks < 16; ks++) {
        uint32_t a[4], bh[4][2], bl[4][2];
        LDSM4(a[0], a[1], a[2], a[3],
              sb + G2_SA + (uint32_t)(aRow * SKEW2 + ks * 16 + aColHalf) * 2);
        #pragma unroll
        for (int p = 0; p < 2; p++) {
            uint32_t off = (uint32_t)((p * 16 + bRowX4) * SKEW2 + ks * 16 + bColHalf) * 2;
            LDSM4(bh[2 * p][0], bh[2 * p][1], bh[2 * p + 1][0], bh[2 * p + 1][1], sb + G2_SBH + off);
            LDSM4(bl[2 * p][0], bl[2 * p][1], bl[2 * p + 1][0], bl[2 * p + 1][1], sb + G2_SBL + off);
        }
        #pragma unroll
        for (int nt = 0; nt < 4; nt++) {
            MMA16816H(acc[nt], a[0], a[1], a[2], a[3], bh[nt][0], bh[nt][1]);
            MMA16816H(acc[nt], a[0], a[1], a[2], a[3], bl[nt][0], bl[nt][1]);
        }
    }

    // epilogue: h2h store + att2 dots (quad reduce)
    float aS[8], aD[8];
    #pragma unroll
    for (int nt = 0; nt < 4; nt++) {
        aS[nt * 2 + 0] = __ldg(&attS2[nt * 8 + cq]);
        aS[nt * 2 + 1] = __ldg(&attS2[nt * 8 + cq + 1]);
        aD[nt * 2 + 0] = __ldg(&attD2[nt * 8 + cq]);
        aD[nt * 2 + 1] = __ldg(&attD2[nt * 8 + cq + 1]);
    }
    int r0 = rowBase + wid * 16 + rq;
    int r1 = r0 + 8;
    float ps0 = 0.f, pd0 = 0.f, ps1 = 0.f, pd1 = 0.f;
    #pragma unroll
    for (int nt = 0; nt < 4; nt++) {
        ps0 += acc[nt][0] * aS[nt * 2] + acc[nt][1] * aS[nt * 2 + 1];
        pd0 += acc[nt][0] * aD[nt * 2] + acc[nt][1] * aD[nt * 2 + 1];
        ps1 += acc[nt][2] * aS[nt * 2] + acc[nt][3] * aS[nt * 2 + 1];
        pd1 += acc[nt][2] * aD[nt * 2] + acc[nt][3] * aD[nt * 2 + 1];
        int cc = nt * 8 + cq;
        if (r0 < NN)
            *(__half2*)&g_h2h[r0 * 32 + cc] = __floats2half2_rn(acc[nt][0], acc[nt][1]);
        if (r1 < NN)
            *(__half2*)&g_h2h[r1 * 32 + cc] = __floats2half2_rn(acc[nt][2], acc[nt][3]);
    }
    #pragma unroll
    for (int o = 1; o <= 2; o <<= 1) {
        ps0 += __shfl_xor_sync(0xffffffffu, ps0, o);
        pd0 += __shfl_xor_sync(0xffffffffu, pd0, o);
        ps1 += __shfl_xor_sync(0xffffffffu, ps1, o);
        pd1 += __shfl_xor_sync(0xffffffffu, pd1, o);
    }
    if ((lane & 3) == 0) {
        if (r0 < NN) { g_as2[r0] = ps0; g_ad2[r0] = pd0; }
        if (r1 < NN) { g_as2[r1] = ps1; g_ad2[r1] = pd1; }
    }
}

// ============ GAT2 (4-edge groups, fp16 8B loads) + fused final linear ============
__global__ void __launch_bounds__(256) k_gat2(const float* __restrict__ b2,
                                              const float* __restrict__ linW,
                                              const float* __restrict__ linb,
                                              float* __restrict__ out) {
    __shared__ float lw[32 * 40];
    __shared__ float rows[8][32];
    int tid = threadIdx.x;
    for (int i = tid; i < 32 * 40; i += 256) lw[i] = linW[i];

    int wl = tid >> 5, lane = tid & 31;
    int n = blockIdx.x * 8 + wl;
    int grp = lane >> 3, c4 = (lane & 7) * 4;

    float adst = g_ad2[n];
    float asn  = g_as2[n];
    float den; float4 acc;
    {
        float ws = __expf(leaky(asn + adst));
        if (grp == 0) {
            uint2 rh = *(const uint2*)&g_h2h[n * 32 + c4];
            float2 h01 = __half22float2(*(__half2*)&rh.x);
            float2 h23 = __half22float2(*(__half2*)&rh.y);
            den = ws;
            acc = make_float4(ws * h01.x, ws * h01.y, ws * h23.x, ws * h23.y);
        } else {
            den = 0.f;
            acc = make_float4(0.f, 0.f, 0.f, 0.f);
        }
    }
    int e0 = g_rowptr[n], e1 = g_rowptr[n + 1];
    #pragma unroll 2
    for (int p0 = e0; p0 < e1; p0 += 4) {
        int p = p0 + grp;
        bool v = p < e1;
        int s = v ? __ldg(&g_col[p]) : n;
        float w = v ? __expf(leaky(__ldg(&g_as2[s]) + adst)) : 0.f;
        den += w;
        uint2 rh = *(const uint2*)&g_h2h[s * 32 + c4];
        float2 h01 = __half22float2(*(__half2*)&rh.x);
        float2 h23 = __half22float2(*(__half2*)&rh.y);
        acc.x += w * h01.x; acc.y += w * h01.y; acc.z += w * h23.x; acc.w += w * h23.y;
    }
    #pragma unroll
    for (int o = 8; o <= 16; o <<= 1) {
        acc.x += __shfl_xor_sync(0xffffffffu, acc.x, o);
        acc.y += __shfl_xor_sync(0xffffffffu, acc.y, o);
        acc.z += __shfl_xor_sync(0xffffffffu, acc.z, o);
        acc.w += __shfl_xor_sync(0xffffffffu, acc.w, o);
        den   += __shfl_xor_sync(0xffffffffu, den, o);
    }
    if (grp == 0) {
        float inv = 1.f / fmaxf(den, 1e-16f);
        float4 bb = __ldg((const float4*)&b2[c4]);
        rows[wl][c4 + 0] = acc.x * inv + bb.x;
        rows[wl][c4 + 1] = acc.y * inv + bb.y;
        rows[wl][c4 + 2] = acc.z * inv + bb.z;
        rows[wl][c4 + 3] = acc.w * inv + bb.w;
    }
    __syncthreads();
    int nb = blockIdx.x * 8;
    for (int t = tid; t < 320; t += 256) {
        int r = t / 40, o = t % 40;
        float s = __ldg(&linb[o]);
        #pragma unroll
        for (int k = 0; k < 32; k++) s += rows[r][k] * lw[k * 40 + o];
        out[(size_t)(nb + r) * 40 + o] = s;
    }
}

// ================= launch =================
extern "C" void kernel_launch(void* const* d_in, const int* in_sizes, int n_in,
                              void* d_out, int out_size) {
    const float* x0    = (const float*)d_in[0];
    const float* W1    = (const float*)d_in[1];
    const float* attS1 = (const float*)d_in[2];
    const float* attD1 = (const float*)d_in[3];
    const float* b1    = (const float*)d_in[4];
    const float* W2    = (const float*)d_in[5];
    const float* attS2 = (const float*)d_in[6];
    const float* attD2 = (const float*)d_in[7];
    const float* b2    = (const float*)d_in[8];
    const float* linW  = (const float*)d_in[9];
    const float* linb  = (const float*)d_in[10];
    const int*   ei    = (const int*)d_in[11];
    float* out = (float*)d_out;

    static cudaStream_t s_side = nullptr;
    static cudaEvent_t ev_fork = nullptr, ev_join = nullptr;
    if (!s_side) {
        cudaFuncSetAttribute(k_gemm1_mma, cudaFuncAttributeMaxDynamicSharedMemorySize, SM_G1);
        cudaFuncSetAttribute(k_gemm2_mma, cudaFuncAttributeMaxDynamicSharedMemorySize, SM_G2);
        cudaStreamCreateWithFlags(&s_side, cudaStreamNonBlocking);
        cudaEventCreateWithFlags(&ev_fork, cudaEventDisableTiming);
        cudaEventCreateWithFlags(&ev_join, cudaEventDisableTiming);
    }

    const int NBLK = (NN + 1023) / 1024;   // 98

    // fork: CSR chain + weight preps on side stream; gemm1 stays launch #4 (ncu).
    cudaEventRecord(ev_fork, 0);
    cudaStreamWaitEvent(s_side, ev_fork, 0);
    k_prepw1<<<128, 256>>>(W1);                                  // 1 (main)
    k_zero<<<(NN + 255) / 256, 256, 0, s_side>>>();              // 2 (side)
    k_hist<<<(EE + 255) / 256, 256, 0, s_side>>>(ei);            // 3 (side)
    k_gemm1_mma<<<(NN + 63) / 64, 256, SM_G1>>>(x0, attS1, attD1); // 4 (main)
    k_prepw2<<<32, 256, 0, s_side>>>(W2);                        // 5 (side)
    k_scan1<<<NBLK, 1024, 0, s_side>>>();                        // 6
    k_scan2<<<1, 128, 0, s_side>>>(NBLK);                        // 7
    k_scan3<<<NBLK, 1024, 0, s_side>>>();                        // 8
    k_scatter<<<(EE + 255) / 256, 256, 0, s_side>>>(ei);         // 9
    cudaEventRecord(ev_join, s_side);

    cudaStreamWaitEvent(0, ev_join, 0);
    k_gat1<<<(NN + 7) / 8, 256>>>(b1);
    k_gemm2_mma<<<(NN + 127) / 128, 256, SM_G2>>>(attS2, attD2);
    k_gat2<<<NN / 8, 256>>>(b2, linW, linb, out);
}

// round 13
// speedup vs baseline: 4.0978x; 1.0975x over previous
#include <cuda_runtime.h>
#include <cuda_bf16.h>
#include <cuda_fp16.h>
#include <cstdint>

#define NN   100000
#define EE   1000000
#define HID  32
#define NH1  8
#define OUTC 40
#define NEGS 0.2f

// ================= device scratch =================
__device__ __align__(16) __half g_h1h[(size_t)NN * 256];   // layer1 messages, fp16
__device__ __align__(16) __half g_x2h[(size_t)NN * 256];   // relu(layer1 out), fp16
__device__ __align__(16) float g_as1[NN * NH1];
__device__ __align__(16) float g_ad1[NN * NH1];
__device__ __align__(16) __half g_h2h[NN * HID];           // layer2 messages, fp16
__device__ __align__(16) float g_as2[NN];
__device__ __align__(16) float g_ad2[NN];
__device__ __align__(16) __half g_w1h[32768];              // W1 fp16 hi, tile layout [ct][n][k]
__device__ __align__(16) __half g_w2hi[8192];              // W2 split fp16, [n][k] layout
__device__ __align__(16) __half g_w2lo[8192];
__device__ int g_cnt[NN];
__device__ int g_rowptr[NN + 1];
__device__ int g_cursor[NN];
__device__ int g_col[EE];
__device__ int g_bsum[128];
__device__ int g_boff[128];

__device__ __forceinline__ float leaky(float x) { return x > 0.f ? x : NEGS * x; }

__device__ __forceinline__ uint32_t smem_u32(const void* p) {
    uint32_t a;
    asm("{ .reg .u64 t; cvta.to.shared.u64 t, %1; cvt.u32.u64 %0, t; }" : "=r"(a) : "l"(p));
    return a;
}

#define LDSM4(r0, r1, r2, r3, a) \
    asm volatile("ldmatrix.sync.aligned.m8n8.x4.shared.b16 {%0,%1,%2,%3}, [%4];" \
                 : "=r"(r0), "=r"(r1), "=r"(r2), "=r"(r3) : "r"(a))
#define MMA16816H(c, a0, a1, a2, a3, b0, b1) \
    asm volatile("mma.sync.aligned.m16n8k16.row.col.f32.f16.f16.f32 " \
                 "{%0,%1,%2,%3},{%4,%5,%6,%7},{%8,%9},{%0,%1,%2,%3};" \
                 : "+f"((c)[0]), "+f"((c)[1]), "+f"((c)[2]), "+f"((c)[3]) \
                 : "r"(a0), "r"(a1), "r"(a2), "r"(a3), "r"(b0), "r"(b1))

// ================= weight prep =================
__global__ void k_prepw1(const float* __restrict__ W1) {
    int idx = blockIdx.x * blockDim.x + threadIdx.x;
    if (idx >= 32768) return;
    int k = idx >> 8, n = idx & 255;
    float v = __ldg(&W1[idx]);
    int ct = n >> 7, nl = n & 127;
    g_w1h[ct * 16384 + nl * 128 + k] = __float2half_rn(v);
}
__global__ void k_prepw2(const float* __restrict__ W2) {
    int idx = blockIdx.x * blockDim.x + threadIdx.x;
    if (idx >= 8192) return;
    int k = idx >> 5, n = idx & 31;
    float v = __ldg(&W2[idx]);
    __half hi = __float2half_rn(v);
    __half lo = __float2half_rn(v - __half2float(hi));
    g_w2hi[n * 256 + k] = hi;
    g_w2lo[n * 256 + k] = lo;
}

// ================= CSR build =================
__global__ void k_zero() {
    int i = blockIdx.x * blockDim.x + threadIdx.x;
    if (i < NN) g_cnt[i] = 0;
}
__global__ void k_hist(const int* __restrict__ ei) {
    int e = blockIdx.x * blockDim.x + threadIdx.x;
    if (e < EE) atomicAdd(&g_cnt[ei[EE + e]], 1);
}
__global__ void __launch_bounds__(1024) k_scan1() {
    __shared__ int ws[32];
    int tid = threadIdx.x, lane = tid & 31, wid = tid >> 5;
    int i = blockIdx.x * 1024 + tid;
    int v = (i < NN) ? g_cnt[i] : 0;
    int x = v;
    #pragma unroll
    for (int o = 1; o < 32; o <<= 1) {
        int y = __shfl_up_sync(0xffffffffu, x, o);
        if (lane >= o) x += y;
    }
    if (lane == 31) ws[wid] = x;
    __syncthreads();
    if (wid == 0) {
        int s = ws[lane];
        #pragma unroll
        for (int o = 1; o < 32; o <<= 1) {
            int y = __shfl_up_sync(0xffffffffu, s, o);
            if (lane >= o) s += y;
        }
        ws[lane] = s;
    }
    __syncthreads();
    int incl = x + (wid ? ws[wid - 1] : 0);
    if (i < NN) g_rowptr[i] = incl - v;
    if (tid == 1023) g_bsum[blockIdx.x] = incl;
}
__global__ void k_scan2(int nblk) {
    __shared__ int ws[4];
    int tid = threadIdx.x, lane = tid & 31, wid = tid >> 5;
    int v = (tid < nblk) ? g_bsum[tid] : 0;
    int x = v;
    #pragma unroll
    for (int o = 1; o < 32; o <<= 1) {
        int y = __shfl_up_sync(0xffffffffu, x, o);
        if (lane >= o) x += y;
    }
    if (lane == 31) ws[wid] = x;
    __syncthreads();
    int pre = 0;
    for (int w = 0; w < wid; w++) pre += ws[w];
    int incl = x + pre;
    if (tid < nblk) g_boff[tid] = incl - v;
    if (tid == nblk - 1) g_rowptr[NN] = incl;
}
__global__ void __launch_bounds__(1024) k_scan3() {
    int i = blockIdx.x * 1024 + threadIdx.x;
    if (i < NN) {
        int r = g_rowptr[i] + g_boff[blockIdx.x];
        g_rowptr[i] = r;
        g_cursor[i] = r;
    }
}
__global__ void k_scatter(const int* __restrict__ ei) {
    int e = blockIdx.x * blockDim.x + threadIdx.x;
    if (e < EE) {
        int s = ei[e];
        int d = ei[EE + e];
        int pos = atomicAdd(&g_cursor[d], 1);
        g_col[pos] = s;
    }
}

// ======== GEMM1: fp16 2-term (A split hi+lo, B single), 3 CTAs/SM + fused att1 ========
#define SKEW 136
#define SA_HI 0
#define SA_LO 17408
#define SB_H  34816
#define SM_G1 69632

__global__ void __launch_bounds__(256, 3) k_gemm1_mma(const float* __restrict__ x0,
                                                      const float* __restrict__ attS,
                                                      const float* __restrict__ attD) {
    extern __shared__ __align__(128) char smem[];
    __half* sAhi = (__half*)(smem + SA_HI);
    __half* sAlo = (__half*)(smem + SA_LO);
    __half* sB   = (__half*)(smem + SB_H);
    uint32_t sb = smem_u32(smem);

    int tid = threadIdx.x;
    int rowBase = blockIdx.x * 64;

    // stage A: 64 rows x 128 cols fp32 -> fp16 hi/lo split
    #pragma unroll 4
    for (int i = 0; i < 32; i++) {
        int idx = i * 256 + tid;
        int r = idx >> 7, c = idx & 127;
        int grow = rowBase + r;
        float v = (grow < NN) ? __ldg(&x0[(size_t)grow * 128 + c]) : 0.f;
        __half hi = __float2half_rn(v);
        __half lo = __float2half_rn(v - __half2float(hi));
        sAhi[r * SKEW + c] = hi;
        sAlo[r * SKEW + c] = lo;
    }

    int wid = tid >> 5, lane = tid & 31;
    int warpM = wid >> 2, warpN = wid & 3;
    int aRow = warpM * 32 + (lane & 15);
    int aColHalf = (lane >> 4) * 8;
    int bRowX4 = ((lane >> 4) * 8) + (lane & 7);   // x4 pair row within 16-row block
    int bColHalf = ((lane >> 3) & 1) * 8;
    int rq = lane >> 2, cq = (lane & 3) * 2;

    #pragma unroll 1
    for (int ct = 0; ct < 2; ct++) {
        __syncthreads();
        // stage B: pure uint4 copy from pre-split fp16 image (tile layout [n][k])
        {
            const uint4* src = (const uint4*)(g_w1h + ct * 16384);
            #pragma unroll
            for (int i = 0; i < 8; i++) {
                int q = i * 256 + tid;
                int nl = q >> 4, k8 = (q & 15) * 8;
                *(uint4*)&sB[nl * SKEW + k8] = src[q];
            }
        }
        __syncthreads();

        float acc[2][4][4];
        #pragma unroll
        for (int mt = 0; mt < 2; mt++)
            #pragma unroll
            for (int nt = 0; nt < 4; nt++)
                #pragma unroll
                for (int q = 0; q < 4; q++) acc[mt][nt][q] = 0.f;

        #pragma unroll 1
        for (int ks = 0; ks < 8; ks++) {
            uint32_t ah[2][4], al[2][4], b[4][2];
            #pragma unroll
            for (int mt = 0; mt < 2; mt++) {
                uint32_t off = (uint32_t)(((aRow + mt * 16) * SKEW) + ks * 16 + aColHalf) * 2;
                LDSM4(ah[mt][0], ah[mt][1], ah[mt][2], ah[mt][3], sb + SA_HI + off);
                LDSM4(al[mt][0], al[mt][1], al[mt][2], al[mt][3], sb + SA_LO + off);
            }
            #pragma unroll
            for (int p = 0; p < 2; p++) {
                uint32_t off = (uint32_t)(((warpN * 32 + p * 16 + bRowX4) * SKEW) + ks * 16 + bColHalf) * 2;
                LDSM4(b[2 * p][0], b[2 * p][1], b[2 * p + 1][0], b[2 * p + 1][1], sb + SB_H + off);
            }
            #pragma unroll
            for (int mt = 0; mt < 2; mt++)
                #pragma unroll
                for (int nt = 0; nt < 4; nt++) {
                    MMA16816H(acc[mt][nt], ah[mt][0], ah[mt][1], ah[mt][2], ah[mt][3],
                              b[nt][0], b[nt][1]);
                    MMA16816H(acc[mt][nt], al[mt][0], al[mt][1], al[mt][2], al[mt][3],
                              b[nt][0], b[nt][1]);
                }
        }

        int h = ct * 4 + warpN;
        float aS[8], aD[8];
        #pragma unroll
        for (int nt = 0; nt < 4; nt++) {
            aS[nt * 2 + 0] = __ldg(&attS[h * 32 + nt * 8 + cq]);
            aS[nt * 2 + 1] = __ldg(&attS[h * 32 + nt * 8 + cq + 1]);
            aD[nt * 2 + 0] = __ldg(&attD[h * 32 + nt * 8 + cq]);
            aD[nt * 2 + 1] = __ldg(&attD[h * 32 + nt * 8 + cq + 1]);
        }
        #pragma unroll
        for (int mt = 0; mt < 2; mt++) {
            int r0 = rowBase + warpM * 32 + mt * 16 + rq;
            int r1 = r0 + 8;
            float ps0 = 0.f, pd0 = 0.f, ps1 = 0.f, pd1 = 0.f;
            #pragma unroll
            for (int nt = 0; nt < 4; nt++) {
                ps0 += acc[mt][nt][0] * aS[nt * 2] + acc[mt][nt][1] * aS[nt * 2 + 1];
                pd0 += acc[mt][nt][0] * aD[nt * 2] + acc[mt][nt][1] * aD[nt * 2 + 1];
                ps1 += acc[mt][nt][2] * aS[nt * 2] + acc[mt][nt][3] * aS[nt * 2 + 1];
                pd1 += acc[mt][nt][2] * aD[nt * 2] + acc[mt][nt][3] * aD[nt * 2 + 1];
                int cc = ct * 128 + warpN * 32 + nt * 8 + cq;
                if (r0 < NN)
                    *(__half2*)&g_h1h[(size_t)r0 * 256 + cc] =
                        __floats2half2_rn(acc[mt][nt][0], acc[mt][nt][1]);
                if (r1 < NN)
                    *(__half2*)&g_h1h[(size_t)r1 * 256 + cc] =
                        __floats2half2_rn(acc[mt][nt][2], acc[mt][nt][3]);
            }
            #pragma unroll
            for (int o = 1; o <= 2; o <<= 1) {
                ps0 += __shfl_xor_sync(0xffffffffu, ps0, o);
                pd0 += __shfl_xor_sync(0xffffffffu, pd0, o);
                ps1 += __shfl_xor_sync(0xffffffffu, ps1, o);
                pd1 += __shfl_xor_sync(0xffffffffu, pd1, o);
            }
            if ((lane & 3) == 0) {
                if (r0 < NN) { g_as1[r0 * 8 + h] = ps0; g_ad1[r0 * 8 + h] = pd0; }
                if (r1 < NN) { g_as1[r1 * 8 + h] = ps1; g_ad1[r1 * 8 + h] = pd1; }
            }
        }
    }
}

// ============ GAT1: per-lane head ownership, fp16 8B gathers, zero shuffles ============
__global__ void __launch_bounds__(256) k_gat1(const float* __restrict__ b1) {
    int n = (blockIdx.x * blockDim.x + threadIdx.x) >> 5;
    int lane = threadIdx.x & 31;
    if (n >= NN) return;
    int ha = lane >> 3, hb = ha + 4;
    int c4 = (lane & 7) * 4;

    float adA = __ldg(&g_ad1[n * 8 + ha]);
    float adB = __ldg(&g_ad1[n * 8 + hb]);
    float denA = 0.f, denB = 0.f;
    float4 accA = make_float4(0.f, 0.f, 0.f, 0.f);
    float4 accB = make_float4(0.f, 0.f, 0.f, 0.f);

    int e0 = g_rowptr[n], e1 = g_rowptr[n + 1];
    #pragma unroll 4
    for (int p = e0 - 1; p < e1; p++) {
        int s = (p < e0) ? n : __ldg(&g_col[p]);
        float wa = __expf(leaky(__ldg(&g_as1[s * 8 + ha]) + adA));
        float wb = __expf(leaky(__ldg(&g_as1[s * 8 + hb]) + adB));
        denA += wa; denB += wb;
        uint2 ra = *(const uint2*)&g_h1h[(size_t)s * 256 + ha * 32 + c4];
        uint2 rb = *(const uint2*)&g_h1h[(size_t)s * 256 + hb * 32 + c4];
        float2 a01 = __half22float2(*(__half2*)&ra.x);
        float2 a23 = __half22float2(*(__half2*)&ra.y);
        float2 b01 = __half22float2(*(__half2*)&rb.x);
        float2 b23 = __half22float2(*(__half2*)&rb.y);
        accA.x += wa * a01.x; accA.y += wa * a01.y; accA.z += wa * a23.x; accA.w += wa * a23.y;
        accB.x += wb * b01.x; accB.y += wb * b01.y; accB.z += wb * b23.x; accB.w += wb * b23.y;
    }
    float iA = 1.f / fmaxf(denA, 1e-16f);
    float iB = 1.f / fmaxf(denB, 1e-16f);
    float4 bA = __ldg((const float4*)&b1[ha * 32 + c4]);
    float4 bB = __ldg((const float4*)&b1[hb * 32 + c4]);
    __half2 rA0 = __floats2half2_rn(fmaxf(accA.x * iA + bA.x, 0.f), fmaxf(accA.y * iA + bA.y, 0.f));
    __half2 rA1 = __floats2half2_rn(fmaxf(accA.z * iA + bA.z, 0.f), fmaxf(accA.w * iA + bA.w, 0.f));
    __half2 rB0 = __floats2half2_rn(fmaxf(accB.x * iB + bB.x, 0.f), fmaxf(accB.y * iB + bB.y, 0.f));
    __half2 rB1 = __floats2half2_rn(fmaxf(accB.z * iB + bB.z, 0.f), fmaxf(accB.w * iB + bB.w, 0.f));
    uint2 pa, pb;
    pa.x = *(uint32_t*)&rA0; pa.y = *(uint32_t*)&rA1;
    pb.x = *(uint32_t*)&rB0; pb.y = *(uint32_t*)&rB1;
    __stcs((uint2*)&g_x2h[(size_t)n * 256 + ha * 32 + c4], pa);
    __stcs((uint2*)&g_x2h[(size_t)n * 256 + hb * 32 + c4], pb);
}

// ======== GEMM2 via fp16 mma: h2 = x2 @ W2 (K=256 -> 32) + fused att2 dots ========
#define SKEW2 264
#define G2_SA  0
#define G2_SBH 67584
#define G2_SBL 84480
#define SM_G2  101376

__global__ void __launch_bounds__(256, 2) k_gemm2_mma(const float* __restrict__ attS2,
                                                      const float* __restrict__ attD2) {
    extern __shared__ __align__(128) char smem[];
    __half* sA  = (__half*)(smem + G2_SA);
    __half* sBh = (__half*)(smem + G2_SBH);
    __half* sBl = (__half*)(smem + G2_SBL);
    uint32_t sb = smem_u32(smem);

    int tid = threadIdx.x;
    int rowBase = blockIdx.x * 128;

    #pragma unroll 4
    for (int i = 0; i < 16; i++) {
        int q = i * 256 + tid;
        int r = q >> 5, c8 = (q & 31) * 8;
        int grow = rowBase + r;
        uint4 v = (grow < NN) ? *(const uint4*)&g_x2h[(size_t)grow * 256 + c8]
                              : make_uint4(0, 0, 0, 0);
        *(uint4*)&sA[r * SKEW2 + c8] = v;
    }
    #pragma unroll
    for (int i = 0; i < 4; i++) {
        int q = i * 256 + tid;
        int nl = q >> 5, k8 = (q & 31) * 8;
        *(uint4*)&sBh[nl * SKEW2 + k8] = *(const uint4*)&g_w2hi[nl * 256 + k8];
        *(uint4*)&sBl[nl * SKEW2 + k8] = *(const uint4*)&g_w2lo[nl * 256 + k8];
    }
    __syncthreads();

    int wid = tid >> 5, lane = tid & 31;
    int aRow = wid * 16 + (lane & 15);
    int aColHalf = (lane >> 4) * 8;
    int bRowX4 = ((lane >> 4) * 8) + (lane & 7);
    int bColHalf = ((lane >> 3) & 1) * 8;
    int rq = lane >> 2, cq = (lane & 3) * 2;

    float acc[4][4];
    #pragma unroll
    for (int nt = 0; nt < 4; nt++)
        #pragma unroll
        for (int q = 0; q < 4; q++) acc[nt][q] = 0.f;

    #pragma unroll 2
    for (int ks = 0; ks < 16; ks++) {
        uint32_t a[4], bh[4][2], bl[4][2];
        LDSM4(a[0], a[1], a[2], a[3],
              sb + G2_SA + (uint32_t)(aRow * SKEW2 + ks * 16 + aColHalf) * 2);
        #pragma unroll
        for (int p = 0; p < 2; p++) {
            uint32_t off = (uint32_t)((p * 16 + bRowX4) * SKEW2 + ks * 16 + bColHalf) * 2;
            LDSM4(bh[2 * p][0], bh[2 * p][1], bh[2 * p + 1][0], bh[2 * p + 1][1], sb + G2_SBH + off);
            LDSM4(bl[2 * p][0], bl[2 * p][1], bl[2 * p + 1][0], bl[2 * p + 1][1], sb + G2_SBL + off);
        }
        #pragma unroll
        for (int nt = 0; nt < 4; nt++) {
            MMA16816H(acc[nt], a[0], a[1], a[2], a[3], bh[nt][0], bh[nt][1]);
            MMA16816H(acc[nt], a[0], a[1], a[2], a[3], bl[nt][0], bl[nt][1]);
        }
    }

    float aS[8], aD[8];
    #pragma unroll
    for (int nt = 0; nt < 4; nt++) {
        aS[nt * 2 + 0] = __ldg(&attS2[nt * 8 + cq]);
        aS[nt * 2 + 1] = __ldg(&attS2[nt * 8 + cq + 1]);
        aD[nt * 2 + 0] = __ldg(&attD2[nt * 8 + cq]);
        aD[nt * 2 + 1] = __ldg(&attD2[nt * 8 + cq + 1]);
    }
    int r0 = rowBase + wid * 16 + rq;
    int r1 = r0 + 8;
    float ps0 = 0.f, pd0 = 0.f, ps1 = 0.f, pd1 = 0.f;
    #pragma unroll
    for (int nt = 0; nt < 4; nt++) {
        ps0 += acc[nt][0] * aS[nt * 2] + acc[nt][1] * aS[nt * 2 + 1];
        pd0 += acc[nt][0] * aD[nt * 2] + acc[nt][1] * aD[nt * 2 + 1];
        ps1 += acc[nt][2] * aS[nt * 2] + acc[nt][3] * aS[nt * 2 + 1];
        pd1 += acc[nt][2] * aD[nt * 2] + acc[nt][3] * aD[nt * 2 + 1];
        int cc = nt * 8 + cq;
        if (r0 < NN)
            *(__half2*)&g_h2h[r0 * 32 + cc] = __floats2half2_rn(acc[nt][0], acc[nt][1]);
        if (r1 < NN)
            *(__half2*)&g_h2h[r1 * 32 + cc] = __floats2half2_rn(acc[nt][2], acc[nt][3]);
    }
    #pragma unroll
    for (int o = 1; o <= 2; o <<= 1) {
        ps0 += __shfl_xor_sync(0xffffffffu, ps0, o);
        pd0 += __shfl_xor_sync(0xffffffffu, pd0, o);
        ps1 += __shfl_xor_sync(0xffffffffu, ps1, o);
        pd1 += __shfl_xor_sync(0xffffffffu, pd1, o);
    }
    if ((lane & 3) == 0) {
        if (r0 < NN) { g_as2[r0] = ps0; g_ad2[r0] = pd0; }
        if (r1 < NN) { g_as2[r1] = ps1; g_ad2[r1] = pd1; }
    }
}

// ============ GAT2 (4-edge groups, fp16 8B loads) + fused final linear ============
__global__ void __launch_bounds__(256) k_gat2(const float* __restrict__ b2,
                                              const float* __restrict__ linW,
                                              const float* __restrict__ linb,
                                              float* __restrict__ out) {
    __shared__ float lw[32 * 40];
    __shared__ float rows[8][32];
    int tid = threadIdx.x;
    for (int i = tid; i < 32 * 40; i += 256) lw[i] = linW[i];

    int wl = tid >> 5, lane = tid & 31;
    int n = blockIdx.x * 8 + wl;
    int grp = lane >> 3, c4 = (lane & 7) * 4;

    float adst = g_ad2[n];
    float asn  = g_as2[n];
    float den; float4 acc;
    {
        float ws = __expf(leaky(asn + adst));
        if (grp == 0) {
            uint2 rh = *(const uint2*)&g_h2h[n * 32 + c4];
            float2 h01 = __half22float2(*(__half2*)&rh.x);
            float2 h23 = __half22float2(*(__half2*)&rh.y);
            den = ws;
            acc = make_float4(ws * h01.x, ws * h01.y, ws * h23.x, ws * h23.y);
        } else {
            den = 0.f;
            acc = make_float4(0.f, 0.f, 0.f, 0.f);
        }
    }
    int e0 = g_rowptr[n], e1 = g_rowptr[n + 1];
    #pragma unroll 2
    for (int p0 = e0; p0 < e1; p0 += 4) {
        int p = p0 + grp;
        bool v = p < e1;
        int s = v ? __ldg(&g_col[p]) : n;
        float w = v ? __expf(leaky(__ldg(&g_as2[s]) + adst)) : 0.f;
        den += w;
        uint2 rh = *(const uint2*)&g_h2h[s * 32 + c4];
        float2 h01 = __half22float2(*(__half2*)&rh.x);
        float2 h23 = __half22float2(*(__half2*)&rh.y);
        acc.x += w * h01.x; acc.y += w * h01.y; acc.z += w * h23.x; acc.w += w * h23.y;
    }
    #pragma unroll
    for (int o = 8; o <= 16; o <<= 1) {
        acc.x += __shfl_xor_sync(0xffffffffu, acc.x, o);
        acc.y += __shfl_xor_sync(0xffffffffu, acc.y, o);
        acc.z += __shfl_xor_sync(0xffffffffu, acc.z, o);
        acc.w += __shfl_xor_sync(0xffffffffu, acc.w, o);
        den   += __shfl_xor_sync(0xffffffffu, den, o);
    }
    if (grp == 0) {
        float inv = 1.f / fmaxf(den, 1e-16f);
        float4 bb = __ldg((const float4*)&b2[c4]);
        rows[wl][c4 + 0] = acc.x * inv + bb.x;
        rows[wl][c4 + 1] = acc.y * inv + bb.y;
        rows[wl][c4 + 2] = acc.z * inv + bb.z;
        rows[wl][c4 + 3] = acc.w * inv + bb.w;
    }
    __syncthreads();
    int nb = blockIdx.x * 8;
    for (int t = tid; t < 320; t += 256) {
        int r = t / 40, o = t % 40;
        float s = __ldg(&linb[o]);
        #pragma unroll
        for (int k = 0; k < 32; k++) s += rows[r][k] * lw[k * 40 + o];
        out[(size_t)(nb + r) * 40 + o] = s;
    }
}

// ================= launch =================
extern "C" void kernel_launch(void* const* d_in, const int* in_sizes, int n_in,
                              void* d_out, int out_size) {
    const float* x0    = (const float*)d_in[0];
    const float* W1    = (const float*)d_in[1];
    const float* attS1 = (const float*)d_in[2];
    const float* attD1 = (const float*)d_in[3];
    const float* b1    = (const float*)d_in[4];
    const float* W2    = (const float*)d_in[5];
    const float* attS2 = (const float*)d_in[6];
    const float* attD2 = (const float*)d_in[7];
    const float* b2    = (const float*)d_in[8];
    const float* linW  = (const float*)d_in[9];
    const float* linb  = (const float*)d_in[10];
    const int*   ei    = (const int*)d_in[11];
    float* out = (float*)d_out;

    static cudaStream_t s_side = nullptr;
    static cudaEvent_t ev_fork = nullptr, ev_join = nullptr;
    if (!s_side) {
        cudaFuncSetAttribute(k_gemm1_mma, cudaFuncAttributeMaxDynamicSharedMemorySize, SM_G1);
        cudaFuncSetAttribute(k_gemm2_mma, cudaFuncAttributeMaxDynamicSharedMemorySize, SM_G2);
        cudaStreamCreateWithFlags(&s_side, cudaStreamNonBlocking);
        cudaEventCreateWithFlags(&ev_fork, cudaEventDisableTiming);
        cudaEventCreateWithFlags(&ev_join, cudaEventDisableTiming);
    }

    const int NBLK = (NN + 1023) / 1024;   // 98

    cudaEventRecord(ev_fork, 0);
    cudaStreamWaitEvent(s_side, ev_fork, 0);
    k_prepw1<<<128, 256>>>(W1);                                  // 1 (main)
    k_zero<<<(NN + 255) / 256, 256, 0, s_side>>>();              // 2 (side)
    k_hist<<<(EE + 255) / 256, 256, 0, s_side>>>(ei);            // 3 (side)
    k_gemm1_mma<<<(NN + 63) / 64, 256, SM_G1>>>(x0, attS1, attD1); // 4 (main)
    k_prepw2<<<32, 256, 0, s_side>>>(W2);                        // 5 (side)
    k_scan1<<<NBLK, 1024, 0, s_side>>>();                        // 6
    k_scan2<<<1, 128, 0, s_side>>>(NBLK);                        // 7
    k_scan3<<<NBLK, 1024, 0, s_side>>>();                        // 8
    k_scatter<<<(EE + 255) / 256, 256, 0, s_side>>>(ei);         // 9
    cudaEventRecord(ev_join, s_side);

    cudaStreamWaitEvent(0, ev_join, 0);
    k_gat1<<<(NN + 7) / 8, 256>>>(b1);
    k_gemm2_mma<<<(NN + 127) / 128, 256, SM_G2>>>(attS2, attD2);
    k_gat2<<<NN / 8, 256>>>(b2, linW, linb, out);
}

// round 14
// speedup vs baseline: 4.5488x; 1.1101x over previous
#include <cuda_runtime.h>
#include <cuda_bf16.h>
#include <cuda_fp16.h>
#include <cstdint>

#define NN   100000
#define EE   1000000
#define HID  32
#define NH1  8
#define OUTC 40
#define NEGS 0.2f

// ================= device scratch =================
__device__ __align__(16) __half g_h1h[(size_t)NN * 256];   // layer1 messages, fp16
__device__ __align__(16) __half g_x2h[(size_t)NN * 256];   // relu(layer1 out), fp16
__device__ __align__(16) float g_as1[NN * NH1];
__device__ __align__(16) float g_ad1[NN * NH1];
__device__ __align__(16) __half g_h2h[NN * HID];           // layer2 messages, fp16
__device__ __align__(16) float g_as2[NN];
__device__ __align__(16) float g_ad2[NN];
__device__ __align__(16) __half g_w1h[32768];              // W1 fp16, tile layout [ct][n][k]
__device__ __align__(16) __half g_w2hi[8192];              // W2 split fp16, [n][k] layout
__device__ __align__(16) __half g_w2lo[8192];
__device__ int g_cnt[NN];
__device__ int g_rowptr[NN + 1];
__device__ int g_cursor[NN];
__device__ int g_col[EE];
__device__ int g_bsum[128];
__device__ int g_boff[128];

__device__ __forceinline__ float leaky(float x) { return x > 0.f ? x : NEGS * x; }

__device__ __forceinline__ uint32_t smem_u32(const void* p) {
    uint32_t a;
    asm("{ .reg .u64 t; cvta.to.shared.u64 t, %1; cvt.u32.u64 %0, t; }" : "=r"(a) : "l"(p));
    return a;
}

#define LDSM4(r0, r1, r2, r3, a) \
    asm volatile("ldmatrix.sync.aligned.m8n8.x4.shared.b16 {%0,%1,%2,%3}, [%4];" \
                 : "=r"(r0), "=r"(r1), "=r"(r2), "=r"(r3) : "r"(a))
#define MMA16816H(c, a0, a1, a2, a3, b0, b1) \
    asm volatile("mma.sync.aligned.m16n8k16.row.col.f32.f16.f16.f32 " \
                 "{%0,%1,%2,%3},{%4,%5,%6,%7},{%8,%9},{%0,%1,%2,%3};" \
                 : "+f"((c)[0]), "+f"((c)[1]), "+f"((c)[2]), "+f"((c)[3]) \
                 : "r"(a0), "r"(a1), "r"(a2), "r"(a3), "r"(b0), "r"(b1))

// ================= weight prep =================
__global__ void k_prepw1(const float* __restrict__ W1) {
    int idx = blockIdx.x * blockDim.x + threadIdx.x;
    if (idx >= 32768) return;
    int k = idx >> 8, n = idx & 255;
    float v = __ldg(&W1[idx]);
    int ct = n >> 7, nl = n & 127;
    g_w1h[ct * 16384 + nl * 128 + k] = __float2half_rn(v);
}
__global__ void k_prepw2(const float* __restrict__ W2) {
    int idx = blockIdx.x * blockDim.x + threadIdx.x;
    if (idx >= 8192) return;
    int k = idx >> 5, n = idx & 31;
    float v = __ldg(&W2[idx]);
    __half hi = __float2half_rn(v);
    __half lo = __float2half_rn(v - __half2float(hi));
    g_w2hi[n * 256 + k] = hi;
    g_w2lo[n * 256 + k] = lo;
}

// ================= CSR build =================
__global__ void k_zero() {
    int i = blockIdx.x * blockDim.x + threadIdx.x;
    if (i < NN) g_cnt[i] = 0;
}
__global__ void k_hist(const int* __restrict__ ei) {
    int e = blockIdx.x * blockDim.x + threadIdx.x;
    if (e < EE) atomicAdd(&g_cnt[ei[EE + e]], 1);
}
__global__ void __launch_bounds__(1024) k_scan1() {
    __shared__ int ws[32];
    int tid = threadIdx.x, lane = tid & 31, wid = tid >> 5;
    int i = blockIdx.x * 1024 + tid;
    int v = (i < NN) ? g_cnt[i] : 0;
    int x = v;
    #pragma unroll
    for (int o = 1; o < 32; o <<= 1) {
        int y = __shfl_up_sync(0xffffffffu, x, o);
        if (lane >= o) x += y;
    }
    if (lane == 31) ws[wid] = x;
    __syncthreads();
    if (wid == 0) {
        int s = ws[lane];
        #pragma unroll
        for (int o = 1; o < 32; o <<= 1) {
            int y = __shfl_up_sync(0xffffffffu, s, o);
            if (lane >= o) s += y;
        }
        ws[lane] = s;
    }
    __syncthreads();
    int incl = x + (wid ? ws[wid - 1] : 0);
    if (i < NN) g_rowptr[i] = incl - v;
    if (tid == 1023) g_bsum[blockIdx.x] = incl;
}
__global__ void k_scan2(int nblk) {
    __shared__ int ws[4];
    int tid = threadIdx.x, lane = tid & 31, wid = tid >> 5;
    int v = (tid < nblk) ? g_bsum[tid] : 0;
    int x = v;
    #pragma unroll
    for (int o = 1; o < 32; o <<= 1) {
        int y = __shfl_up_sync(0xffffffffu, x, o);
        if (lane >= o) x += y;
    }
    if (lane == 31) ws[wid] = x;
    __syncthreads();
    int pre = 0;
    for (int w = 0; w < wid; w++) pre += ws[w];
    int incl = x + pre;
    if (tid < nblk) g_boff[tid] = incl - v;
    if (tid == nblk - 1) g_rowptr[NN] = incl;
}
__global__ void __launch_bounds__(1024) k_scan3() {
    int i = blockIdx.x * 1024 + threadIdx.x;
    if (i < NN) {
        int r = g_rowptr[i] + g_boff[blockIdx.x];
        g_rowptr[i] = r;
        g_cursor[i] = r;
    }
}
__global__ void k_scatter(const int* __restrict__ ei) {
    int e = blockIdx.x * blockDim.x + threadIdx.x;
    if (e < EE) {
        int s = ei[e];
        int d = ei[EE + e];
        int pos = atomicAdd(&g_cursor[d], 1);
        g_col[pos] = s;
    }
}

// ======== GEMM1: fp16 2-term (A split hi+lo, B single), 3 CTAs/SM + fused att1 ========
#define SKEW 136
#define SA_HI 0
#define SA_LO 17408
#define SB_H  34816
#define SM_G1 69632

__global__ void __launch_bounds__(256, 3) k_gemm1_mma(const float* __restrict__ x0,
                                                      const float* __restrict__ attS,
                                                      const float* __restrict__ attD) {
    extern __shared__ __align__(128) char smem[];
    __half* sAhi = (__half*)(smem + SA_HI);
    __half* sAlo = (__half*)(smem + SA_LO);
    __half* sB   = (__half*)(smem + SB_H);
    uint32_t sb = smem_u32(smem);

    int tid = threadIdx.x;
    int rowBase = blockIdx.x * 64;

    #pragma unroll 4
    for (int i = 0; i < 32; i++) {
        int idx = i * 256 + tid;
        int r = idx >> 7, c = idx & 127;
        int grow = rowBase + r;
        float v = (grow < NN) ? __ldg(&x0[(size_t)grow * 128 + c]) : 0.f;
        __half hi = __float2half_rn(v);
        __half lo = __float2half_rn(v - __half2float(hi));
        sAhi[r * SKEW + c] = hi;
        sAlo[r * SKEW + c] = lo;
    }

    int wid = tid >> 5, lane = tid & 31;
    int warpM = wid >> 2, warpN = wid & 3;
    int aRow = warpM * 32 + (lane & 15);
    int aColHalf = (lane >> 4) * 8;
    int bRowX4 = ((lane >> 4) * 8) + (lane & 7);
    int bColHalf = ((lane >> 3) & 1) * 8;
    int rq = lane >> 2, cq = (lane & 3) * 2;

    #pragma unroll 1
    for (int ct = 0; ct < 2; ct++) {
        __syncthreads();
        {
            const uint4* src = (const uint4*)(g_w1h + ct * 16384);
            #pragma unroll
            for (int i = 0; i < 8; i++) {
                int q = i * 256 + tid;
                int nl = q >> 4, k8 = (q & 15) * 8;
                *(uint4*)&sB[nl * SKEW + k8] = src[q];
            }
        }
        __syncthreads();

        float acc[2][4][4];
        #pragma unroll
        for (int mt = 0; mt < 2; mt++)
            #pragma unroll
            for (int nt = 0; nt < 4; nt++)
                #pragma unroll
                for (int q = 0; q < 4; q++) acc[mt][nt][q] = 0.f;

        #pragma unroll 1
        for (int ks = 0; ks < 8; ks++) {
            uint32_t ah[2][4], al[2][4], b[4][2];
            #pragma unroll
            for (int mt = 0; mt < 2; mt++) {
                uint32_t off = (uint32_t)(((aRow + mt * 16) * SKEW) + ks * 16 + aColHalf) * 2;
                LDSM4(ah[mt][0], ah[mt][1], ah[mt][2], ah[mt][3], sb + SA_HI + off);
                LDSM4(al[mt][0], al[mt][1], al[mt][2], al[mt][3], sb + SA_LO + off);
            }
            #pragma unroll
            for (int p = 0; p < 2; p++) {
                uint32_t off = (uint32_t)(((warpN * 32 + p * 16 + bRowX4) * SKEW) + ks * 16 + bColHalf) * 2;
                LDSM4(b[2 * p][0], b[2 * p][1], b[2 * p + 1][0], b[2 * p + 1][1], sb + SB_H + off);
            }
            #pragma unroll
            for (int mt = 0; mt < 2; mt++)
                #pragma unroll
                for (int nt = 0; nt < 4; nt++) {
                    MMA16816H(acc[mt][nt], ah[mt][0], ah[mt][1], ah[mt][2], ah[mt][3],
                              b[nt][0], b[nt][1]);
                    MMA16816H(acc[mt][nt], al[mt][0], al[mt][1], al[mt][2], al[mt][3],
                              b[nt][0], b[nt][1]);
                }
        }

        int h = ct * 4 + warpN;
        float aS[8], aD[8];
        #pragma unroll
        for (int nt = 0; nt < 4; nt++) {
            aS[nt * 2 + 0] = __ldg(&attS[h * 32 + nt * 8 + cq]);
            aS[nt * 2 + 1] = __ldg(&attS[h * 32 + nt * 8 + cq + 1]);
            aD[nt * 2 + 0] = __ldg(&attD[h * 32 + nt * 8 + cq]);
            aD[nt * 2 + 1] = __ldg(&attD[h * 32 + nt * 8 + cq + 1]);
        }
        #pragma unroll
        for (int mt = 0; mt < 2; mt++) {
            int r0 = rowBase + warpM * 32 + mt * 16 + rq;
            int r1 = r0 + 8;
            float ps0 = 0.f, pd0 = 0.f, ps1 = 0.f, pd1 = 0.f;
            #pragma unroll
            for (int nt = 0; nt < 4; nt++) {
                ps0 += acc[mt][nt][0] * aS[nt * 2] + acc[mt][nt][1] * aS[nt * 2 + 1];
                pd0 += acc[mt][nt][0] * aD[nt * 2] + acc[mt][nt][1] * aD[nt * 2 + 1];
                ps1 += acc[mt][nt][2] * aS[nt * 2] + acc[mt][nt][3] * aS[nt * 2 + 1];
                pd1 += acc[mt][nt][2] * aD[nt * 2] + acc[mt][nt][3] * aD[nt * 2 + 1];
                int cc = ct * 128 + warpN * 32 + nt * 8 + cq;
                if (r0 < NN)
                    *(__half2*)&g_h1h[(size_t)r0 * 256 + cc] =
                        __floats2half2_rn(acc[mt][nt][0], acc[mt][nt][1]);
                if (r1 < NN)
                    *(__half2*)&g_h1h[(size_t)r1 * 256 + cc] =
                        __floats2half2_rn(acc[mt][nt][2], acc[mt][nt][3]);
            }
            #pragma unroll
            for (int o = 1; o <= 2; o <<= 1) {
                ps0 += __shfl_xor_sync(0xffffffffu, ps0, o);
                pd0 += __shfl_xor_sync(0xffffffffu, pd0, o);
                ps1 += __shfl_xor_sync(0xffffffffu, ps1, o);
                pd1 += __shfl_xor_sync(0xffffffffu, pd1, o);
            }
            if ((lane & 3) == 0) {
                if (r0 < NN) { g_as1[r0 * 8 + h] = ps0; g_ad1[r0 * 8 + h] = pd0; }
                if (r1 < NN) { g_as1[r1 * 8 + h] = ps1; g_ad1[r1 * 8 + h] = pd1; }
            }
        }
    }
}

// ============ GAT1: lane owns 8 channels of ONE head; 16B loads, 1 exp/edge ============
__global__ void __launch_bounds__(256) k_gat1(const float* __restrict__ b1) {
    int n = (blockIdx.x * blockDim.x + threadIdx.x) >> 5;
    int lane = threadIdx.x & 31;
    if (n >= NN) return;
    int hh = lane >> 2;              // head 0..7
    int c8 = (lane & 3) * 8;         // channel base within head
    int coff = hh * 32 + c8;         // offset within 256-ch row

    float ad = __ldg(&g_ad1[n * 8 + hh]);

    // self loop hoisted
    float den = __expf(leaky(__ldg(&g_as1[n * 8 + hh]) + ad));
    float acc[8];
    {
        uint4 rh = *(const uint4*)&g_h1h[(size_t)n * 256 + coff];
        const __half2* hp = (const __half2*)&rh;
        #pragma unroll
        for (int j = 0; j < 4; j++) {
            float2 f = __half22float2(hp[j]);
            acc[2 * j]     = den * f.x;
            acc[2 * j + 1] = den * f.y;
        }
    }

    int e0 = g_rowptr[n], e1 = g_rowptr[n + 1];
    #pragma unroll 4
    for (int p = e0; p < e1; p++) {
        int s = __ldg(&g_col[p]);
        float w = __expf(leaky(__ldg(&g_as1[s * 8 + hh]) + ad));
        den += w;
        uint4 rh = *(const uint4*)&g_h1h[(size_t)s * 256 + coff];
        const __half2* hp = (const __half2*)&rh;
        #pragma unroll
        for (int j = 0; j < 4; j++) {
            float2 f = __half22float2(hp[j]);
            acc[2 * j]     += w * f.x;
            acc[2 * j + 1] += w * f.y;
        }
    }

    float inv = 1.f / fmaxf(den, 1e-16f);
    float4 bb0 = __ldg((const float4*)&b1[coff]);
    float4 bb1 = __ldg((const float4*)&b1[coff + 4]);
    float bv[8] = {bb0.x, bb0.y, bb0.z, bb0.w, bb1.x, bb1.y, bb1.z, bb1.w};
    uint4 outp;
    __half2* op = (__half2*)&outp;
    #pragma unroll
    for (int j = 0; j < 4; j++) {
        float r0 = fmaxf(acc[2 * j]     * inv + bv[2 * j],     0.f);
        float r1 = fmaxf(acc[2 * j + 1] * inv + bv[2 * j + 1], 0.f);
        op[j] = __floats2half2_rn(r0, r1);
    }
    __stcs((uint4*)&g_x2h[(size_t)n * 256 + coff], outp);
}

// ======== GEMM2 via fp16 mma: h2 = x2 @ W2 (K=256 -> 32) + fused att2 dots ========
#define SKEW2 264
#define G2_SA  0
#define G2_SBH 67584
#define G2_SBL 84480
#define SM_G2  101376

__global__ void __launch_bounds__(256, 2) k_gemm2_mma(const float* __restrict__ attS2,
                                                      const float* __restrict__ attD2) {
    extern __shared__ __align__(128) char smem[];
    __half* sA  = (__half*)(smem + G2_SA);
    __half* sBh = (__half*)(smem + G2_SBH);
    __half* sBl = (__half*)(smem + G2_SBL);
    uint32_t sb = smem_u32(smem);

    int tid = threadIdx.x;
    int rowBase = blockIdx.x * 128;

    #pragma unroll 4
    for (int i = 0; i < 16; i++) {
        int q = i * 256 + tid;
        int r = q >> 5, c8 = (q & 31) * 8;
        int grow = rowBase + r;
        uint4 v = (grow < NN) ? *(const uint4*)&g_x2h[(size_t)grow * 256 + c8]
                              : make_uint4(0, 0, 0, 0);
        *(uint4*)&sA[r * SKEW2 + c8] = v;
    }
    #pragma unroll
    for (int i = 0; i < 4; i++) {
        int q = i * 256 + tid;
        int nl = q >> 5, k8 = (q & 31) * 8;
        *(uint4*)&sBh[nl * SKEW2 + k8] = *(const uint4*)&g_w2hi[nl * 256 + k8];
        *(uint4*)&sBl[nl * SKEW2 + k8] = *(const uint4*)&g_w2lo[nl * 256 + k8];
    }
    __syncthreads();

    int wid = tid >> 5, lane = tid & 31;
    int aRow = wid * 16 + (lane & 15);
    int aColHalf = (lane >> 4) * 8;
    int bRowX4 = ((lane >> 4) * 8) + (lane & 7);
    int bColHalf = ((lane >> 3) & 1) * 8;
    int rq = lane >> 2, cq = (lane & 3) * 2;

    float acc[4][4];
    #pragma unroll
    for (int nt = 0; nt < 4; nt++)
        #pragma unroll
        for (int q = 0; q < 4; q++) acc[nt][q] = 0.f;

    #pragma unroll 2
    for (int ks = 0; ks < 16; ks++) {
        uint32_t a[4], bh[4][2], bl[4][2];
        LDSM4(a[0], a[1], a[2], a[3],
              sb + G2_SA + (uint32_t)(aRow * SKEW2 + ks * 16 + aColHalf) * 2);
        #pragma unroll
        for (int p = 0; p < 2; p++) {
            uint32_t off = (uint32_t)((p * 16 + bRowX4) * SKEW2 + ks * 16 + bColHalf) * 2;
            LDSM4(bh[2 * p][0], bh[2 * p][1], bh[2 * p + 1][0], bh[2 * p + 1][1], sb + G2_SBH + off);
            LDSM4(bl[2 * p][0], bl[2 * p][1], bl[2 * p + 1][0], bl[2 * p + 1][1], sb + G2_SBL + off);
        }
        #pragma unroll
        for (int nt = 0; nt < 4; nt++) {
            MMA16816H(acc[nt], a[0], a[1], a[2], a[3], bh[nt][0], bh[nt][1]);
            MMA16816H(acc[nt], a[0], a[1], a[2], a[3], bl[nt][0], bl[nt][1]);
        }
    }

    float aS[8], aD[8];
    #pragma unroll
    for (int nt = 0; nt < 4; nt++) {
        aS[nt * 2 + 0] = __ldg(&attS2[nt * 8 + cq]);
        aS[nt * 2 + 1] = __ldg(&attS2[nt * 8 + cq + 1]);
        aD[nt * 2 + 0] = __ldg(&attD2[nt * 8 + cq]);
        aD[nt * 2 + 1] = __ldg(&attD2[nt * 8 + cq + 1]);
    }
    int r0 = rowBase + wid * 16 + rq;
    int r1 = r0 + 8;
    float ps0 = 0.f, pd0 = 0.f, ps1 = 0.f, pd1 = 0.f;
    #pragma unroll
    for (int nt = 0; nt < 4; nt++) {
        ps0 += acc[nt][0] * aS[nt * 2] + acc[nt][1] * aS[nt * 2 + 1];
        pd0 += acc[nt][0] * aD[nt * 2] + acc[nt][1] * aD[nt * 2 + 1];
        ps1 += acc[nt][2] * aS[nt * 2] + acc[nt][3] * aS[nt * 2 + 1];
        pd1 += acc[nt][2] * aD[nt * 2] + acc[nt][3] * aD[nt * 2 + 1];
        int cc = nt * 8 + cq;
        if (r0 < NN)
            *(__half2*)&g_h2h[r0 * 32 + cc] = __floats2half2_rn(acc[nt][0], acc[nt][1]);
        if (r1 < NN)
            *(__half2*)&g_h2h[r1 * 32 + cc] = __floats2half2_rn(acc[nt][2], acc[nt][3]);
    }
    #pragma unroll
    for (int o = 1; o <= 2; o <<= 1) {
        ps0 += __shfl_xor_sync(0xffffffffu, ps0, o);
        pd0 += __shfl_xor_sync(0xffffffffu, pd0, o);
        ps1 += __shfl_xor_sync(0xffffffffu, ps1, o);
        pd1 += __shfl_xor_sync(0xffffffffu, pd1, o);
    }
    if ((lane & 3) == 0) {
        if (r0 < NN) { g_as2[r0] = ps0; g_ad2[r0] = pd0; }
        if (r1 < NN) { g_as2[r1] = ps1; g_ad2[r1] = pd1; }
    }
}

// ============ GAT2 (4-edge groups, fp16 8B loads) + fused final linear ============
__global__ void __launch_bounds__(256) k_gat2(const float* __restrict__ b2,
                                              const float* __restrict__ linW,
                                              const float* __restrict__ linb,
                                              float* __restrict__ out) {
    __shared__ float lw[32 * 40];
    __shared__ float rows[8][32];
    int tid = threadIdx.x;
    for (int i = tid; i < 32 * 40; i += 256) lw[i] = linW[i];

    int wl = tid >> 5, lane = tid & 31;
    int n = blockIdx.x * 8 + wl;
    int grp = lane >> 3, c4 = (lane & 7) * 4;

    float adst = g_ad2[n];
    float asn  = g_as2[n];
    float den; float4 acc;
    {
        float ws = __expf(leaky(asn + adst));
        if (grp == 0) {
            uint2 rh = *(const uint2*)&g_h2h[n * 32 + c4];
            float2 h01 = __half22float2(*(__half2*)&rh.x);
            float2 h23 = __half22float2(*(__half2*)&rh.y);
            den = ws;
            acc = make_float4(ws * h01.x, ws * h01.y, ws * h23.x, ws * h23.y);
        } else {
            den = 0.f;
            acc = make_float4(0.f, 0.f, 0.f, 0.f);
        }
    }
    int e0 = g_rowptr[n], e1 = g_rowptr[n + 1];
    #pragma unroll 2
    for (int p0 = e0; p0 < e1; p0 += 4) {
        int p = p0 + grp;
        bool v = p < e1;
        int s = v ? __ldg(&g_col[p]) : n;
        float w = v ? __expf(leaky(__ldg(&g_as2[s]) + adst)) : 0.f;
        den += w;
        uint2 rh = *(const uint2*)&g_h2h[s * 32 + c4];
        float2 h01 = __half22float2(*(__half2*)&rh.x);
        float2 h23 = __half22float2(*(__half2*)&rh.y);
        acc.x += w * h01.x; acc.y += w * h01.y; acc.z += w * h23.x; acc.w += w * h23.y;
    }
    #pragma unroll
    for (int o = 8; o <= 16; o <<= 1) {
        acc.x += __shfl_xor_sync(0xffffffffu, acc.x, o);
        acc.y += __shfl_xor_sync(0xffffffffu, acc.y, o);
        acc.z += __shfl_xor_sync(0xffffffffu, acc.z, o);
        acc.w += __shfl_xor_sync(0xffffffffu, acc.w, o);
        den   += __shfl_xor_sync(0xffffffffu, den, o);
    }
    if (grp == 0) {
        float inv = 1.f / fmaxf(den, 1e-16f);
        float4 bb = __ldg((const float4*)&b2[c4]);
        rows[wl][c4 + 0] = acc.x * inv + bb.x;
        rows[wl][c4 + 1] = acc.y * inv + bb.y;
        rows[wl][c4 + 2] = acc.z * inv + bb.z;
        rows[wl][c4 + 3] = acc.w * inv + bb.w;
    }
    __syncthreads();
    int nb = blockIdx.x * 8;
    for (int t = tid; t < 320; t += 256) {
        int r = t / 40, o = t % 40;
        float s = __ldg(&linb[o]);
        #pragma unroll
        for (int k = 0; k < 32; k++) s += rows[r][k] * lw[k * 40 + o];
        out[(size_t)(nb + r) * 40 + o] = s;
    }
}

// ================= launch =================
extern "C" void kernel_launch(void* const* d_in, const int* in_sizes, int n_in,
                              void* d_out, int out_size) {
    const float* x0    = (const float*)d_in[0];
    const float* W1    = (const float*)d_in[1];
    const float* attS1 = (const float*)d_in[2];
    const float* attD1 = (const float*)d_in[3];
    const float* b1    = (const float*)d_in[4];
    const float* W2    = (const float*)d_in[5];
    const float* attS2 = (const float*)d_in[6];
    const float* attD2 = (const float*)d_in[7];
    const float* b2    = (const float*)d_in[8];
    const float* linW  = (const float*)d_in[9];
    const float* linb  = (const float*)d_in[10];
    const int*   ei    = (const int*)d_in[11];
    float* out = (float*)d_out;

    static cudaStream_t s_side = nullptr;
    static cudaEvent_t ev_fork = nullptr, ev_join = nullptr;
    if (!s_side) {
        cudaFuncSetAttribute(k_gemm1_mma, cudaFuncAttributeMaxDynamicSharedMemorySize, SM_G1);
        cudaFuncSetAttribute(k_gemm2_mma, cudaFuncAttributeMaxDynamicSharedMemorySize, SM_G2);
        cudaStreamCreateWithFlags(&s_side, cudaStreamNonBlocking);
        cudaEventCreateWithFlags(&ev_fork, cudaEventDisableTiming);
        cudaEventCreateWithFlags(&ev_join, cudaEventDisableTiming);
    }

    const int NBLK = (NN + 1023) / 1024;   // 98

    cudaEventRecord(ev_fork, 0);
    cudaStreamWaitEvent(s_side, ev_fork, 0);
    k_prepw1<<<128, 256>>>(W1);                                  // 1 (main)
    k_zero<<<(NN + 255) / 256, 256, 0, s_side>>>();              // 2 (side)
    k_hist<<<(EE + 255) / 256, 256, 0, s_side>>>(ei);            // 3 (side)
    k_gemm1_mma<<<(NN + 63) / 64, 256, SM_G1>>>(x0, attS1, attD1); // 4 (main)
    k_prepw2<<<32, 256, 0, s_side>>>(W2);                        // 5 (side)
    k_scan1<<<NBLK, 1024, 0, s_side>>>();                        // 6
    k_scan2<<<1, 128, 0, s_side>>>(NBLK);                        // 7
    k_scan3<<<NBLK, 1024, 0, s_side>>>();                        // 8
    k_scatter<<<(EE + 255) / 256, 256, 0, s_side>>>(ei);         // 9
    cudaEventRecord(ev_join, s_side);

    cudaStreamWaitEvent(0, ev_join, 0);
    k_gat1<<<(NN + 7) / 8, 256>>>(b1);
    k_gemm2_mma<<<(NN + 127) / 128, 256, SM_G2>>>(attS2, attD2);
    k_gat2<<<NN / 8, 256>>>(b2, linW, linb, out);
}